// round 1
// baseline (speedup 1.0000x reference)
#include <cuda_runtime.h>
#include <math.h>

#define SEQ 4097
#define H   1024
#define NH  16
#define HD  64
#define H3  3072
#define FFD 4096
#define LAYERS 6
#define OUTD 128

// ---------------- scratch (device globals; no allocations) ----------------
__device__ float g_x[SEQ * H];
__device__ float g_qkv[SEQ * H3];
__device__ float g_attn[SEQ * H];
__device__ float g_tmp[SEQ * H];
__device__ float g_ff[SEQ * FFD];

// ---------------- embedding ----------------
// x[s] = proj(input_s) + pos[s] + noise_emb[int(mask_s * 100)]
__global__ void embed_kernel(
    const float* __restrict__ q, const float* __restrict__ p,
    const float* __restrict__ qm, const float* __restrict__ pm,
    const float* __restrict__ z,
    const float* __restrict__ Wq, const float* __restrict__ bq,
    const float* __restrict__ Wp, const float* __restrict__ bp,
    const float* __restrict__ Wz, const float* __restrict__ bz,
    const float* __restrict__ pos, const float* __restrict__ noise,
    float* __restrict__ x)
{
    int s = blockIdx.x;
    __shared__ float vin[128];
    const float *W, *b, *src;
    int dim;
    float mask;
    if (s == 0)          { src = z;                 dim = 128; W = Wz; b = bz; mask = 1.0f; }
    else if (s <= 2048)  { src = q + (s - 1) * 64;  dim = 64;  W = Wq; b = bq; mask = qm[s - 1]; }
    else                 { src = p + (s - 2049) * 64; dim = 64; W = Wp; b = bp; mask = pm[s - 2049]; }

    for (int i = threadIdx.x; i < dim; i += blockDim.x) vin[i] = src[i];
    __syncthreads();

    int idx = (int)(mask * 100.0f);            // truncation matches jnp astype(int32)
    const float* ne = noise + (size_t)idx * H;

    for (int h = threadIdx.x; h < H; h += blockDim.x) {
        const float* w = W + (size_t)h * dim;
        float acc = b[h];
#pragma unroll 8
        for (int d = 0; d < dim; d++) acc = fmaf(vin[d], w[d], acc);
        x[(size_t)s * H + h] = acc + pos[(size_t)s * H + h] + ne[h];
    }
}

// ---------------- tiled SGEMM: C[M,N] = A[M,K] @ B[N,K]^T + bias (opt relu) ----------------
// 64x64 tile, BK=16, 256 threads, 4x4 per thread. N must be a multiple of 64.
template <bool RELU>
__global__ __launch_bounds__(256)
void gemm_kernel(const float* __restrict__ A, const float* __restrict__ B,
                 const float* __restrict__ bias, float* __restrict__ C,
                 int M, int N, int K)
{
    __shared__ float As[16][68];
    __shared__ float Bs[16][68];

    int tid = threadIdx.x;
    int tx = tid & 15, ty = tid >> 4;
    int bm = blockIdx.y * 64, bn = blockIdx.x * 64;

    float acc[4][4] = {};

    int lr = tid >> 2;            // 0..63
    int lk = (tid & 3) << 2;      // 0,4,8,12
    const float* Aptr = A + (size_t)(bm + lr) * K + lk;
    const float* Bptr = B + (size_t)(bn + lr) * K + lk;
    bool avalid = (bm + lr) < M;

    for (int k0 = 0; k0 < K; k0 += 16) {
        float4 av = avalid ? *(const float4*)(Aptr + k0) : make_float4(0.f, 0.f, 0.f, 0.f);
        float4 bv = *(const float4*)(Bptr + k0);
        As[lk + 0][lr] = av.x; As[lk + 1][lr] = av.y; As[lk + 2][lr] = av.z; As[lk + 3][lr] = av.w;
        Bs[lk + 0][lr] = bv.x; Bs[lk + 1][lr] = bv.y; Bs[lk + 2][lr] = bv.z; Bs[lk + 3][lr] = bv.w;
        __syncthreads();
#pragma unroll
        for (int kk = 0; kk < 16; kk++) {
            float4 a = *(const float4*)&As[kk][ty << 2];
            float4 b2 = *(const float4*)&Bs[kk][tx << 2];
            float af[4] = {a.x, a.y, a.z, a.w};
            float bf[4] = {b2.x, b2.y, b2.z, b2.w};
#pragma unroll
            for (int i = 0; i < 4; i++)
#pragma unroll
                for (int j = 0; j < 4; j++)
                    acc[i][j] = fmaf(af[i], bf[j], acc[i][j]);
        }
        __syncthreads();
    }

#pragma unroll
    for (int i = 0; i < 4; i++) {
        int row = bm + (ty << 2) + i;
        if (row >= M) continue;
#pragma unroll
        for (int j = 0; j < 4; j++) {
            int col = bn + (tx << 2) + j;
            float v = acc[i][j] + bias[col];
            if (RELU) v = fmaxf(v, 0.0f);
            C[(size_t)row * N + col] = v;
        }
    }
}

// ---------------- flash attention (fp32, online softmax) ----------------
// grid: (ceil(SEQ/64), NH); block: 256 threads (16x16), each thread 4 queries x 4 cols.
// smem: Qs[d][q] (transposed), Ks[d][k] (transposed, aliased as Ps[k][q]), Vs[k][d].
#define APAD 68
#define ATTN_SMEM (3 * 64 * APAD * 4)

__global__ __launch_bounds__(256)
void attn_kernel(const float* __restrict__ qkv, float* __restrict__ out)
{
    extern __shared__ float sm[];
    float* Qs = sm;                  // 64 x 68
    float* Ks = sm + 64 * APAD;      // 64 x 68 (aliased as Ps after scores)
    float* Vs = sm + 2 * 64 * APAD;  // 64 x 68

    int tid = threadIdx.x;
    int tx = tid & 15, ty = tid >> 4;
    int head = blockIdx.y;
    int q0 = blockIdx.x * 64;
    int coff = head * 64;

    // load Q tile transposed: Qs[d][q]
    {
        int d = (tid & 15) * 4;
        int qq = tid >> 4;
#pragma unroll
        for (int r = 0; r < 4; r++) {
            int qrow = qq + r * 16;
            float4 v = make_float4(0.f, 0.f, 0.f, 0.f);
            if (q0 + qrow < SEQ)
                v = *(const float4*)&qkv[(size_t)(q0 + qrow) * H3 + coff + d];
            Qs[(d + 0) * APAD + qrow] = v.x;
            Qs[(d + 1) * APAD + qrow] = v.y;
            Qs[(d + 2) * APAD + qrow] = v.z;
            Qs[(d + 3) * APAD + qrow] = v.w;
        }
    }

    float m[4], l[4], o[4][4];
#pragma unroll
    for (int i = 0; i < 4; i++) {
        m[i] = -1e30f; l[i] = 0.f;
#pragma unroll
        for (int j = 0; j < 4; j++) o[i][j] = 0.f;
    }

    for (int k0 = 0; k0 < SEQ; k0 += 64) {
        __syncthreads();   // prev AV reads done (also covers initial Q load)
        // load K transposed + V natural
        {
            int d = (tid & 15) * 4;
            int kk = tid >> 4;
#pragma unroll
            for (int r = 0; r < 4; r++) {
                int krow = kk + r * 16;
                float4 kv = make_float4(0.f, 0.f, 0.f, 0.f);
                float4 vv = make_float4(0.f, 0.f, 0.f, 0.f);
                if (k0 + krow < SEQ) {
                    kv = *(const float4*)&qkv[(size_t)(k0 + krow) * H3 + H  + coff + d];
                    vv = *(const float4*)&qkv[(size_t)(k0 + krow) * H3 + 2*H + coff + d];
                }
                Ks[(d + 0) * APAD + krow] = kv.x;
                Ks[(d + 1) * APAD + krow] = kv.y;
                Ks[(d + 2) * APAD + krow] = kv.z;
                Ks[(d + 3) * APAD + krow] = kv.w;
                *(float4*)&Vs[krow * APAD + d] = vv;
            }
        }
        __syncthreads();

        // scores: S = Q K^T
        float s[4][4] = {};
#pragma unroll 8
        for (int d = 0; d < 64; d++) {
            float4 qa = *(const float4*)&Qs[d * APAD + (ty << 2)];
            float4 kb = *(const float4*)&Ks[d * APAD + (tx << 2)];
            float qf[4] = {qa.x, qa.y, qa.z, qa.w};
            float kf[4] = {kb.x, kb.y, kb.z, kb.w};
#pragma unroll
            for (int i = 0; i < 4; i++)
#pragma unroll
                for (int j = 0; j < 4; j++)
                    s[i][j] = fmaf(qf[i], kf[j], s[i][j]);
        }
#pragma unroll
        for (int i = 0; i < 4; i++)
#pragma unroll
            for (int j = 0; j < 4; j++) {
                if (k0 + (tx << 2) + j >= SEQ) s[i][j] = -1e30f;
                else                            s[i][j] *= 0.125f;   // 1/sqrt(64)
            }

        __syncthreads();   // all Ks reads done before aliasing as Ps

        // online softmax; write P into Ps[k][q] (aliases Ks)
        float* Ps = Ks;
#pragma unroll
        for (int i = 0; i < 4; i++) {
            float rmax = fmaxf(fmaxf(s[i][0], s[i][1]), fmaxf(s[i][2], s[i][3]));
#pragma unroll
            for (int off = 8; off > 0; off >>= 1)
                rmax = fmaxf(rmax, __shfl_xor_sync(0xffffffffu, rmax, off));
            float mn = fmaxf(m[i], rmax);
            float corr = __expf(m[i] - mn);
            float rsum = 0.f;
#pragma unroll
            for (int j = 0; j < 4; j++) {
                float pv = __expf(s[i][j] - mn);
                Ps[((tx << 2) + j) * APAD + (ty << 2) + i] = pv;
                rsum += pv;
            }
#pragma unroll
            for (int off = 8; off > 0; off >>= 1)
                rsum += __shfl_xor_sync(0xffffffffu, rsum, off);
            l[i] = l[i] * corr + rsum;
            m[i] = mn;
#pragma unroll
            for (int j = 0; j < 4; j++) o[i][j] *= corr;
        }
        __syncthreads();   // Ps visible

        // O += P V
#pragma unroll 8
        for (int kk = 0; kk < 64; kk++) {
            float4 pa = *(const float4*)&Ps[kk * APAD + (ty << 2)];
            float4 vb = *(const float4*)&Vs[kk * APAD + (tx << 2)];
            float pf[4] = {pa.x, pa.y, pa.z, pa.w};
            float vf[4] = {vb.x, vb.y, vb.z, vb.w};
#pragma unroll
            for (int i = 0; i < 4; i++)
#pragma unroll
                for (int j = 0; j < 4; j++)
                    o[i][j] = fmaf(pf[i], vf[j], o[i][j]);
        }
    }

    // write out[q][head*64 + d] = o / l
#pragma unroll
    for (int i = 0; i < 4; i++) {
        int qrow = q0 + (ty << 2) + i;
        if (qrow < SEQ) {
            float inv = 1.0f / l[i];
            float4 v = make_float4(o[i][0] * inv, o[i][1] * inv, o[i][2] * inv, o[i][3] * inv);
            *(float4*)&out[(size_t)qrow * H + coff + (tx << 2)] = v;
        }
    }
}

// ---------------- fused add + LayerNorm (biased var, eps=1e-5) ----------------
__global__ __launch_bounds__(256)
void addln_kernel(const float* __restrict__ a, const float* __restrict__ b,
                  const float* __restrict__ w, const float* __restrict__ wb,
                  float* __restrict__ outx)
{
    int s = blockIdx.x;
    int t = threadIdx.x;
    const float4 av = ((const float4*)(a + (size_t)s * H))[t];
    const float4 bv = ((const float4*)(b + (size_t)s * H))[t];
    float v[4] = {av.x + bv.x, av.y + bv.y, av.z + bv.z, av.w + bv.w};

    float s1 = v[0] + v[1] + v[2] + v[3];
    float s2 = v[0]*v[0] + v[1]*v[1] + v[2]*v[2] + v[3]*v[3];
#pragma unroll
    for (int off = 16; off > 0; off >>= 1) {
        s1 += __shfl_xor_sync(0xffffffffu, s1, off);
        s2 += __shfl_xor_sync(0xffffffffu, s2, off);
    }
    __shared__ float r1[8], r2[8];
    int wid = t >> 5, lane = t & 31;
    if (lane == 0) { r1[wid] = s1; r2[wid] = s2; }
    __syncthreads();
    if (t == 0) {
        float a0 = 0.f, b0 = 0.f;
#pragma unroll
        for (int i = 0; i < 8; i++) { a0 += r1[i]; b0 += r2[i]; }
        r1[0] = a0; r2[0] = b0;
    }
    __syncthreads();
    float mean = r1[0] * (1.0f / H);
    float var  = r2[0] * (1.0f / H) - mean * mean;
    float rstd = rsqrtf(var + 1e-5f);

    const float4 wv  = ((const float4*)w)[t];
    const float4 wbv = ((const float4*)wb)[t];
    float4 ov;
    ov.x = (v[0] - mean) * rstd * wv.x + wbv.x;
    ov.y = (v[1] - mean) * rstd * wv.y + wbv.y;
    ov.z = (v[2] - mean) * rstd * wv.z + wbv.z;
    ov.w = (v[3] - mean) * rstd * wv.w + wbv.w;
    ((float4*)(outx + (size_t)s * H))[t] = ov;
}

// ---------------- final projection: out = Wout @ x[0] + bout ----------------
__global__ void final_kernel(const float* __restrict__ x, const float* __restrict__ Wout,
                             const float* __restrict__ bout, float* __restrict__ out)
{
    int o = threadIdx.x;   // 128 threads
    if (o >= OUTD) return;
    const float* w = Wout + (size_t)o * H;
    float acc = bout[o];
#pragma unroll 8
    for (int d = 0; d < H; d++) acc = fmaf(x[d], w[d], acc);
    out[o] = acc;
}

// ---------------- launch ----------------
extern "C" void kernel_launch(void* const* d_in, const int* in_sizes, int n_in,
                              void* d_out, int out_size)
{
    (void)in_sizes; (void)n_in; (void)out_size;
    const float* q     = (const float*)d_in[0];
    const float* p     = (const float*)d_in[1];
    const float* qm    = (const float*)d_in[2];
    const float* pm    = (const float*)d_in[3];
    const float* z     = (const float*)d_in[4];
    const float* Wq    = (const float*)d_in[5];
    const float* bq    = (const float*)d_in[6];
    const float* Wp    = (const float*)d_in[7];
    const float* bp    = (const float*)d_in[8];
    const float* Wz    = (const float*)d_in[9];
    const float* bz    = (const float*)d_in[10];
    const float* pos   = (const float*)d_in[11];
    const float* noise = (const float*)d_in[12];
    const float* Wqkv  = (const float*)d_in[13];
    const float* bqkv  = (const float*)d_in[14];
    const float* Wo    = (const float*)d_in[15];
    const float* bo    = (const float*)d_in[16];
    const float* ln1w  = (const float*)d_in[17];
    const float* ln1b  = (const float*)d_in[18];
    const float* W1    = (const float*)d_in[19];
    const float* b1    = (const float*)d_in[20];
    const float* W2    = (const float*)d_in[21];
    const float* b2    = (const float*)d_in[22];
    const float* ln2w  = (const float*)d_in[23];
    const float* ln2b  = (const float*)d_in[24];
    const float* Wout  = (const float*)d_in[25];
    const float* bout  = (const float*)d_in[26];

    float *x, *qkvb, *attnb, *tmp, *ff;
    cudaGetSymbolAddress((void**)&x,     g_x);
    cudaGetSymbolAddress((void**)&qkvb,  g_qkv);
    cudaGetSymbolAddress((void**)&attnb, g_attn);
    cudaGetSymbolAddress((void**)&tmp,   g_tmp);
    cudaGetSymbolAddress((void**)&ff,    g_ff);

    cudaFuncSetAttribute(attn_kernel, cudaFuncAttributeMaxDynamicSharedMemorySize, ATTN_SMEM);

    embed_kernel<<<SEQ, 256>>>(q, p, qm, pm, z, Wq, bq, Wp, bp, Wz, bz, pos, noise, x);

    const int MT = (SEQ + 63) / 64;   // 65 row tiles
    for (int i = 0; i < LAYERS; i++) {
        gemm_kernel<false><<<dim3(H3 / 64, MT), 256>>>(
            x, Wqkv + (size_t)i * H3 * H, bqkv + (size_t)i * H3, qkvb, SEQ, H3, H);
        attn_kernel<<<dim3(MT, NH), 256, ATTN_SMEM>>>(qkvb, attnb);
        gemm_kernel<false><<<dim3(H / 64, MT), 256>>>(
            attnb, Wo + (size_t)i * H * H, bo + (size_t)i * H, tmp, SEQ, H, H);
        addln_kernel<<<SEQ, 256>>>(x, tmp, ln1w + (size_t)i * H, ln1b + (size_t)i * H, x);
        gemm_kernel<true><<<dim3(FFD / 64, MT), 256>>>(
            x, W1 + (size_t)i * FFD * H, b1 + (size_t)i * FFD, ff, SEQ, FFD, H);
        gemm_kernel<false><<<dim3(H / 64, MT), 256>>>(
            ff, W2 + (size_t)i * H * FFD, b2 + (size_t)i * H, tmp, SEQ, H, FFD);
        addln_kernel<<<SEQ, 256>>>(x, tmp, ln2w + (size_t)i * H, ln2b + (size_t)i * H, x);
    }

    final_kernel<<<1, 128>>>(x, Wout, bout, (float*)d_out);
}

// round 2
// speedup vs baseline: 1.4099x; 1.4099x over previous
#include <cuda_runtime.h>
#include <cuda_pipeline.h>
#include <mma.h>
#include <math.h>

using namespace nvcuda;

#define SEQ  4097
#define SEQP 4224          // 33 * 128, padded
#define H    1024
#define NH   16
#define HD   64
#define H3   3072
#define FFD  4096
#define LAYERS 6
#define OUTD 128

// ---------------- scratch (device globals; no allocations) ----------------
__device__ float g_x[SEQP * H];
__device__ float g_qkv[SEQP * H3];
__device__ float g_attn[SEQP * H];
__device__ float g_tmp[SEQP * H];
__device__ float g_ff[SEQP * FFD];

// ---------------- embedding ----------------
__global__ void embed_kernel(
    const float* __restrict__ q, const float* __restrict__ p,
    const float* __restrict__ qm, const float* __restrict__ pm,
    const float* __restrict__ z,
    const float* __restrict__ Wq, const float* __restrict__ bq,
    const float* __restrict__ Wp, const float* __restrict__ bp,
    const float* __restrict__ Wz, const float* __restrict__ bz,
    const float* __restrict__ pos, const float* __restrict__ noise,
    float* __restrict__ x)
{
    int s = blockIdx.x;
    if (s >= SEQ) {                       // zero pad rows
        for (int h = threadIdx.x; h < H; h += blockDim.x)
            x[(size_t)s * H + h] = 0.0f;
        return;
    }
    __shared__ float vin[128];
    const float *W, *b, *src;
    int dim;
    float mask;
    if (s == 0)          { src = z;                   dim = 128; W = Wz; b = bz; mask = 1.0f; }
    else if (s <= 2048)  { src = q + (s - 1) * 64;    dim = 64;  W = Wq; b = bq; mask = qm[s - 1]; }
    else                 { src = p + (s - 2049) * 64; dim = 64;  W = Wp; b = bp; mask = pm[s - 2049]; }

    for (int i = threadIdx.x; i < dim; i += blockDim.x) vin[i] = src[i];
    __syncthreads();

    int idx = (int)(mask * 100.0f);
    const float* ne = noise + (size_t)idx * H;

    for (int h = threadIdx.x; h < H; h += blockDim.x) {
        const float* w = W + (size_t)h * dim;
        float acc = b[h];
#pragma unroll 8
        for (int d = 0; d < dim; d++) acc = fmaf(vin[d], w[d], acc);
        x[(size_t)s * H + h] = acc + pos[(size_t)s * H + h] + ne[h];
    }
}

// ---------------- TF32 tensor-core GEMM ----------------
// C[M,N] = A[M,K] @ W[N,K]^T + bias  (optional ReLU)
// BM=BN=128, BK=32, 256 threads / 8 warps, warp tile 64x32 (4x2 wmma 16x16x8).
// cp.async double-buffered staging. M, N multiples of 128; K multiple of 32.
#define GLDT 36
#define GTILE (128 * GLDT)
#define GEMM_SMEM (4 * GTILE * 4)   // 73728 bytes
#define GLDC 136

template <bool RELU>
__global__ __launch_bounds__(256)
void tgemm(const float* __restrict__ A, const float* __restrict__ W,
           const float* __restrict__ bias, float* __restrict__ C,
           int M, int N, int K)
{
    extern __shared__ float smg[];
    float* AsBuf[2] = { smg,             smg + 2 * GTILE };
    float* BsBuf[2] = { smg + GTILE,     smg + 3 * GTILE };

    int t  = threadIdx.x;
    int w  = t >> 5;
    int bm = blockIdx.y * 128, bn = blockIdx.x * 128;
    int wm = w >> 2, wn = w & 3;     // wm 0..1 (64 rows), wn 0..3 (32 cols)

    const float* Ab = A + (size_t)bm * K;
    const float* Wb = W + (size_t)bn * K;

    wmma::fragment<wmma::accumulator, 16, 16, 8, float> c[4][2];
#pragma unroll
    for (int i = 0; i < 4; i++)
#pragma unroll
        for (int j = 0; j < 2; j++) wmma::fill_fragment(c[i][j], 0.0f);

    int kt = K / 32;

    // stage tile k into buffer buf
    auto stage = [&](int buf, int k0) {
#pragma unroll
        for (int v = 0; v < 4; v++) {
            int linear = t + v * 256;
            int row = linear >> 3;
            int qq  = (linear & 7) << 2;
            __pipeline_memcpy_async(&AsBuf[buf][row * GLDT + qq],
                                    Ab + (size_t)row * K + k0 + qq, 16);
            __pipeline_memcpy_async(&BsBuf[buf][row * GLDT + qq],
                                    Wb + (size_t)row * K + k0 + qq, 16);
        }
        __pipeline_commit();
    };

    stage(0, 0);
    for (int it = 0; it < kt; it++) {
        if (it + 1 < kt) stage((it + 1) & 1, (it + 1) * 32);
        __pipeline_wait_prior((it + 1 < kt) ? 1 : 0);
        __syncthreads();

        const float* Ap = AsBuf[it & 1];
        const float* Bp = BsBuf[it & 1];
#pragma unroll
        for (int kk = 0; kk < 32; kk += 8) {
            wmma::fragment<wmma::matrix_a, 16, 16, 8, wmma::precision::tf32, wmma::row_major> a[4];
            wmma::fragment<wmma::matrix_b, 16, 16, 8, wmma::precision::tf32, wmma::col_major> b[2];
#pragma unroll
            for (int i = 0; i < 4; i++) {
                wmma::load_matrix_sync(a[i], Ap + (wm * 64 + i * 16) * GLDT + kk, GLDT);
#pragma unroll
                for (int e = 0; e < a[i].num_elements; e++)
                    a[i].x[e] = wmma::__float_to_tf32(a[i].x[e]);
            }
#pragma unroll
            for (int j = 0; j < 2; j++) {
                wmma::load_matrix_sync(b[j], Bp + (wn * 32 + j * 16) * GLDT + kk, GLDT);
#pragma unroll
                for (int e = 0; e < b[j].num_elements; e++)
                    b[j].x[e] = wmma::__float_to_tf32(b[j].x[e]);
            }
#pragma unroll
            for (int i = 0; i < 4; i++)
#pragma unroll
                for (int j = 0; j < 2; j++)
                    wmma::mma_sync(c[i][j], a[i], b[j], c[i][j]);
        }
        __syncthreads();
    }

    // epilogue: stage C tile in smem, add bias (+relu), vectorized global store
    float* Cs = smg;   // 128 x GLDC floats (17408 <= 18432 available)
#pragma unroll
    for (int i = 0; i < 4; i++)
#pragma unroll
        for (int j = 0; j < 2; j++)
            wmma::store_matrix_sync(Cs + (wm * 64 + i * 16) * GLDC + wn * 32 + j * 16,
                                    c[i][j], GLDC, wmma::mem_row_major);
    __syncthreads();

#pragma unroll
    for (int v = 0; v < 16; v++) {
        int linear = t + v * 256;
        int row = linear >> 5;
        int qq  = (linear & 31) << 2;
        float4 val = *(float4*)&Cs[row * GLDC + qq];
        float4 bb  = *(const float4*)&bias[bn + qq];
        val.x += bb.x; val.y += bb.y; val.z += bb.z; val.w += bb.w;
        if (RELU) {
            val.x = fmaxf(val.x, 0.f); val.y = fmaxf(val.y, 0.f);
            val.z = fmaxf(val.z, 0.f); val.w = fmaxf(val.w, 0.f);
        }
        *(float4*)&C[(size_t)(bm + row) * N + bn + qq] = val;
    }
}

// ---------------- flash attention, TF32 tensor cores ----------------
// grid: (SEQP/64, NH); 256 threads / 8 warps. Per block: 64 queries, one head.
// smem: Qs,Ks,Vs,Ps (64x68) + Sc scratch (64x68).
#define AP 68
#define ATILE (64 * AP)
#define ATTN_SMEM (5 * ATILE * 4)   // 87040 bytes

__global__ __launch_bounds__(256)
void attn_kernel(const float* __restrict__ qkv, float* __restrict__ out)
{
    extern __shared__ float sma[];
    float* Qs = sma;
    float* Ks = sma + ATILE;
    float* Vs = sma + 2 * ATILE;
    float* Ps = sma + 3 * ATILE;
    float* Sc = sma + 4 * ATILE;

    int t = threadIdx.x;
    int tx = t & 15, ty = t >> 4;
    int tx4 = tx << 2, ty4 = ty << 2;
    int w = t >> 5;
    int wm = w & 3, wn = w >> 2;      // wm: 16-row band, wn: 32-col half
    int head = blockIdx.y;
    int q0 = blockIdx.x * 64;
    int coff = head * 64;

    // load Q tile natural [q][d]
#pragma unroll
    for (int v = 0; v < 4; v++) {
        int linear = t + v * 256;
        int row = linear >> 4;
        int qq  = (linear & 15) << 2;
        __pipeline_memcpy_async(&Qs[row * AP + qq],
                                &qkv[(size_t)(q0 + row) * H3 + coff + qq], 16);
    }
    __pipeline_commit();

    float m[4], l[4], o[4][4];
#pragma unroll
    for (int i = 0; i < 4; i++) {
        m[i] = -1e30f; l[i] = 0.f;
#pragma unroll
        for (int j = 0; j < 4; j++) o[i][j] = 0.f;
    }

    for (int k0 = 0; k0 < SEQ; k0 += 64) {
        __syncthreads();   // prev iteration's Sc/Ps reads done; K/V reusable
        // load K,V tiles natural [k][d] (rows < SEQP always valid memory)
#pragma unroll
        for (int v = 0; v < 4; v++) {
            int linear = t + v * 256;
            int row = linear >> 4;
            int qq  = (linear & 15) << 2;
            __pipeline_memcpy_async(&Ks[row * AP + qq],
                                    &qkv[(size_t)(k0 + row) * H3 + H + coff + qq], 16);
            __pipeline_memcpy_async(&Vs[row * AP + qq],
                                    &qkv[(size_t)(k0 + row) * H3 + 2 * H + coff + qq], 16);
        }
        __pipeline_commit();
        __pipeline_wait_prior(0);
        __syncthreads();

        // S = Q @ K^T  (wmma: A=Qs row-major, B=Ks col-major view)
        {
            wmma::fragment<wmma::accumulator, 16, 16, 8, float> cs[2];
            wmma::fill_fragment(cs[0], 0.0f);
            wmma::fill_fragment(cs[1], 0.0f);
#pragma unroll
            for (int d = 0; d < 64; d += 8) {
                wmma::fragment<wmma::matrix_a, 16, 16, 8, wmma::precision::tf32, wmma::row_major> a;
                wmma::load_matrix_sync(a, Qs + wm * 16 * AP + d, AP);
#pragma unroll
                for (int e = 0; e < a.num_elements; e++) a.x[e] = wmma::__float_to_tf32(a.x[e]);
#pragma unroll
                for (int j = 0; j < 2; j++) {
                    wmma::fragment<wmma::matrix_b, 16, 16, 8, wmma::precision::tf32, wmma::col_major> b;
                    wmma::load_matrix_sync(b, Ks + (wn * 32 + j * 16) * AP + d, AP);
#pragma unroll
                    for (int e = 0; e < b.num_elements; e++) b.x[e] = wmma::__float_to_tf32(b.x[e]);
                    wmma::mma_sync(cs[j], a, b, cs[j]);
                }
            }
            wmma::store_matrix_sync(Sc + wm * 16 * AP + wn * 32,      cs[0], AP, wmma::mem_row_major);
            wmma::store_matrix_sync(Sc + wm * 16 * AP + wn * 32 + 16, cs[1], AP, wmma::mem_row_major);
        }
        __syncthreads();

        // online softmax: read Sc, update (m,l,o-scale), write P row-major
#pragma unroll
        for (int i = 0; i < 4; i++) {
            int row = ty4 + i;
            float sv[4];
#pragma unroll
            for (int j = 0; j < 4; j++) {
                float x = Sc[row * AP + tx4 + j] * 0.125f;   // 1/sqrt(64)
                sv[j] = (k0 + tx4 + j < SEQ) ? x : -1e30f;
            }
            float rmax = fmaxf(fmaxf(sv[0], sv[1]), fmaxf(sv[2], sv[3]));
#pragma unroll
            for (int off = 8; off > 0; off >>= 1)
                rmax = fmaxf(rmax, __shfl_xor_sync(0xffffffffu, rmax, off));
            float mn = fmaxf(m[i], rmax);
            float corr = __expf(m[i] - mn);
            float rsum = 0.f;
#pragma unroll
            for (int j = 0; j < 4; j++) {
                float pv = __expf(sv[j] - mn);
                Ps[row * AP + tx4 + j] = pv;
                rsum += pv;
            }
#pragma unroll
            for (int off = 8; off > 0; off >>= 1)
                rsum += __shfl_xor_sync(0xffffffffu, rsum, off);
            l[i] = l[i] * corr + rsum;
            m[i] = mn;
#pragma unroll
            for (int j = 0; j < 4; j++) o[i][j] *= corr;
        }
        __syncthreads();

        // PV = P @ V  (A=Ps row-major, B=Vs row-major) -> Sc
        {
            wmma::fragment<wmma::accumulator, 16, 16, 8, float> cv[2];
            wmma::fill_fragment(cv[0], 0.0f);
            wmma::fill_fragment(cv[1], 0.0f);
#pragma unroll
            for (int kk = 0; kk < 64; kk += 8) {
                wmma::fragment<wmma::matrix_a, 16, 16, 8, wmma::precision::tf32, wmma::row_major> a;
                wmma::load_matrix_sync(a, Ps + wm * 16 * AP + kk, AP);
#pragma unroll
                for (int e = 0; e < a.num_elements; e++) a.x[e] = wmma::__float_to_tf32(a.x[e]);
#pragma unroll
                for (int j = 0; j < 2; j++) {
                    wmma::fragment<wmma::matrix_b, 16, 16, 8, wmma::precision::tf32, wmma::row_major> b;
                    wmma::load_matrix_sync(b, Vs + kk * AP + wn * 32 + j * 16, AP);
#pragma unroll
                    for (int e = 0; e < b.num_elements; e++) b.x[e] = wmma::__float_to_tf32(b.x[e]);
                    wmma::mma_sync(cv[j], a, b, cv[j]);
                }
            }
            wmma::store_matrix_sync(Sc + wm * 16 * AP + wn * 32,      cv[0], AP, wmma::mem_row_major);
            wmma::store_matrix_sync(Sc + wm * 16 * AP + wn * 32 + 16, cv[1], AP, wmma::mem_row_major);
        }
        __syncthreads();

        // accumulate into per-thread O
#pragma unroll
        for (int i = 0; i < 4; i++)
#pragma unroll
            for (int j = 0; j < 4; j++)
                o[i][j] += Sc[(ty4 + i) * AP + tx4 + j];
    }

    // write out (all SEQP rows; pad rows are finite garbage, masked upstream)
#pragma unroll
    for (int i = 0; i < 4; i++) {
        int qrow = q0 + ty4 + i;
        float inv = 1.0f / l[i];
        float4 v = make_float4(o[i][0] * inv, o[i][1] * inv, o[i][2] * inv, o[i][3] * inv);
        *(float4*)&out[(size_t)qrow * H + coff + tx4] = v;
    }
}

// ---------------- fused add + LayerNorm ----------------
__global__ __launch_bounds__(256)
void addln_kernel(const float* __restrict__ a, const float* __restrict__ b,
                  const float* __restrict__ w, const float* __restrict__ wb,
                  float* __restrict__ outx)
{
    int s = blockIdx.x;
    int t = threadIdx.x;
    const float4 av = ((const float4*)(a + (size_t)s * H))[t];
    const float4 bv = ((const float4*)(b + (size_t)s * H))[t];
    float v[4] = {av.x + bv.x, av.y + bv.y, av.z + bv.z, av.w + bv.w};

    float s1 = v[0] + v[1] + v[2] + v[3];
    float s2 = v[0]*v[0] + v[1]*v[1] + v[2]*v[2] + v[3]*v[3];
#pragma unroll
    for (int off = 16; off > 0; off >>= 1) {
        s1 += __shfl_xor_sync(0xffffffffu, s1, off);
        s2 += __shfl_xor_sync(0xffffffffu, s2, off);
    }
    __shared__ float r1[8], r2[8];
    int wid = t >> 5, lane = t & 31;
    if (lane == 0) { r1[wid] = s1; r2[wid] = s2; }
    __syncthreads();
    if (t == 0) {
        float a0 = 0.f, b0 = 0.f;
#pragma unroll
        for (int i = 0; i < 8; i++) { a0 += r1[i]; b0 += r2[i]; }
        r1[0] = a0; r2[0] = b0;
    }
    __syncthreads();
    float mean = r1[0] * (1.0f / H);
    float var  = r2[0] * (1.0f / H) - mean * mean;
    float rstd = rsqrtf(var + 1e-5f);

    const float4 wv  = ((const float4*)w)[t];
    const float4 wbv = ((const float4*)wb)[t];
    float4 ov;
    ov.x = (v[0] - mean) * rstd * wv.x + wbv.x;
    ov.y = (v[1] - mean) * rstd * wv.y + wbv.y;
    ov.z = (v[2] - mean) * rstd * wv.z + wbv.z;
    ov.w = (v[3] - mean) * rstd * wv.w + wbv.w;
    ((float4*)(outx + (size_t)s * H))[t] = ov;
}

// ---------------- final projection ----------------
__global__ void final_kernel(const float* __restrict__ x, const float* __restrict__ Wout,
                             const float* __restrict__ bout, float* __restrict__ out)
{
    int o = threadIdx.x;
    if (o >= OUTD) return;
    const float* w = Wout + (size_t)o * H;
    float acc = bout[o];
#pragma unroll 8
    for (int d = 0; d < H; d++) acc = fmaf(x[d], w[d], acc);
    out[o] = acc;
}

// ---------------- launch ----------------
extern "C" void kernel_launch(void* const* d_in, const int* in_sizes, int n_in,
                              void* d_out, int out_size)
{
    (void)in_sizes; (void)n_in; (void)out_size;
    const float* q     = (const float*)d_in[0];
    const float* p     = (const float*)d_in[1];
    const float* qm    = (const float*)d_in[2];
    const float* pm    = (const float*)d_in[3];
    const float* z     = (const float*)d_in[4];
    const float* Wq    = (const float*)d_in[5];
    const float* bq    = (const float*)d_in[6];
    const float* Wp    = (const float*)d_in[7];
    const float* bp    = (const float*)d_in[8];
    const float* Wz    = (const float*)d_in[9];
    const float* bz    = (const float*)d_in[10];
    const float* pos   = (const float*)d_in[11];
    const float* noise = (const float*)d_in[12];
    const float* Wqkv  = (const float*)d_in[13];
    const float* bqkv  = (const float*)d_in[14];
    const float* Wo    = (const float*)d_in[15];
    const float* bo    = (const float*)d_in[16];
    const float* ln1w  = (const float*)d_in[17];
    const float* ln1b  = (const float*)d_in[18];
    const float* W1    = (const float*)d_in[19];
    const float* b1    = (const float*)d_in[20];
    const float* W2    = (const float*)d_in[21];
    const float* b2    = (const float*)d_in[22];
    const float* ln2w  = (const float*)d_in[23];
    const float* ln2b  = (const float*)d_in[24];
    const float* Wout  = (const float*)d_in[25];
    const float* bout  = (const float*)d_in[26];

    float *x, *qkvb, *attnb, *tmp, *ff;
    cudaGetSymbolAddress((void**)&x,     g_x);
    cudaGetSymbolAddress((void**)&qkvb,  g_qkv);
    cudaGetSymbolAddress((void**)&attnb, g_attn);
    cudaGetSymbolAddress((void**)&tmp,   g_tmp);
    cudaGetSymbolAddress((void**)&ff,    g_ff);

    cudaFuncSetAttribute(tgemm<false>, cudaFuncAttributeMaxDynamicSharedMemorySize, GEMM_SMEM);
    cudaFuncSetAttribute(tgemm<true>,  cudaFuncAttributeMaxDynamicSharedMemorySize, GEMM_SMEM);
    cudaFuncSetAttribute(attn_kernel,  cudaFuncAttributeMaxDynamicSharedMemorySize, ATTN_SMEM);

    embed_kernel<<<SEQP, 256>>>(q, p, qm, pm, z, Wq, bq, Wp, bp, Wz, bz, pos, noise, x);

    const int MB = SEQP / 128;   // 33
    for (int i = 0; i < LAYERS; i++) {
        tgemm<false><<<dim3(H3 / 128, MB), 256, GEMM_SMEM>>>(
            x, Wqkv + (size_t)i * H3 * H, bqkv + (size_t)i * H3, qkvb, SEQP, H3, H);
        attn_kernel<<<dim3(SEQP / 64, NH), 256, ATTN_SMEM>>>(qkvb, attnb);
        tgemm<false><<<dim3(H / 128, MB), 256, GEMM_SMEM>>>(
            attnb, Wo + (size_t)i * H * H, bo + (size_t)i * H, tmp, SEQP, H, H);
        addln_kernel<<<SEQP, 256>>>(x, tmp, ln1w + (size_t)i * H, ln1b + (size_t)i * H, x);
        tgemm<true><<<dim3(FFD / 128, MB), 256, GEMM_SMEM>>>(
            x, W1 + (size_t)i * FFD * H, b1 + (size_t)i * FFD, ff, SEQP, FFD, H);
        tgemm<false><<<dim3(H / 128, MB), 256, GEMM_SMEM>>>(
            ff, W2 + (size_t)i * H * FFD, b2 + (size_t)i * H, tmp, SEQP, H, FFD);
        addln_kernel<<<SEQP, 256>>>(x, tmp, ln2w + (size_t)i * H, ln2b + (size_t)i * H, x);
    }

    final_kernel<<<1, 128>>>(x, Wout, bout, (float*)d_out);
}

// round 3
// speedup vs baseline: 1.8437x; 1.3077x over previous
#include <cuda_runtime.h>
#include <cuda_pipeline.h>
#include <mma.h>
#include <math.h>
#include <stdint.h>

using namespace nvcuda;

#define SEQ  4097
#define SEQP 4224          // 33 * 128, padded
#define H    1024
#define NH   16
#define HD   64
#define H3   3072
#define FFD  4096
#define LAYERS 6
#define OUTD 128

// ---------------- scratch (device globals; no allocations) ----------------
__device__ float g_x[SEQP * H];
__device__ float g_qkv[SEQP * H3];
__device__ float g_attn[SEQP * H];
__device__ float g_tmp[SEQP * H];
__device__ float g_ff[SEQP * FFD];

__device__ __forceinline__ uint32_t f2tf(float x) {
    uint32_t r;
    asm("cvt.rna.tf32.f32 %0, %1;" : "=r"(r) : "f"(x));
    return r;
}

__device__ __forceinline__ void mma_tf32(float& d0, float& d1, float& d2, float& d3,
                                         uint32_t a0, uint32_t a1, uint32_t a2, uint32_t a3,
                                         uint32_t b0, uint32_t b1)
{
    asm volatile("mma.sync.aligned.m16n8k8.row.col.f32.tf32.tf32.f32 "
                 "{%0,%1,%2,%3},{%4,%5,%6,%7},{%8,%9},{%0,%1,%2,%3};"
                 : "+f"(d0), "+f"(d1), "+f"(d2), "+f"(d3)
                 : "r"(a0), "r"(a1), "r"(a2), "r"(a3), "r"(b0), "r"(b1));
}

// ---------------- embedding ----------------
__global__ void embed_kernel(
    const float* __restrict__ q, const float* __restrict__ p,
    const float* __restrict__ qm, const float* __restrict__ pm,
    const float* __restrict__ z,
    const float* __restrict__ Wq, const float* __restrict__ bq,
    const float* __restrict__ Wp, const float* __restrict__ bp,
    const float* __restrict__ Wz, const float* __restrict__ bz,
    const float* __restrict__ pos, const float* __restrict__ noise,
    float* __restrict__ x)
{
    int s = blockIdx.x;
    if (s >= SEQ) {
        for (int h = threadIdx.x; h < H; h += blockDim.x)
            x[(size_t)s * H + h] = 0.0f;
        return;
    }
    __shared__ float vin[128];
    const float *W, *b, *src;
    int dim;
    float mask;
    if (s == 0)          { src = z;                   dim = 128; W = Wz; b = bz; mask = 1.0f; }
    else if (s <= 2048)  { src = q + (s - 1) * 64;    dim = 64;  W = Wq; b = bq; mask = qm[s - 1]; }
    else                 { src = p + (s - 2049) * 64; dim = 64;  W = Wp; b = bp; mask = pm[s - 2049]; }

    for (int i = threadIdx.x; i < dim; i += blockDim.x) vin[i] = src[i];
    __syncthreads();

    int idx = (int)(mask * 100.0f);
    const float* ne = noise + (size_t)idx * H;

    for (int h = threadIdx.x; h < H; h += blockDim.x) {
        const float* w = W + (size_t)h * dim;
        float acc = b[h];
#pragma unroll 8
        for (int d = 0; d < dim; d++) acc = fmaf(vin[d], w[d], acc);
        x[(size_t)s * H + h] = acc + pos[(size_t)s * H + h] + ne[h];
    }
}

// ---------------- TF32 tensor-core GEMM (unchanged from R2) ----------------
#define GLDT 36
#define GTILE (128 * GLDT)
#define GEMM_SMEM (4 * GTILE * 4)
#define GLDC 136

template <bool RELU>
__global__ __launch_bounds__(256)
void tgemm(const float* __restrict__ A, const float* __restrict__ W,
           const float* __restrict__ bias, float* __restrict__ C,
           int M, int N, int K)
{
    extern __shared__ float smg[];
    float* AsBuf[2] = { smg,             smg + 2 * GTILE };
    float* BsBuf[2] = { smg + GTILE,     smg + 3 * GTILE };

    int t  = threadIdx.x;
    int w  = t >> 5;
    int bm = blockIdx.y * 128, bn = blockIdx.x * 128;
    int wm = w >> 2, wn = w & 3;

    const float* Ab = A + (size_t)bm * K;
    const float* Wb = W + (size_t)bn * K;

    wmma::fragment<wmma::accumulator, 16, 16, 8, float> c[4][2];
#pragma unroll
    for (int i = 0; i < 4; i++)
#pragma unroll
        for (int j = 0; j < 2; j++) wmma::fill_fragment(c[i][j], 0.0f);

    int kt = K / 32;

    auto stage = [&](int buf, int k0) {
#pragma unroll
        for (int v = 0; v < 4; v++) {
            int linear = t + v * 256;
            int row = linear >> 3;
            int qq  = (linear & 7) << 2;
            __pipeline_memcpy_async(&AsBuf[buf][row * GLDT + qq],
                                    Ab + (size_t)row * K + k0 + qq, 16);
            __pipeline_memcpy_async(&BsBuf[buf][row * GLDT + qq],
                                    Wb + (size_t)row * K + k0 + qq, 16);
        }
        __pipeline_commit();
    };

    stage(0, 0);
    for (int it = 0; it < kt; it++) {
        if (it + 1 < kt) stage((it + 1) & 1, (it + 1) * 32);
        __pipeline_wait_prior((it + 1 < kt) ? 1 : 0);
        __syncthreads();

        const float* Ap = AsBuf[it & 1];
        const float* Bp = BsBuf[it & 1];
#pragma unroll
        for (int kk = 0; kk < 32; kk += 8) {
            wmma::fragment<wmma::matrix_a, 16, 16, 8, wmma::precision::tf32, wmma::row_major> a[4];
            wmma::fragment<wmma::matrix_b, 16, 16, 8, wmma::precision::tf32, wmma::col_major> b[2];
#pragma unroll
            for (int i = 0; i < 4; i++) {
                wmma::load_matrix_sync(a[i], Ap + (wm * 64 + i * 16) * GLDT + kk, GLDT);
#pragma unroll
                for (int e = 0; e < a[i].num_elements; e++)
                    a[i].x[e] = wmma::__float_to_tf32(a[i].x[e]);
            }
#pragma unroll
            for (int j = 0; j < 2; j++) {
                wmma::load_matrix_sync(b[j], Bp + (wn * 32 + j * 16) * GLDT + kk, GLDT);
#pragma unroll
                for (int e = 0; e < b[j].num_elements; e++)
                    b[j].x[e] = wmma::__float_to_tf32(b[j].x[e]);
            }
#pragma unroll
            for (int i = 0; i < 4; i++)
#pragma unroll
                for (int j = 0; j < 2; j++)
                    wmma::mma_sync(c[i][j], a[i], b[j], c[i][j]);
        }
        __syncthreads();
    }

    float* Cs = smg;
#pragma unroll
    for (int i = 0; i < 4; i++)
#pragma unroll
        for (int j = 0; j < 2; j++)
            wmma::store_matrix_sync(Cs + (wm * 64 + i * 16) * GLDC + wn * 32 + j * 16,
                                    c[i][j], GLDC, wmma::mem_row_major);
    __syncthreads();

#pragma unroll
    for (int v = 0; v < 16; v++) {
        int linear = t + v * 256;
        int row = linear >> 5;
        int qq  = (linear & 31) << 2;
        float4 val = *(float4*)&Cs[row * GLDC + qq];
        float4 bb  = *(const float4*)&bias[bn + qq];
        val.x += bb.x; val.y += bb.y; val.z += bb.z; val.w += bb.w;
        if (RELU) {
            val.x = fmaxf(val.x, 0.f); val.y = fmaxf(val.y, 0.f);
            val.z = fmaxf(val.z, 0.f); val.w = fmaxf(val.w, 0.f);
        }
        *(float4*)&C[(size_t)(bm + row) * N + bn + qq] = val;
    }
}

// ---------------- flash attention, register-resident FA2, raw mma tf32 ----------------
// grid (SEQP/128, NH), 256 threads / 8 warps. Warp w owns 16 query rows.
// K/V staged gmem->regs->smem (tf32 converted once), double buffered.
// Softmax fully in registers (row lives in one quad). P via warp-private smem.
#define KST 68            // K smem row stride (floats)
#define VST 72            // V smem row stride
#define PST 68            // P smem row stride
#define KBUF (64 * KST)
#define VBUF (64 * VST)
#define ATTN_SMEM ((2 * KBUF + 2 * VBUF + 8 * 16 * PST) * 4)

__global__ __launch_bounds__(256)
void attn_kernel(const float* __restrict__ qkv, float* __restrict__ out)
{
    extern __shared__ float sma[];
    float* Ksm[2] = { sma, sma + KBUF };
    float* Vsm[2] = { sma + 2 * KBUF, sma + 2 * KBUF + VBUF };
    float* Pall   = sma + 2 * KBUF + 2 * VBUF;

    const int t    = threadIdx.x;
    const int lane = t & 31;
    const int w    = t >> 5;
    const int quad = lane >> 2;       // 0..7
    const int tig  = lane & 3;        // 0..3
    const int head = blockIdx.y;
    const int q0   = blockIdx.x * 128;
    const int coff = head * 64;

    float* Pme = Pall + w * 16 * PST;

    // ---- Q fragments: rows [q0 + w*16, +16), pre-scaled by 1/8, tf32 ----
    uint32_t Qa[8][4];
    {
        const float* qb = qkv + (size_t)(q0 + w * 16) * H3 + coff;
#pragma unroll
        for (int c = 0; c < 8; c++) {
            int col = 8 * c + tig;
            Qa[c][0] = f2tf(qb[(size_t)quad * H3 + col]       * 0.125f);
            Qa[c][1] = f2tf(qb[(size_t)(quad + 8) * H3 + col] * 0.125f);
            Qa[c][2] = f2tf(qb[(size_t)quad * H3 + col + 4]       * 0.125f);
            Qa[c][3] = f2tf(qb[(size_t)(quad + 8) * H3 + col + 4] * 0.125f);
        }
    }

    // ---- O accumulators, m, l ----
    float o[8][4];
#pragma unroll
    for (int nb = 0; nb < 8; nb++)
#pragma unroll
        for (int e = 0; e < 4; e++) o[nb][e] = 0.f;
    float m0 = -1e30f, m1 = -1e30f, l0 = 0.f, l1 = 0.f;

    // ---- K/V staging: thread -> (row = t>>2, 16-col segment = (t&3)*16) ----
    const int krow  = t >> 2;
    const int kcol0 = (t & 3) * 16;
    float4 kreg[4], vreg[4];

    auto ldKV = [&](int k0) {
        const float* kb = qkv + (size_t)(k0 + krow) * H3 + H     + coff + kcol0;
        const float* vb = qkv + (size_t)(k0 + krow) * H3 + 2 * H + coff + kcol0;
#pragma unroll
        for (int i = 0; i < 4; i++) {
            kreg[i] = *(const float4*)(kb + 4 * i);
            vreg[i] = *(const float4*)(vb + 4 * i);
        }
    };
    auto stKV = [&](int buf) {
        float* kd = Ksm[buf] + krow * KST + kcol0;
        float* vd = Vsm[buf] + krow * VST + kcol0;
#pragma unroll
        for (int i = 0; i < 4; i++) {
            float4 kv = kreg[i], vv = vreg[i];
            kv.x = __uint_as_float(f2tf(kv.x)); kv.y = __uint_as_float(f2tf(kv.y));
            kv.z = __uint_as_float(f2tf(kv.z)); kv.w = __uint_as_float(f2tf(kv.w));
            vv.x = __uint_as_float(f2tf(vv.x)); vv.y = __uint_as_float(f2tf(vv.y));
            vv.z = __uint_as_float(f2tf(vv.z)); vv.w = __uint_as_float(f2tf(vv.w));
            *(float4*)(kd + 4 * i) = kv;
            *(float4*)(vd + 4 * i) = vv;
        }
    };

    const int NITER = (SEQ + 63) / 64;   // 65

    ldKV(0);
    stKV(0);
    __syncthreads();

    for (int it = 0; it < NITER; it++) {
        const int k0 = it * 64;
        const float* Kb = Ksm[it & 1];
        const float* Vb = Vsm[it & 1];

        if (it + 1 < NITER) ldKV((it + 1) * 64);   // prefetch next tile into regs

        // ---- S = Q @ K^T (scaled) ----
        float s[8][4];
#pragma unroll
        for (int jb = 0; jb < 8; jb++) {
            s[jb][0] = s[jb][1] = s[jb][2] = s[jb][3] = 0.f;
#pragma unroll
            for (int c = 0; c < 8; c++) {
                uint32_t b0 = __float_as_uint(Kb[(8 * jb + quad) * KST + 8 * c + tig]);
                uint32_t b1 = __float_as_uint(Kb[(8 * jb + quad) * KST + 8 * c + tig + 4]);
                mma_tf32(s[jb][0], s[jb][1], s[jb][2], s[jb][3],
                         Qa[c][0], Qa[c][1], Qa[c][2], Qa[c][3], b0, b1);
            }
        }

        // ---- tail masking (last tile only) ----
        if (k0 + 64 > SEQ) {
#pragma unroll
            for (int jb = 0; jb < 8; jb++) {
                int col0 = k0 + jb * 8 + 2 * tig;
                if (col0 >= SEQ)     { s[jb][0] = -1e30f; s[jb][2] = -1e30f; }
                if (col0 + 1 >= SEQ) { s[jb][1] = -1e30f; s[jb][3] = -1e30f; }
            }
        }

        // ---- online softmax (rows live in quads) ----
        float mx0 = -1e30f, mx1 = -1e30f;
#pragma unroll
        for (int jb = 0; jb < 8; jb++) {
            mx0 = fmaxf(mx0, fmaxf(s[jb][0], s[jb][1]));
            mx1 = fmaxf(mx1, fmaxf(s[jb][2], s[jb][3]));
        }
        mx0 = fmaxf(mx0, __shfl_xor_sync(0xffffffffu, mx0, 1));
        mx0 = fmaxf(mx0, __shfl_xor_sync(0xffffffffu, mx0, 2));
        mx1 = fmaxf(mx1, __shfl_xor_sync(0xffffffffu, mx1, 1));
        mx1 = fmaxf(mx1, __shfl_xor_sync(0xffffffffu, mx1, 2));

        float mn0 = fmaxf(m0, mx0), mn1 = fmaxf(m1, mx1);
        float corr0 = __expf(m0 - mn0), corr1 = __expf(m1 - mn1);
        m0 = mn0; m1 = mn1;

        float sum0 = 0.f, sum1 = 0.f;
#pragma unroll
        for (int jb = 0; jb < 8; jb++) {
            float p0 = __expf(s[jb][0] - mn0);
            float p1 = __expf(s[jb][1] - mn0);
            float p2 = __expf(s[jb][2] - mn1);
            float p3 = __expf(s[jb][3] - mn1);
            sum0 += p0 + p1;
            sum1 += p2 + p3;
            float2 v0 = make_float2(__uint_as_float(f2tf(p0)), __uint_as_float(f2tf(p1)));
            float2 v1 = make_float2(__uint_as_float(f2tf(p2)), __uint_as_float(f2tf(p3)));
            *(float2*)&Pme[quad * PST + jb * 8 + 2 * tig]       = v0;
            *(float2*)&Pme[(quad + 8) * PST + jb * 8 + 2 * tig] = v1;
        }
        sum0 += __shfl_xor_sync(0xffffffffu, sum0, 1);
        sum0 += __shfl_xor_sync(0xffffffffu, sum0, 2);
        sum1 += __shfl_xor_sync(0xffffffffu, sum1, 1);
        sum1 += __shfl_xor_sync(0xffffffffu, sum1, 2);
        l0 = l0 * corr0 + sum0;
        l1 = l1 * corr1 + sum1;

#pragma unroll
        for (int nb = 0; nb < 8; nb++) {
            o[nb][0] *= corr0; o[nb][1] *= corr0;
            o[nb][2] *= corr1; o[nb][3] *= corr1;
        }

        __syncwarp();

        // ---- load P fragments (warp-private smem) ----
        uint32_t pf[8][4];
#pragma unroll
        for (int kc = 0; kc < 8; kc++) {
            pf[kc][0] = __float_as_uint(Pme[quad * PST + 8 * kc + tig]);
            pf[kc][1] = __float_as_uint(Pme[(quad + 8) * PST + 8 * kc + tig]);
            pf[kc][2] = __float_as_uint(Pme[quad * PST + 8 * kc + tig + 4]);
            pf[kc][3] = __float_as_uint(Pme[(quad + 8) * PST + 8 * kc + tig + 4]);
        }

        // ---- O += P @ V ----
#pragma unroll
        for (int nb = 0; nb < 8; nb++) {
#pragma unroll
            for (int kc = 0; kc < 8; kc++) {
                uint32_t b0 = __float_as_uint(Vb[(8 * kc + tig) * VST + 8 * nb + quad]);
                uint32_t b1 = __float_as_uint(Vb[(8 * kc + tig + 4) * VST + 8 * nb + quad]);
                mma_tf32(o[nb][0], o[nb][1], o[nb][2], o[nb][3],
                         pf[kc][0], pf[kc][1], pf[kc][2], pf[kc][3], b0, b1);
            }
        }

        if (it + 1 < NITER) {
            stKV((it + 1) & 1);       // other buffer; current readers unaffected
            __syncthreads();          // stores visible before next tile compute
        }
    }

    // ---- write O / l ----
    float inv0 = 1.0f / l0, inv1 = 1.0f / l1;
    float* ob0 = out + (size_t)(q0 + w * 16 + quad) * H + coff;
    float* ob1 = out + (size_t)(q0 + w * 16 + quad + 8) * H + coff;
#pragma unroll
    for (int nb = 0; nb < 8; nb++) {
        *(float2*)&ob0[nb * 8 + 2 * tig] = make_float2(o[nb][0] * inv0, o[nb][1] * inv0);
        *(float2*)&ob1[nb * 8 + 2 * tig] = make_float2(o[nb][2] * inv1, o[nb][3] * inv1);
    }
}

// ---------------- fused add + LayerNorm ----------------
__global__ __launch_bounds__(256)
void addln_kernel(const float* __restrict__ a, const float* __restrict__ b,
                  const float* __restrict__ w, const float* __restrict__ wb,
                  float* __restrict__ outx)
{
    int s = blockIdx.x;
    int t = threadIdx.x;
    const float4 av = ((const float4*)(a + (size_t)s * H))[t];
    const float4 bv = ((const float4*)(b + (size_t)s * H))[t];
    float v[4] = {av.x + bv.x, av.y + bv.y, av.z + bv.z, av.w + bv.w};

    float s1 = v[0] + v[1] + v[2] + v[3];
    float s2 = v[0]*v[0] + v[1]*v[1] + v[2]*v[2] + v[3]*v[3];
#pragma unroll
    for (int off = 16; off > 0; off >>= 1) {
        s1 += __shfl_xor_sync(0xffffffffu, s1, off);
        s2 += __shfl_xor_sync(0xffffffffu, s2, off);
    }
    __shared__ float r1[8], r2[8];
    int wid = t >> 5, lane = t & 31;
    if (lane == 0) { r1[wid] = s1; r2[wid] = s2; }
    __syncthreads();
    if (t == 0) {
        float a0 = 0.f, b0 = 0.f;
#pragma unroll
        for (int i = 0; i < 8; i++) { a0 += r1[i]; b0 += r2[i]; }
        r1[0] = a0; r2[0] = b0;
    }
    __syncthreads();
    float mean = r1[0] * (1.0f / H);
    float var  = r2[0] * (1.0f / H) - mean * mean;
    float rstd = rsqrtf(var + 1e-5f);

    const float4 wv  = ((const float4*)w)[t];
    const float4 wbv = ((const float4*)wb)[t];
    float4 ov;
    ov.x = (v[0] - mean) * rstd * wv.x + wbv.x;
    ov.y = (v[1] - mean) * rstd * wv.y + wbv.y;
    ov.z = (v[2] - mean) * rstd * wv.z + wbv.z;
    ov.w = (v[3] - mean) * rstd * wv.w + wbv.w;
    ((float4*)(outx + (size_t)s * H))[t] = ov;
}

// ---------------- final projection ----------------
__global__ void final_kernel(const float* __restrict__ x, const float* __restrict__ Wout,
                             const float* __restrict__ bout, float* __restrict__ out)
{
    int o = threadIdx.x;
    if (o >= OUTD) return;
    const float* w = Wout + (size_t)o * H;
    float acc = bout[o];
#pragma unroll 8
    for (int d = 0; d < H; d++) acc = fmaf(x[d], w[d], acc);
    out[o] = acc;
}

// ---------------- launch ----------------
extern "C" void kernel_launch(void* const* d_in, const int* in_sizes, int n_in,
                              void* d_out, int out_size)
{
    (void)in_sizes; (void)n_in; (void)out_size;
    const float* q     = (const float*)d_in[0];
    const float* p     = (const float*)d_in[1];
    const float* qm    = (const float*)d_in[2];
    const float* pm    = (const float*)d_in[3];
    const float* z     = (const float*)d_in[4];
    const float* Wq    = (const float*)d_in[5];
    const float* bq    = (const float*)d_in[6];
    const float* Wp    = (const float*)d_in[7];
    const float* bp    = (const float*)d_in[8];
    const float* Wz    = (const float*)d_in[9];
    const float* bz    = (const float*)d_in[10];
    const float* pos   = (const float*)d_in[11];
    const float* noise = (const float*)d_in[12];
    const float* Wqkv  = (const float*)d_in[13];
    const float* bqkv  = (const float*)d_in[14];
    const float* Wo    = (const float*)d_in[15];
    const float* bo    = (const float*)d_in[16];
    const float* ln1w  = (const float*)d_in[17];
    const float* ln1b  = (const float*)d_in[18];
    const float* W1    = (const float*)d_in[19];
    const float* b1    = (const float*)d_in[20];
    const float* W2    = (const float*)d_in[21];
    const float* b2    = (const float*)d_in[22];
    const float* ln2w  = (const float*)d_in[23];
    const float* ln2b  = (const float*)d_in[24];
    const float* Wout  = (const float*)d_in[25];
    const float* bout  = (const float*)d_in[26];

    float *x, *qkvb, *attnb, *tmp, *ff;
    cudaGetSymbolAddress((void**)&x,     g_x);
    cudaGetSymbolAddress((void**)&qkvb,  g_qkv);
    cudaGetSymbolAddress((void**)&attnb, g_attn);
    cudaGetSymbolAddress((void**)&tmp,   g_tmp);
    cudaGetSymbolAddress((void**)&ff,    g_ff);

    cudaFuncSetAttribute(tgemm<false>, cudaFuncAttributeMaxDynamicSharedMemorySize, GEMM_SMEM);
    cudaFuncSetAttribute(tgemm<true>,  cudaFuncAttributeMaxDynamicSharedMemorySize, GEMM_SMEM);
    cudaFuncSetAttribute(attn_kernel,  cudaFuncAttributeMaxDynamicSharedMemorySize, ATTN_SMEM);

    embed_kernel<<<SEQP, 256>>>(q, p, qm, pm, z, Wq, bq, Wp, bp, Wz, bz, pos, noise, x);

    const int MB = SEQP / 128;   // 33
    for (int i = 0; i < LAYERS; i++) {
        tgemm<false><<<dim3(H3 / 128, MB), 256, GEMM_SMEM>>>(
            x, Wqkv + (size_t)i * H3 * H, bqkv + (size_t)i * H3, qkvb, SEQP, H3, H);
        attn_kernel<<<dim3(SEQP / 128, NH), 256, ATTN_SMEM>>>(qkvb, attnb);
        tgemm<false><<<dim3(H / 128, MB), 256, GEMM_SMEM>>>(
            attnb, Wo + (size_t)i * H * H, bo + (size_t)i * H, tmp, SEQP, H, H);
        addln_kernel<<<SEQP, 256>>>(x, tmp, ln1w + (size_t)i * H, ln1b + (size_t)i * H, x);
        tgemm<true><<<dim3(FFD / 128, MB), 256, GEMM_SMEM>>>(
            x, W1 + (size_t)i * FFD * H, b1 + (size_t)i * FFD, ff, SEQP, FFD, H);
        tgemm<false><<<dim3(H / 128, MB), 256, GEMM_SMEM>>>(
            ff, W2 + (size_t)i * H * FFD, b2 + (size_t)i * H, tmp, SEQP, H, FFD);
        addln_kernel<<<SEQP, 256>>>(x, tmp, ln2w + (size_t)i * H, ln2b + (size_t)i * H, x);
    }

    final_kernel<<<1, 128>>>(x, Wout, bout, (float*)d_out);
}

// round 4
// speedup vs baseline: 2.1349x; 1.1579x over previous
#include <cuda_runtime.h>
#include <cuda_pipeline.h>
#include <mma.h>
#include <math.h>
#include <stdint.h>

using namespace nvcuda;

#define SEQ  4097
#define SEQP 4224          // 33 * 128, padded
#define H    1024
#define NH   16
#define HD   64
#define H3   3072
#define FFD  4096
#define LAYERS 6
#define OUTD 128

// ---------------- scratch (device globals; no allocations) ----------------
__device__ float g_x[SEQP * H];
__device__ float g_qkv[SEQP * H3];
__device__ float g_attn[SEQP * H];
__device__ float g_tmp[SEQP * H];
__device__ float g_ff[SEQP * FFD];

__device__ __forceinline__ uint32_t f2tf(float x) {
    uint32_t r;
    asm("cvt.rna.tf32.f32 %0, %1;" : "=r"(r) : "f"(x));
    return r;
}

__device__ __forceinline__ void mma_tf32(float& d0, float& d1, float& d2, float& d3,
                                         uint32_t a0, uint32_t a1, uint32_t a2, uint32_t a3,
                                         uint32_t b0, uint32_t b1)
{
    asm volatile("mma.sync.aligned.m16n8k8.row.col.f32.tf32.tf32.f32 "
                 "{%0,%1,%2,%3},{%4,%5,%6,%7},{%8,%9},{%0,%1,%2,%3};"
                 : "+f"(d0), "+f"(d1), "+f"(d2), "+f"(d3)
                 : "r"(a0), "r"(a1), "r"(a2), "r"(a3), "r"(b0), "r"(b1));
}

// ---------------- embedding ----------------
__global__ void embed_kernel(
    const float* __restrict__ q, const float* __restrict__ p,
    const float* __restrict__ qm, const float* __restrict__ pm,
    const float* __restrict__ z,
    const float* __restrict__ Wq, const float* __restrict__ bq,
    const float* __restrict__ Wp, const float* __restrict__ bp,
    const float* __restrict__ Wz, const float* __restrict__ bz,
    const float* __restrict__ pos, const float* __restrict__ noise,
    float* __restrict__ x)
{
    int s = blockIdx.x;
    if (s >= SEQ) {
        for (int h = threadIdx.x; h < H; h += blockDim.x)
            x[(size_t)s * H + h] = 0.0f;
        return;
    }
    __shared__ float vin[128];
    const float *W, *b, *src;
    int dim;
    float mask;
    if (s == 0)          { src = z;                   dim = 128; W = Wz; b = bz; mask = 1.0f; }
    else if (s <= 2048)  { src = q + (s - 1) * 64;    dim = 64;  W = Wq; b = bq; mask = qm[s - 1]; }
    else                 { src = p + (s - 2049) * 64; dim = 64;  W = Wp; b = bp; mask = pm[s - 2049]; }

    for (int i = threadIdx.x; i < dim; i += blockDim.x) vin[i] = src[i];
    __syncthreads();

    int idx = (int)(mask * 100.0f);
    const float* ne = noise + (size_t)idx * H;

    for (int h = threadIdx.x; h < H; h += blockDim.x) {
        const float* w = W + (size_t)h * dim;
        float acc = b[h];
#pragma unroll 8
        for (int d = 0; d < dim; d++) acc = fmaf(vin[d], w[d], acc);
        x[(size_t)s * H + h] = acc + pos[(size_t)s * H + h] + ne[h];
    }
}

// ---------------- TF32 tensor-core GEMM ----------------
// C[M,N] = A[M,K] @ W[N,K]^T + bias  (optional ReLU)
// BM=BN=128, BK=32, 256 threads / 8 warps, warp tile 64x32.
// __launch_bounds__(256,2): cap regs at 128 -> 2 blocks/SM.
#define GLDT 36
#define GTILE (128 * GLDT)
#define GEMM_SMEM (4 * GTILE * 4)
#define GLDC 136

template <bool RELU>
__global__ __launch_bounds__(256, 2)
void tgemm(const float* __restrict__ A, const float* __restrict__ W,
           const float* __restrict__ bias, float* __restrict__ C,
           int M, int N, int K)
{
    extern __shared__ float smg[];
    float* AsBuf[2] = { smg,             smg + 2 * GTILE };
    float* BsBuf[2] = { smg + GTILE,     smg + 3 * GTILE };

    int t  = threadIdx.x;
    int w  = t >> 5;
    int bm = blockIdx.y * 128, bn = blockIdx.x * 128;
    int wm = w >> 2, wn = w & 3;

    const float* Ab = A + (size_t)bm * K;
    const float* Wb = W + (size_t)bn * K;

    wmma::fragment<wmma::accumulator, 16, 16, 8, float> c[4][2];
#pragma unroll
    for (int i = 0; i < 4; i++)
#pragma unroll
        for (int j = 0; j < 2; j++) wmma::fill_fragment(c[i][j], 0.0f);

    int kt = K / 32;

    auto stage = [&](int buf, int k0) {
#pragma unroll
        for (int v = 0; v < 4; v++) {
            int linear = t + v * 256;
            int row = linear >> 3;
            int qq  = (linear & 7) << 2;
            __pipeline_memcpy_async(&AsBuf[buf][row * GLDT + qq],
                                    Ab + (size_t)row * K + k0 + qq, 16);
            __pipeline_memcpy_async(&BsBuf[buf][row * GLDT + qq],
                                    Wb + (size_t)row * K + k0 + qq, 16);
        }
        __pipeline_commit();
    };

    stage(0, 0);
    for (int it = 0; it < kt; it++) {
        if (it + 1 < kt) stage((it + 1) & 1, (it + 1) * 32);
        __pipeline_wait_prior((it + 1 < kt) ? 1 : 0);
        __syncthreads();

        const float* Ap = AsBuf[it & 1];
        const float* Bp = BsBuf[it & 1];
#pragma unroll
        for (int kk = 0; kk < 32; kk += 8) {
            wmma::fragment<wmma::matrix_a, 16, 16, 8, wmma::precision::tf32, wmma::row_major> a[4];
            wmma::fragment<wmma::matrix_b, 16, 16, 8, wmma::precision::tf32, wmma::col_major> b[2];
#pragma unroll
            for (int i = 0; i < 4; i++) {
                wmma::load_matrix_sync(a[i], Ap + (wm * 64 + i * 16) * GLDT + kk, GLDT);
#pragma unroll
                for (int e = 0; e < a[i].num_elements; e++)
                    a[i].x[e] = wmma::__float_to_tf32(a[i].x[e]);
            }
#pragma unroll
            for (int j = 0; j < 2; j++) {
                wmma::load_matrix_sync(b[j], Bp + (wn * 32 + j * 16) * GLDT + kk, GLDT);
#pragma unroll
                for (int e = 0; e < b[j].num_elements; e++)
                    b[j].x[e] = wmma::__float_to_tf32(b[j].x[e]);
            }
#pragma unroll
            for (int i = 0; i < 4; i++)
#pragma unroll
                for (int j = 0; j < 2; j++)
                    wmma::mma_sync(c[i][j], a[i], b[j], c[i][j]);
        }
        __syncthreads();
    }

    float* Cs = smg;
#pragma unroll
    for (int i = 0; i < 4; i++)
#pragma unroll
        for (int j = 0; j < 2; j++)
            wmma::store_matrix_sync(Cs + (wm * 64 + i * 16) * GLDC + wn * 32 + j * 16,
                                    c[i][j], GLDC, wmma::mem_row_major);
    __syncthreads();

#pragma unroll
    for (int v = 0; v < 16; v++) {
        int linear = t + v * 256;
        int row = linear >> 5;
        int qq  = (linear & 31) << 2;
        float4 val = *(float4*)&Cs[row * GLDC + qq];
        float4 bb  = *(const float4*)&bias[bn + qq];
        val.x += bb.x; val.y += bb.y; val.z += bb.z; val.w += bb.w;
        if (RELU) {
            val.x = fmaxf(val.x, 0.f); val.y = fmaxf(val.y, 0.f);
            val.z = fmaxf(val.z, 0.f); val.w = fmaxf(val.w, 0.f);
        }
        *(float4*)&C[(size_t)(bm + row) * N + bn + qq] = val;
    }
}

// ---------------- flash attention, register FA2, cp.async staging ----------------
// grid (SEQP/128, NH), 256 threads / 8 warps; warp owns 16 query rows.
// K/V: cp.async double-buffered, consumed as raw f32 by tf32 mma (HW truncation).
// Q and P: explicit cvt.rna. 2 blocks/SM target.
#define KST 68
#define VST 72
#define PST 68
#define KBUF (64 * KST)
#define VBUF (64 * VST)
#define ATTN_SMEM ((2 * KBUF + 2 * VBUF + 8 * 16 * PST) * 4)

__global__ __launch_bounds__(256, 2)
void attn_kernel(const float* __restrict__ qkv, float* __restrict__ out)
{
    extern __shared__ float sma[];
    float* Ksm[2] = { sma, sma + KBUF };
    float* Vsm[2] = { sma + 2 * KBUF, sma + 2 * KBUF + VBUF };
    float* Pall   = sma + 2 * KBUF + 2 * VBUF;

    const int t    = threadIdx.x;
    const int lane = t & 31;
    const int w    = t >> 5;
    const int quad = lane >> 2;
    const int tig  = lane & 3;
    const int head = blockIdx.y;
    const int q0   = blockIdx.x * 128;
    const int coff = head * 64;

    float* Pme = Pall + w * 16 * PST;

    // cp.async staging: 1024 16B-chunks per tile per matrix; 4 per thread each.
    auto stage = [&](int k0, int buf) {
#pragma unroll
        for (int v = 0; v < 4; v++) {
            int linear = t + v * 256;
            int row  = linear >> 4;
            int col4 = (linear & 15) << 2;
            __pipeline_memcpy_async(&Ksm[buf][row * KST + col4],
                                    &qkv[(size_t)(k0 + row) * H3 + H + coff + col4], 16);
            __pipeline_memcpy_async(&Vsm[buf][row * VST + col4],
                                    &qkv[(size_t)(k0 + row) * H3 + 2 * H + coff + col4], 16);
        }
        __pipeline_commit();
    };

    // ---- Q fragments: pre-scaled by 1/8, rna tf32 ----
    uint32_t Qa[8][4];
    {
        const float* qb = qkv + (size_t)(q0 + w * 16) * H3 + coff;
#pragma unroll
        for (int c = 0; c < 8; c++) {
            int col = 8 * c + tig;
            Qa[c][0] = f2tf(qb[(size_t)quad * H3 + col]           * 0.125f);
            Qa[c][1] = f2tf(qb[(size_t)(quad + 8) * H3 + col]     * 0.125f);
            Qa[c][2] = f2tf(qb[(size_t)quad * H3 + col + 4]       * 0.125f);
            Qa[c][3] = f2tf(qb[(size_t)(quad + 8) * H3 + col + 4] * 0.125f);
        }
    }

    float o[8][4];
#pragma unroll
    for (int nb = 0; nb < 8; nb++)
#pragma unroll
        for (int e = 0; e < 4; e++) o[nb][e] = 0.f;
    float m0 = -1e30f, m1 = -1e30f, l0 = 0.f, l1 = 0.f;

    const int NITER = (SEQ + 63) / 64;   // 65

    stage(0, 0);
    for (int it = 0; it < NITER; it++) {
        const int k0 = it * 64;
        if (it + 1 < NITER) stage((it + 1) * 64, (it + 1) & 1);
        __pipeline_wait_prior((it + 1 < NITER) ? 1 : 0);
        __syncthreads();                 // tile it visible

        const float* Kb = Ksm[it & 1];
        const float* Vb = Vsm[it & 1];

        // ---- S = Q @ K^T (K raw f32 -> tf32 truncation) ----
        float s[8][4];
#pragma unroll
        for (int jb = 0; jb < 8; jb++) {
            s[jb][0] = s[jb][1] = s[jb][2] = s[jb][3] = 0.f;
#pragma unroll
            for (int c = 0; c < 8; c++) {
                uint32_t b0 = __float_as_uint(Kb[(8 * jb + quad) * KST + 8 * c + tig]);
                uint32_t b1 = __float_as_uint(Kb[(8 * jb + quad) * KST + 8 * c + tig + 4]);
                mma_tf32(s[jb][0], s[jb][1], s[jb][2], s[jb][3],
                         Qa[c][0], Qa[c][1], Qa[c][2], Qa[c][3], b0, b1);
            }
        }

        if (k0 + 64 > SEQ) {
#pragma unroll
            for (int jb = 0; jb < 8; jb++) {
                int col0 = k0 + jb * 8 + 2 * tig;
                if (col0 >= SEQ)     { s[jb][0] = -1e30f; s[jb][2] = -1e30f; }
                if (col0 + 1 >= SEQ) { s[jb][1] = -1e30f; s[jb][3] = -1e30f; }
            }
        }

        // ---- online softmax ----
        float mx0 = -1e30f, mx1 = -1e30f;
#pragma unroll
        for (int jb = 0; jb < 8; jb++) {
            mx0 = fmaxf(mx0, fmaxf(s[jb][0], s[jb][1]));
            mx1 = fmaxf(mx1, fmaxf(s[jb][2], s[jb][3]));
        }
        mx0 = fmaxf(mx0, __shfl_xor_sync(0xffffffffu, mx0, 1));
        mx0 = fmaxf(mx0, __shfl_xor_sync(0xffffffffu, mx0, 2));
        mx1 = fmaxf(mx1, __shfl_xor_sync(0xffffffffu, mx1, 1));
        mx1 = fmaxf(mx1, __shfl_xor_sync(0xffffffffu, mx1, 2));

        float mn0 = fmaxf(m0, mx0), mn1 = fmaxf(m1, mx1);
        float corr0 = __expf(m0 - mn0), corr1 = __expf(m1 - mn1);
        m0 = mn0; m1 = mn1;

        float sum0 = 0.f, sum1 = 0.f;
#pragma unroll
        for (int jb = 0; jb < 8; jb++) {
            float p0 = __expf(s[jb][0] - mn0);
            float p1 = __expf(s[jb][1] - mn0);
            float p2 = __expf(s[jb][2] - mn1);
            float p3 = __expf(s[jb][3] - mn1);
            sum0 += p0 + p1;
            sum1 += p2 + p3;
            float2 v0 = make_float2(__uint_as_float(f2tf(p0)), __uint_as_float(f2tf(p1)));
            float2 v1 = make_float2(__uint_as_float(f2tf(p2)), __uint_as_float(f2tf(p3)));
            *(float2*)&Pme[quad * PST + jb * 8 + 2 * tig]       = v0;
            *(float2*)&Pme[(quad + 8) * PST + jb * 8 + 2 * tig] = v1;
        }
        sum0 += __shfl_xor_sync(0xffffffffu, sum0, 1);
        sum0 += __shfl_xor_sync(0xffffffffu, sum0, 2);
        sum1 += __shfl_xor_sync(0xffffffffu, sum1, 1);
        sum1 += __shfl_xor_sync(0xffffffffu, sum1, 2);
        l0 = l0 * corr0 + sum0;
        l1 = l1 * corr1 + sum1;

#pragma unroll
        for (int nb = 0; nb < 8; nb++) {
            o[nb][0] *= corr0; o[nb][1] *= corr0;
            o[nb][2] *= corr1; o[nb][3] *= corr1;
        }

        __syncwarp();

        // ---- O += P @ V (V raw f32 -> tf32 truncation) ----
#pragma unroll
        for (int kc = 0; kc < 8; kc++) {
            uint32_t p0 = __float_as_uint(Pme[quad * PST + 8 * kc + tig]);
            uint32_t p1 = __float_as_uint(Pme[(quad + 8) * PST + 8 * kc + tig]);
            uint32_t p2 = __float_as_uint(Pme[quad * PST + 8 * kc + tig + 4]);
            uint32_t p3 = __float_as_uint(Pme[(quad + 8) * PST + 8 * kc + tig + 4]);
#pragma unroll
            for (int nb = 0; nb < 8; nb++) {
                uint32_t b0 = __float_as_uint(Vb[(8 * kc + tig) * VST + 8 * nb + quad]);
                uint32_t b1 = __float_as_uint(Vb[(8 * kc + tig + 4) * VST + 8 * nb + quad]);
                mma_tf32(o[nb][0], o[nb][1], o[nb][2], o[nb][3],
                         p0, p1, p2, p3, b0, b1);
            }
        }

        __syncthreads();   // all reads of buf it&1 done before iter it+1 stages into it
    }

    float inv0 = 1.0f / l0, inv1 = 1.0f / l1;
    float* ob0 = out + (size_t)(q0 + w * 16 + quad) * H + coff;
    float* ob1 = out + (size_t)(q0 + w * 16 + quad + 8) * H + coff;
#pragma unroll
    for (int nb = 0; nb < 8; nb++) {
        *(float2*)&ob0[nb * 8 + 2 * tig] = make_float2(o[nb][0] * inv0, o[nb][1] * inv0);
        *(float2*)&ob1[nb * 8 + 2 * tig] = make_float2(o[nb][2] * inv1, o[nb][3] * inv1);
    }
}

// ---------------- fused add + LayerNorm ----------------
__global__ __launch_bounds__(256)
void addln_kernel(const float* __restrict__ a, const float* __restrict__ b,
                  const float* __restrict__ w, const float* __restrict__ wb,
                  float* __restrict__ outx)
{
    int s = blockIdx.x;
    int t = threadIdx.x;
    const float4 av = ((const float4*)(a + (size_t)s * H))[t];
    const float4 bv = ((const float4*)(b + (size_t)s * H))[t];
    float v[4] = {av.x + bv.x, av.y + bv.y, av.z + bv.z, av.w + bv.w};

    float s1 = v[0] + v[1] + v[2] + v[3];
    float s2 = v[0]*v[0] + v[1]*v[1] + v[2]*v[2] + v[3]*v[3];
#pragma unroll
    for (int off = 16; off > 0; off >>= 1) {
        s1 += __shfl_xor_sync(0xffffffffu, s1, off);
        s2 += __shfl_xor_sync(0xffffffffu, s2, off);
    }
    __shared__ float r1[8], r2[8];
    int wid = t >> 5, lane = t & 31;
    if (lane == 0) { r1[wid] = s1; r2[wid] = s2; }
    __syncthreads();
    if (t == 0) {
        float a0 = 0.f, b0 = 0.f;
#pragma unroll
        for (int i = 0; i < 8; i++) { a0 += r1[i]; b0 += r2[i]; }
        r1[0] = a0; r2[0] = b0;
    }
    __syncthreads();
    float mean = r1[0] * (1.0f / H);
    float var  = r2[0] * (1.0f / H) - mean * mean;
    float rstd = rsqrtf(var + 1e-5f);

    const float4 wv  = ((const float4*)w)[t];
    const float4 wbv = ((const float4*)wb)[t];
    float4 ov;
    ov.x = (v[0] - mean) * rstd * wv.x + wbv.x;
    ov.y = (v[1] - mean) * rstd * wv.y + wbv.y;
    ov.z = (v[2] - mean) * rstd * wv.z + wbv.z;
    ov.w = (v[3] - mean) * rstd * wv.w + wbv.w;
    ((float4*)(outx + (size_t)s * H))[t] = ov;
}

// ---------------- final projection ----------------
__global__ void final_kernel(const float* __restrict__ x, const float* __restrict__ Wout,
                             const float* __restrict__ bout, float* __restrict__ out)
{
    int o = threadIdx.x;
    if (o >= OUTD) return;
    const float* w = Wout + (size_t)o * H;
    float acc = bout[o];
#pragma unroll 8
    for (int d = 0; d < H; d++) acc = fmaf(x[d], w[d], acc);
    out[o] = acc;
}

// ---------------- launch ----------------
extern "C" void kernel_launch(void* const* d_in, const int* in_sizes, int n_in,
                              void* d_out, int out_size)
{
    (void)in_sizes; (void)n_in; (void)out_size;
    const float* q     = (const float*)d_in[0];
    const float* p     = (const float*)d_in[1];
    const float* qm    = (const float*)d_in[2];
    const float* pm    = (const float*)d_in[3];
    const float* z     = (const float*)d_in[4];
    const float* Wq    = (const float*)d_in[5];
    const float* bq    = (const float*)d_in[6];
    const float* Wp    = (const float*)d_in[7];
    const float* bp    = (const float*)d_in[8];
    const float* Wz    = (const float*)d_in[9];
    const float* bz    = (const float*)d_in[10];
    const float* pos   = (const float*)d_in[11];
    const float* noise = (const float*)d_in[12];
    const float* Wqkv  = (const float*)d_in[13];
    const float* bqkv  = (const float*)d_in[14];
    const float* Wo    = (const float*)d_in[15];
    const float* bo    = (const float*)d_in[16];
    const float* ln1w  = (const float*)d_in[17];
    const float* ln1b  = (const float*)d_in[18];
    const float* W1    = (const float*)d_in[19];
    const float* b1    = (const float*)d_in[20];
    const float* W2    = (const float*)d_in[21];
    const float* b2    = (const float*)d_in[22];
    const float* ln2w  = (const float*)d_in[23];
    const float* ln2b  = (const float*)d_in[24];
    const float* Wout  = (const float*)d_in[25];
    const float* bout  = (const float*)d_in[26];

    float *x, *qkvb, *attnb, *tmp, *ff;
    cudaGetSymbolAddress((void**)&x,     g_x);
    cudaGetSymbolAddress((void**)&qkvb,  g_qkv);
    cudaGetSymbolAddress((void**)&attnb, g_attn);
    cudaGetSymbolAddress((void**)&tmp,   g_tmp);
    cudaGetSymbolAddress((void**)&ff,    g_ff);

    cudaFuncSetAttribute(tgemm<false>, cudaFuncAttributeMaxDynamicSharedMemorySize, GEMM_SMEM);
    cudaFuncSetAttribute(tgemm<true>,  cudaFuncAttributeMaxDynamicSharedMemorySize, GEMM_SMEM);
    cudaFuncSetAttribute(attn_kernel,  cudaFuncAttributeMaxDynamicSharedMemorySize, ATTN_SMEM);

    embed_kernel<<<SEQP, 256>>>(q, p, qm, pm, z, Wq, bq, Wp, bp, Wz, bz, pos, noise, x);

    const int MB = SEQP / 128;   // 33
    for (int i = 0; i < LAYERS; i++) {
        tgemm<false><<<dim3(H3 / 128, MB), 256, GEMM_SMEM>>>(
            x, Wqkv + (size_t)i * H3 * H, bqkv + (size_t)i * H3, qkvb, SEQP, H3, H);
        attn_kernel<<<dim3(SEQP / 128, NH), 256, ATTN_SMEM>>>(qkvb, attnb);
        tgemm<false><<<dim3(H / 128, MB), 256, GEMM_SMEM>>>(
            attnb, Wo + (size_t)i * H * H, bo + (size_t)i * H, tmp, SEQP, H, H);
        addln_kernel<<<SEQP, 256>>>(x, tmp, ln1w + (size_t)i * H, ln1b + (size_t)i * H, x);
        tgemm<true><<<dim3(FFD / 128, MB), 256, GEMM_SMEM>>>(
            x, W1 + (size_t)i * FFD * H, b1 + (size_t)i * FFD, ff, SEQP, FFD, H);
        tgemm<false><<<dim3(H / 128, MB), 256, GEMM_SMEM>>>(
            ff, W2 + (size_t)i * H * FFD, b2 + (size_t)i * H, tmp, SEQP, H, FFD);
        addln_kernel<<<SEQP, 256>>>(x, tmp, ln2w + (size_t)i * H, ln2b + (size_t)i * H, x);
    }

    final_kernel<<<1, 128>>>(x, Wout, bout, (float*)d_out);
}

// round 5
// speedup vs baseline: 3.5186x; 1.6481x over previous
#include <cuda_runtime.h>
#include <cuda_pipeline.h>
#include <math.h>
#include <stdint.h>

#define SEQ  4097
#define SEQP 4224          // 33 * 128, padded
#define H    1024
#define NH   16
#define HD   64
#define H3   3072
#define FFD  4096
#define LAYERS 6
#define OUTD 128

#define WQKV_N (LAYERS * H3 * H)
#define WO_N   (LAYERS * H * H)
#define W1_N   (LAYERS * FFD * H)
#define W2_N   (LAYERS * H * FFD)

// ---------------- scratch (device globals; no allocations) ----------------
__device__ float g_x[SEQP * H];
__device__ float g_xr[SEQP * H];        // tf32-rounded copy of x (GEMM input)
__device__ float g_qkv[SEQP * H3];
__device__ float g_attn[SEQP * H];
__device__ float g_tmp[SEQP * H];
__device__ float g_ff[SEQP * FFD];
__device__ float g_wqkv_r[WQKV_N];
__device__ float g_wo_r[WO_N];
__device__ float g_w1_r[W1_N];
__device__ float g_w2_r[W2_N];

__device__ __forceinline__ uint32_t f2tf(float x) {
    uint32_t r;
    asm("cvt.rna.tf32.f32 %0, %1;" : "=r"(r) : "f"(x));
    return r;
}
__device__ __forceinline__ float f2tff(float x) { return __uint_as_float(f2tf(x)); }

__device__ __forceinline__ void mma_tf32(float& d0, float& d1, float& d2, float& d3,
                                         uint32_t a0, uint32_t a1, uint32_t a2, uint32_t a3,
                                         uint32_t b0, uint32_t b1)
{
    asm volatile("mma.sync.aligned.m16n8k8.row.col.f32.tf32.tf32.f32 "
                 "{%0,%1,%2,%3},{%4,%5,%6,%7},{%8,%9},{%0,%1,%2,%3};"
                 : "+f"(d0), "+f"(d1), "+f"(d2), "+f"(d3)
                 : "r"(a0), "r"(a1), "r"(a2), "r"(a3), "r"(b0), "r"(b1));
}

__device__ __forceinline__ void ldsm4(uint32_t& r0, uint32_t& r1, uint32_t& r2, uint32_t& r3,
                                      uint32_t addr)
{
    asm volatile("ldmatrix.sync.aligned.m8n8.x4.shared.b16 {%0,%1,%2,%3}, [%4];"
                 : "=r"(r0), "=r"(r1), "=r"(r2), "=r"(r3) : "r"(addr));
}

// ---------------- tf32 rounding kernel (weights, once per launch) ----------------
__global__ void round_tf32_kernel(const float* __restrict__ in, float* __restrict__ out, int n4)
{
    for (int i = blockIdx.x * blockDim.x + threadIdx.x; i < n4; i += gridDim.x * blockDim.x) {
        float4 v = ((const float4*)in)[i];
        v.x = f2tff(v.x); v.y = f2tff(v.y); v.z = f2tff(v.z); v.w = f2tff(v.w);
        ((float4*)out)[i] = v;
    }
}

// ---------------- embedding (writes x and rounded xr) ----------------
__global__ void embed_kernel(
    const float* __restrict__ q, const float* __restrict__ p,
    const float* __restrict__ qm, const float* __restrict__ pm,
    const float* __restrict__ z,
    const float* __restrict__ Wq, const float* __restrict__ bq,
    const float* __restrict__ Wp, const float* __restrict__ bp,
    const float* __restrict__ Wz, const float* __restrict__ bz,
    const float* __restrict__ pos, const float* __restrict__ noise,
    float* __restrict__ x, float* __restrict__ xr)
{
    int s = blockIdx.x;
    if (s >= SEQ) {
        for (int h = threadIdx.x; h < H; h += blockDim.x) {
            x[(size_t)s * H + h] = 0.0f;
            xr[(size_t)s * H + h] = 0.0f;
        }
        return;
    }
    __shared__ float vin[128];
    const float *W, *b, *src;
    int dim;
    float mask;
    if (s == 0)          { src = z;                   dim = 128; W = Wz; b = bz; mask = 1.0f; }
    else if (s <= 2048)  { src = q + (s - 1) * 64;    dim = 64;  W = Wq; b = bq; mask = qm[s - 1]; }
    else                 { src = p + (s - 2049) * 64; dim = 64;  W = Wp; b = bp; mask = pm[s - 2049]; }

    for (int i = threadIdx.x; i < dim; i += blockDim.x) vin[i] = src[i];
    __syncthreads();

    int idx = (int)(mask * 100.0f);
    const float* ne = noise + (size_t)idx * H;

    for (int h = threadIdx.x; h < H; h += blockDim.x) {
        const float* w = W + (size_t)h * dim;
        float acc = b[h];
#pragma unroll 8
        for (int d = 0; d < dim; d++) acc = fmaf(vin[d], w[d], acc);
        float v = acc + pos[(size_t)s * H + h] + ne[h];
        x[(size_t)s * H + h] = v;
        xr[(size_t)s * H + h] = f2tff(v);
    }
}

// ---------------- TF32 GEMM: raw mma + ldmatrix, pre-rounded inputs ----------------
// C[M,N] = A[M,K] @ W[N,K]^T + bias (opt ReLU, opt tf32-round of output)
// BM=BN=128, BK=32, 256 threads / 8 warps, warp tile 64x32 (4x4 m16n8k8).
#define GLDT 36
#define GTILE (128 * GLDT)
#define GEMM_SMEM (4 * GTILE * 4)   // 73728 B

template <bool RELU, bool ROUND>
__global__ __launch_bounds__(256, 2)
void tgemm(const float* __restrict__ A, const float* __restrict__ W,
           const float* __restrict__ bias, float* __restrict__ C,
           int M, int N, int K)
{
    extern __shared__ float smg[];
    float* AsBuf[2] = { smg,         smg + 2 * GTILE };
    float* BsBuf[2] = { smg + GTILE, smg + 3 * GTILE };

    const int t    = threadIdx.x;
    const int lane = t & 31;
    const int w    = t >> 5;
    const int bm = blockIdx.y * 128, bn = blockIdx.x * 128;
    const int wm = w >> 2, wn = w & 3;
    const int quad = lane >> 2, tig = lane & 3;

    // ldmatrix lane->address mappings
    const int a_row = (lane & 7) + ((lane >> 3) & 1) * 8;   // 0..15
    const int a_col = ((lane >> 4) & 1) * 4;                // 0 or 4
    const int b_row = (lane & 7) + ((lane & 16) >> 1);      // 0..15
    const int b_col = ((lane >> 3) & 1) * 4;                // 0 or 4

    const float* Ab = A + (size_t)bm * K;
    const float* Wb = W + (size_t)bn * K;

    float c[4][4][4];
#pragma unroll
    for (int mi = 0; mi < 4; mi++)
#pragma unroll
        for (int ni = 0; ni < 4; ni++)
#pragma unroll
            for (int e = 0; e < 4; e++) c[mi][ni][e] = 0.f;

    const int kt = K / 32;

    auto stage = [&](int buf, int k0) {
#pragma unroll
        for (int v = 0; v < 4; v++) {
            int linear = t + v * 256;
            int row = linear >> 3;
            int qq  = (linear & 7) << 2;
            __pipeline_memcpy_async(&AsBuf[buf][row * GLDT + qq],
                                    Ab + (size_t)row * K + k0 + qq, 16);
            __pipeline_memcpy_async(&BsBuf[buf][row * GLDT + qq],
                                    Wb + (size_t)row * K + k0 + qq, 16);
        }
        __pipeline_commit();
    };

    stage(0, 0);
    for (int it = 0; it < kt; it++) {
        if (it + 1 < kt) stage((it + 1) & 1, (it + 1) * 32);
        __pipeline_wait_prior((it + 1 < kt) ? 1 : 0);
        __syncthreads();

        const float* Ap = AsBuf[it & 1];
        const float* Bp = BsBuf[it & 1];
        uint32_t aBase = (uint32_t)__cvta_generic_to_shared(
            Ap + (wm * 64 + a_row) * GLDT + a_col);
        uint32_t bBase = (uint32_t)__cvta_generic_to_shared(
            Bp + (wn * 32 + b_row) * GLDT + b_col);

#pragma unroll
        for (int kk = 0; kk < 32; kk += 8) {
            uint32_t a[4][4];
#pragma unroll
            for (int mi = 0; mi < 4; mi++)
                ldsm4(a[mi][0], a[mi][1], a[mi][2], a[mi][3],
                      aBase + (uint32_t)((mi * 16 * GLDT + kk) * 4));
            uint32_t bf[8];
            ldsm4(bf[0], bf[1], bf[2], bf[3], bBase + (uint32_t)(kk * 4));
            ldsm4(bf[4], bf[5], bf[6], bf[7], bBase + (uint32_t)((16 * GLDT + kk) * 4));
#pragma unroll
            for (int mi = 0; mi < 4; mi++)
#pragma unroll
                for (int ni = 0; ni < 4; ni++)
                    mma_tf32(c[mi][ni][0], c[mi][ni][1], c[mi][ni][2], c[mi][ni][3],
                             a[mi][0], a[mi][1], a[mi][2], a[mi][3],
                             bf[2 * ni], bf[2 * ni + 1]);
        }
        __syncthreads();
    }

    // direct global epilogue from c-frags
#pragma unroll
    for (int mi = 0; mi < 4; mi++) {
        int row0 = bm + wm * 64 + mi * 16 + quad;
#pragma unroll
        for (int ni = 0; ni < 4; ni++) {
            int col = bn + wn * 32 + ni * 8 + tig * 2;
            float2 bb = *(const float2*)&bias[col];
            float2 v0 = make_float2(c[mi][ni][0] + bb.x, c[mi][ni][1] + bb.y);
            float2 v1 = make_float2(c[mi][ni][2] + bb.x, c[mi][ni][3] + bb.y);
            if (RELU) {
                v0.x = fmaxf(v0.x, 0.f); v0.y = fmaxf(v0.y, 0.f);
                v1.x = fmaxf(v1.x, 0.f); v1.y = fmaxf(v1.y, 0.f);
            }
            if (ROUND) {
                v0.x = f2tff(v0.x); v0.y = f2tff(v0.y);
                v1.x = f2tff(v1.x); v1.y = f2tff(v1.y);
            }
            *(float2*)&C[(size_t)row0 * N + col]       = v0;
            *(float2*)&C[(size_t)(row0 + 8) * N + col] = v1;
        }
    }
}

// ---------------- flash attention (unchanged core; rounded output) ----------------
#define KST 68
#define VST 72
#define PST 68
#define KBUF (64 * KST)
#define VBUF (64 * VST)
#define ATTN_SMEM ((2 * KBUF + 2 * VBUF + 8 * 16 * PST) * 4)

__global__ __launch_bounds__(256, 2)
void attn_kernel(const float* __restrict__ qkv, float* __restrict__ out)
{
    extern __shared__ float sma[];
    float* Ksm[2] = { sma, sma + KBUF };
    float* Vsm[2] = { sma + 2 * KBUF, sma + 2 * KBUF + VBUF };
    float* Pall   = sma + 2 * KBUF + 2 * VBUF;

    const int t    = threadIdx.x;
    const int lane = t & 31;
    const int w    = t >> 5;
    const int quad = lane >> 2;
    const int tig  = lane & 3;
    const int head = blockIdx.y;
    const int q0   = blockIdx.x * 128;
    const int coff = head * 64;

    float* Pme = Pall + w * 16 * PST;

    auto stage = [&](int k0, int buf) {
#pragma unroll
        for (int v = 0; v < 4; v++) {
            int linear = t + v * 256;
            int row  = linear >> 4;
            int col4 = (linear & 15) << 2;
            __pipeline_memcpy_async(&Ksm[buf][row * KST + col4],
                                    &qkv[(size_t)(k0 + row) * H3 + H + coff + col4], 16);
            __pipeline_memcpy_async(&Vsm[buf][row * VST + col4],
                                    &qkv[(size_t)(k0 + row) * H3 + 2 * H + coff + col4], 16);
        }
        __pipeline_commit();
    };

    uint32_t Qa[8][4];
    {
        const float* qb = qkv + (size_t)(q0 + w * 16) * H3 + coff;
#pragma unroll
        for (int c = 0; c < 8; c++) {
            int col = 8 * c + tig;
            Qa[c][0] = f2tf(qb[(size_t)quad * H3 + col]           * 0.125f);
            Qa[c][1] = f2tf(qb[(size_t)(quad + 8) * H3 + col]     * 0.125f);
            Qa[c][2] = f2tf(qb[(size_t)quad * H3 + col + 4]       * 0.125f);
            Qa[c][3] = f2tf(qb[(size_t)(quad + 8) * H3 + col + 4] * 0.125f);
        }
    }

    float o[8][4];
#pragma unroll
    for (int nb = 0; nb < 8; nb++)
#pragma unroll
        for (int e = 0; e < 4; e++) o[nb][e] = 0.f;
    float m0 = -1e30f, m1 = -1e30f, l0 = 0.f, l1 = 0.f;

    const int NITER = (SEQ + 63) / 64;   // 65

    stage(0, 0);
    for (int it = 0; it < NITER; it++) {
        const int k0 = it * 64;
        if (it + 1 < NITER) stage((it + 1) * 64, (it + 1) & 1);
        __pipeline_wait_prior((it + 1 < NITER) ? 1 : 0);
        __syncthreads();

        const float* Kb = Ksm[it & 1];
        const float* Vb = Vsm[it & 1];

        float s[8][4];
#pragma unroll
        for (int jb = 0; jb < 8; jb++) {
            s[jb][0] = s[jb][1] = s[jb][2] = s[jb][3] = 0.f;
#pragma unroll
            for (int c = 0; c < 8; c++) {
                uint32_t b0 = __float_as_uint(Kb[(8 * jb + quad) * KST + 8 * c + tig]);
                uint32_t b1 = __float_as_uint(Kb[(8 * jb + quad) * KST + 8 * c + tig + 4]);
                mma_tf32(s[jb][0], s[jb][1], s[jb][2], s[jb][3],
                         Qa[c][0], Qa[c][1], Qa[c][2], Qa[c][3], b0, b1);
            }
        }

        if (k0 + 64 > SEQ) {
#pragma unroll
            for (int jb = 0; jb < 8; jb++) {
                int col0 = k0 + jb * 8 + 2 * tig;
                if (col0 >= SEQ)     { s[jb][0] = -1e30f; s[jb][2] = -1e30f; }
                if (col0 + 1 >= SEQ) { s[jb][1] = -1e30f; s[jb][3] = -1e30f; }
            }
        }

        float mx0 = -1e30f, mx1 = -1e30f;
#pragma unroll
        for (int jb = 0; jb < 8; jb++) {
            mx0 = fmaxf(mx0, fmaxf(s[jb][0], s[jb][1]));
            mx1 = fmaxf(mx1, fmaxf(s[jb][2], s[jb][3]));
        }
        mx0 = fmaxf(mx0, __shfl_xor_sync(0xffffffffu, mx0, 1));
        mx0 = fmaxf(mx0, __shfl_xor_sync(0xffffffffu, mx0, 2));
        mx1 = fmaxf(mx1, __shfl_xor_sync(0xffffffffu, mx1, 1));
        mx1 = fmaxf(mx1, __shfl_xor_sync(0xffffffffu, mx1, 2));

        float mn0 = fmaxf(m0, mx0), mn1 = fmaxf(m1, mx1);
        float corr0 = __expf(m0 - mn0), corr1 = __expf(m1 - mn1);
        m0 = mn0; m1 = mn1;

        float sum0 = 0.f, sum1 = 0.f;
#pragma unroll
        for (int jb = 0; jb < 8; jb++) {
            float p0 = __expf(s[jb][0] - mn0);
            float p1 = __expf(s[jb][1] - mn0);
            float p2 = __expf(s[jb][2] - mn1);
            float p3 = __expf(s[jb][3] - mn1);
            sum0 += p0 + p1;
            sum1 += p2 + p3;
            float2 v0 = make_float2(f2tff(p0), f2tff(p1));
            float2 v1 = make_float2(f2tff(p2), f2tff(p3));
            *(float2*)&Pme[quad * PST + jb * 8 + 2 * tig]       = v0;
            *(float2*)&Pme[(quad + 8) * PST + jb * 8 + 2 * tig] = v1;
        }
        sum0 += __shfl_xor_sync(0xffffffffu, sum0, 1);
        sum0 += __shfl_xor_sync(0xffffffffu, sum0, 2);
        sum1 += __shfl_xor_sync(0xffffffffu, sum1, 1);
        sum1 += __shfl_xor_sync(0xffffffffu, sum1, 2);
        l0 = l0 * corr0 + sum0;
        l1 = l1 * corr1 + sum1;

#pragma unroll
        for (int nb = 0; nb < 8; nb++) {
            o[nb][0] *= corr0; o[nb][1] *= corr0;
            o[nb][2] *= corr1; o[nb][3] *= corr1;
        }

        __syncwarp();

#pragma unroll
        for (int kc = 0; kc < 8; kc++) {
            uint32_t p0 = __float_as_uint(Pme[quad * PST + 8 * kc + tig]);
            uint32_t p1 = __float_as_uint(Pme[(quad + 8) * PST + 8 * kc + tig]);
            uint32_t p2 = __float_as_uint(Pme[quad * PST + 8 * kc + tig + 4]);
            uint32_t p3 = __float_as_uint(Pme[(quad + 8) * PST + 8 * kc + tig + 4]);
#pragma unroll
            for (int nb = 0; nb < 8; nb++) {
                uint32_t b0 = __float_as_uint(Vb[(8 * kc + tig) * VST + 8 * nb + quad]);
                uint32_t b1 = __float_as_uint(Vb[(8 * kc + tig + 4) * VST + 8 * nb + quad]);
                mma_tf32(o[nb][0], o[nb][1], o[nb][2], o[nb][3],
                         p0, p1, p2, p3, b0, b1);
            }
        }

        __syncthreads();
    }

    float inv0 = 1.0f / l0, inv1 = 1.0f / l1;
    float* ob0 = out + (size_t)(q0 + w * 16 + quad) * H + coff;
    float* ob1 = out + (size_t)(q0 + w * 16 + quad + 8) * H + coff;
#pragma unroll
    for (int nb = 0; nb < 8; nb++) {
        *(float2*)&ob0[nb * 8 + 2 * tig] =
            make_float2(f2tff(o[nb][0] * inv0), f2tff(o[nb][1] * inv0));
        *(float2*)&ob1[nb * 8 + 2 * tig] =
            make_float2(f2tff(o[nb][2] * inv1), f2tff(o[nb][3] * inv1));
    }
}

// ---------------- fused add + LayerNorm (writes x and rounded xr) ----------------
__global__ __launch_bounds__(256)
void addln_kernel(const float* __restrict__ a, const float* __restrict__ b,
                  const float* __restrict__ w, const float* __restrict__ wb,
                  float* __restrict__ outx, float* __restrict__ outxr)
{
    int s = blockIdx.x;
    int t = threadIdx.x;
    const float4 av = ((const float4*)(a + (size_t)s * H))[t];
    const float4 bv = ((const float4*)(b + (size_t)s * H))[t];
    float v[4] = {av.x + bv.x, av.y + bv.y, av.z + bv.z, av.w + bv.w};

    float s1 = v[0] + v[1] + v[2] + v[3];
    float s2 = v[0]*v[0] + v[1]*v[1] + v[2]*v[2] + v[3]*v[3];
#pragma unroll
    for (int off = 16; off > 0; off >>= 1) {
        s1 += __shfl_xor_sync(0xffffffffu, s1, off);
        s2 += __shfl_xor_sync(0xffffffffu, s2, off);
    }
    __shared__ float r1[8], r2[8];
    int wid = t >> 5, lane = t & 31;
    if (lane == 0) { r1[wid] = s1; r2[wid] = s2; }
    __syncthreads();
    if (t == 0) {
        float a0 = 0.f, b0 = 0.f;
#pragma unroll
        for (int i = 0; i < 8; i++) { a0 += r1[i]; b0 += r2[i]; }
        r1[0] = a0; r2[0] = b0;
    }
    __syncthreads();
    float mean = r1[0] * (1.0f / H);
    float var  = r2[0] * (1.0f / H) - mean * mean;
    float rstd = rsqrtf(var + 1e-5f);

    const float4 wv  = ((const float4*)w)[t];
    const float4 wbv = ((const float4*)wb)[t];
    float4 ov;
    ov.x = (v[0] - mean) * rstd * wv.x + wbv.x;
    ov.y = (v[1] - mean) * rstd * wv.y + wbv.y;
    ov.z = (v[2] - mean) * rstd * wv.z + wbv.z;
    ov.w = (v[3] - mean) * rstd * wv.w + wbv.w;
    ((float4*)(outx + (size_t)s * H))[t] = ov;

    float4 rv;
    rv.x = f2tff(ov.x); rv.y = f2tff(ov.y); rv.z = f2tff(ov.z); rv.w = f2tff(ov.w);
    ((float4*)(outxr + (size_t)s * H))[t] = rv;
}

// ---------------- final projection ----------------
__global__ void final_kernel(const float* __restrict__ x, const float* __restrict__ Wout,
                             const float* __restrict__ bout, float* __restrict__ out)
{
    int o = threadIdx.x;
    if (o >= OUTD) return;
    const float* w = Wout + (size_t)o * H;
    float acc = bout[o];
#pragma unroll 8
    for (int d = 0; d < H; d++) acc = fmaf(x[d], w[d], acc);
    out[o] = acc;
}

// ---------------- launch ----------------
extern "C" void kernel_launch(void* const* d_in, const int* in_sizes, int n_in,
                              void* d_out, int out_size)
{
    (void)in_sizes; (void)n_in; (void)out_size;
    const float* q     = (const float*)d_in[0];
    const float* p     = (const float*)d_in[1];
    const float* qm    = (const float*)d_in[2];
    const float* pm    = (const float*)d_in[3];
    const float* z     = (const float*)d_in[4];
    const float* Wq    = (const float*)d_in[5];
    const float* bq    = (const float*)d_in[6];
    const float* Wp    = (const float*)d_in[7];
    const float* bp    = (const float*)d_in[8];
    const float* Wz    = (const float*)d_in[9];
    const float* bz    = (const float*)d_in[10];
    const float* pos   = (const float*)d_in[11];
    const float* noise = (const float*)d_in[12];
    const float* Wqkv  = (const float*)d_in[13];
    const float* bqkv  = (const float*)d_in[14];
    const float* Wo    = (const float*)d_in[15];
    const float* bo    = (const float*)d_in[16];
    const float* ln1w  = (const float*)d_in[17];
    const float* ln1b  = (const float*)d_in[18];
    const float* W1    = (const float*)d_in[19];
    const float* b1    = (const float*)d_in[20];
    const float* W2    = (const float*)d_in[21];
    const float* b2    = (const float*)d_in[22];
    const float* ln2w  = (const float*)d_in[23];
    const float* ln2b  = (const float*)d_in[24];
    const float* Wout  = (const float*)d_in[25];
    const float* bout  = (const float*)d_in[26];

    float *x, *xr, *qkvb, *attnb, *tmp, *ff;
    float *wqkv_r, *wo_r, *w1_r, *w2_r;
    cudaGetSymbolAddress((void**)&x,      g_x);
    cudaGetSymbolAddress((void**)&xr,     g_xr);
    cudaGetSymbolAddress((void**)&qkvb,   g_qkv);
    cudaGetSymbolAddress((void**)&attnb,  g_attn);
    cudaGetSymbolAddress((void**)&tmp,    g_tmp);
    cudaGetSymbolAddress((void**)&ff,     g_ff);
    cudaGetSymbolAddress((void**)&wqkv_r, g_wqkv_r);
    cudaGetSymbolAddress((void**)&wo_r,   g_wo_r);
    cudaGetSymbolAddress((void**)&w1_r,   g_w1_r);
    cudaGetSymbolAddress((void**)&w2_r,   g_w2_r);

    cudaFuncSetAttribute((const void*)tgemm<false,false>, cudaFuncAttributeMaxDynamicSharedMemorySize, GEMM_SMEM);
    cudaFuncSetAttribute((const void*)tgemm<false,true>,  cudaFuncAttributeMaxDynamicSharedMemorySize, GEMM_SMEM);
    cudaFuncSetAttribute((const void*)tgemm<true,true>,   cudaFuncAttributeMaxDynamicSharedMemorySize, GEMM_SMEM);
    cudaFuncSetAttribute((const void*)attn_kernel,        cudaFuncAttributeMaxDynamicSharedMemorySize, ATTN_SMEM);

    // round weights to tf32 (once per launch; deterministic)
    round_tf32_kernel<<<2048, 256>>>(Wqkv, wqkv_r, WQKV_N / 4);
    round_tf32_kernel<<<2048, 256>>>(Wo,   wo_r,   WO_N / 4);
    round_tf32_kernel<<<2048, 256>>>(W1,   w1_r,   W1_N / 4);
    round_tf32_kernel<<<2048, 256>>>(W2,   w2_r,   W2_N / 4);

    embed_kernel<<<SEQP, 256>>>(q, p, qm, pm, z, Wq, bq, Wp, bp, Wz, bz, pos, noise, x, xr);

    const int MB = SEQP / 128;   // 33
    for (int i = 0; i < LAYERS; i++) {
        tgemm<false,true><<<dim3(H3 / 128, MB), 256, GEMM_SMEM>>>(
            xr, wqkv_r + (size_t)i * H3 * H, bqkv + (size_t)i * H3, qkvb, SEQP, H3, H);
        attn_kernel<<<dim3(SEQP / 128, NH), 256, ATTN_SMEM>>>(qkvb, attnb);
        tgemm<false,false><<<dim3(H / 128, MB), 256, GEMM_SMEM>>>(
            attnb, wo_r + (size_t)i * H * H, bo + (size_t)i * H, tmp, SEQP, H, H);
        addln_kernel<<<SEQP, 256>>>(x, tmp, ln1w + (size_t)i * H, ln1b + (size_t)i * H, x, xr);
        tgemm<true,true><<<dim3(FFD / 128, MB), 256, GEMM_SMEM>>>(
            xr, w1_r + (size_t)i * FFD * H, b1 + (size_t)i * FFD, ff, SEQP, FFD, H);
        tgemm<false,false><<<dim3(H / 128, MB), 256, GEMM_SMEM>>>(
            ff, w2_r + (size_t)i * H * FFD, b2 + (size_t)i * H, tmp, SEQP, H, FFD);
        addln_kernel<<<SEQP, 256>>>(x, tmp, ln2w + (size_t)i * H, ln2b + (size_t)i * H, x, xr);
    }

    final_kernel<<<1, 128>>>(x, Wout, bout, (float*)d_out);
}

// round 6
// speedup vs baseline: 5.5664x; 1.5820x over previous
#include <cuda_runtime.h>
#include <cuda_pipeline.h>
#include <cuda_fp16.h>
#include <math.h>
#include <stdint.h>

#define SEQ  4097
#define SEQP 4224          // 33 * 128, padded
#define H    1024
#define NH   16
#define HD   64
#define H3   3072
#define FFD  4096
#define LAYERS 6
#define OUTD 128

#define WQKV_N (LAYERS * H3 * H)
#define WO_N   (LAYERS * H * H)
#define W1_N   (LAYERS * FFD * H)
#define W2_N   (LAYERS * H * FFD)

// ---------------- scratch (device globals; no allocations) ----------------
__device__ float  g_x[SEQP * H];
__device__ __half g_xh[SEQP * H];        // fp16 copy of x (GEMM input)
__device__ __half g_qkv[SEQP * H3];      // QKV gemm output (attn input)
__device__ __half g_attn[SEQP * H];      // attn output (Wo gemm input)
__device__ float  g_tmp[SEQP * H];       // Wo/W2 outputs (fp32 residual branch)
__device__ __half g_ff[SEQP * FFD];      // W1 output (W2 input)
__device__ __half g_wqkv_h[WQKV_N];
__device__ __half g_wo_h[WO_N];
__device__ __half g_w1_h[W1_N];
__device__ __half g_w2_h[W2_N];

__device__ __forceinline__ void mma_f16(float& d0, float& d1, float& d2, float& d3,
                                        uint32_t a0, uint32_t a1, uint32_t a2, uint32_t a3,
                                        uint32_t b0, uint32_t b1)
{
    asm volatile("mma.sync.aligned.m16n8k16.row.col.f32.f16.f16.f32 "
                 "{%0,%1,%2,%3},{%4,%5,%6,%7},{%8,%9},{%0,%1,%2,%3};"
                 : "+f"(d0), "+f"(d1), "+f"(d2), "+f"(d3)
                 : "r"(a0), "r"(a1), "r"(a2), "r"(a3), "r"(b0), "r"(b1));
}

__device__ __forceinline__ void ldsm4(uint32_t& r0, uint32_t& r1, uint32_t& r2, uint32_t& r3,
                                      uint32_t addr)
{
    asm volatile("ldmatrix.sync.aligned.m8n8.x4.shared.b16 {%0,%1,%2,%3}, [%4];"
                 : "=r"(r0), "=r"(r1), "=r"(r2), "=r"(r3) : "r"(addr));
}

__device__ __forceinline__ uint32_t pack_h2(float a, float b) {
    __half2 h = __floats2half2_rn(a, b);
    return *(uint32_t*)&h;
}

// ---------------- fp16 conversion kernel (weights, once per launch) ----------------
__global__ void to_half_kernel(const float* __restrict__ in, __half* __restrict__ out, int n4)
{
    for (int i = blockIdx.x * blockDim.x + threadIdx.x; i < n4; i += gridDim.x * blockDim.x) {
        float4 v = ((const float4*)in)[i];
        __half2 lo = __floats2half2_rn(v.x, v.y);
        __half2 hi = __floats2half2_rn(v.z, v.w);
        ((__half2*)out)[2 * i]     = lo;
        ((__half2*)out)[2 * i + 1] = hi;
    }
}

// ---------------- embedding (writes x and fp16 xh) ----------------
__global__ void embed_kernel(
    const float* __restrict__ q, const float* __restrict__ p,
    const float* __restrict__ qm, const float* __restrict__ pm,
    const float* __restrict__ z,
    const float* __restrict__ Wq, const float* __restrict__ bq,
    const float* __restrict__ Wp, const float* __restrict__ bp,
    const float* __restrict__ Wz, const float* __restrict__ bz,
    const float* __restrict__ pos, const float* __restrict__ noise,
    float* __restrict__ x, __half* __restrict__ xh)
{
    int s = blockIdx.x;
    if (s >= SEQ) {
        for (int h = threadIdx.x; h < H; h += blockDim.x) {
            x[(size_t)s * H + h] = 0.0f;
            xh[(size_t)s * H + h] = __float2half(0.0f);
        }
        return;
    }
    __shared__ float vin[128];
    const float *W, *b, *src;
    int dim;
    float mask;
    if (s == 0)          { src = z;                   dim = 128; W = Wz; b = bz; mask = 1.0f; }
    else if (s <= 2048)  { src = q + (s - 1) * 64;    dim = 64;  W = Wq; b = bq; mask = qm[s - 1]; }
    else                 { src = p + (s - 2049) * 64; dim = 64;  W = Wp; b = bp; mask = pm[s - 2049]; }

    for (int i = threadIdx.x; i < dim; i += blockDim.x) vin[i] = src[i];
    __syncthreads();

    int idx = (int)(mask * 100.0f);
    const float* ne = noise + (size_t)idx * H;

    for (int h = threadIdx.x; h < H; h += blockDim.x) {
        const float* w = W + (size_t)h * dim;
        float acc = b[h];
#pragma unroll 8
        for (int d = 0; d < dim; d++) acc = fmaf(vin[d], w[d], acc);
        float v = acc + pos[(size_t)s * H + h] + ne[h];
        x[(size_t)s * H + h] = v;
        xh[(size_t)s * H + h] = __float2half_rn(v);
    }
}

// ---------------- fp16 GEMM: raw mma m16n8k16 + ldmatrix ----------------
// C[M,N] = A[M,K] @ W[N,K]^T + bias (opt ReLU); C fp32 or fp16.
// BM=BN=128, BK=64, 256 threads / 8 warps, warp tile 64x32.
#define AST 72                       // smem row stride (halves) = 144B
#define GTILE (128 * AST)            // halves per tile
#define GEMM_SMEM (4 * GTILE * 2)    // 73728 B

template <bool RELU, bool HOUT>
__global__ __launch_bounds__(256, 2)
void tgemm(const __half* __restrict__ A, const __half* __restrict__ W,
           const float* __restrict__ bias, void* __restrict__ Cv,
           int M, int N, int K)
{
    extern __shared__ __half smg[];
    __half* AsBuf[2] = { smg,         smg + 2 * GTILE };
    __half* BsBuf[2] = { smg + GTILE, smg + 3 * GTILE };

    const int t    = threadIdx.x;
    const int lane = t & 31;
    const int w    = t >> 5;
    const int bm = blockIdx.y * 128, bn = blockIdx.x * 128;
    const int wm = w >> 2, wn = w & 3;
    const int quad = lane >> 2, tig = lane & 3;

    // ldmatrix lane->address mappings (halves)
    const int a_row  = (lane & 7) + ((lane >> 3) & 1) * 8;
    const int a_koff = ((lane >> 4) & 1) * 8;
    const int b_row  = (lane & 7) + ((lane & 16) >> 1);
    const int b_koff = ((lane >> 3) & 1) * 8;

    const __half* Ab = A + (size_t)bm * K;
    const __half* Wb = W + (size_t)bn * K;

    float c[4][4][4];
#pragma unroll
    for (int mi = 0; mi < 4; mi++)
#pragma unroll
        for (int ni = 0; ni < 4; ni++)
#pragma unroll
            for (int e = 0; e < 4; e++) c[mi][ni][e] = 0.f;

    const int kt = K / 64;

    auto stage = [&](int buf, int k0) {
#pragma unroll
        for (int v = 0; v < 4; v++) {
            int linear = t + v * 256;
            int row = linear >> 3;
            int off = (linear & 7) * 8;   // halves
            __pipeline_memcpy_async(&AsBuf[buf][row * AST + off],
                                    Ab + (size_t)row * K + k0 + off, 16);
            __pipeline_memcpy_async(&BsBuf[buf][row * AST + off],
                                    Wb + (size_t)row * K + k0 + off, 16);
        }
        __pipeline_commit();
    };

    stage(0, 0);
    for (int it = 0; it < kt; it++) {
        if (it + 1 < kt) stage((it + 1) & 1, (it + 1) * 64);
        __pipeline_wait_prior((it + 1 < kt) ? 1 : 0);
        __syncthreads();

        const __half* Ap = AsBuf[it & 1];
        const __half* Bp = BsBuf[it & 1];
        uint32_t aBase = (uint32_t)__cvta_generic_to_shared(
            Ap + (wm * 64 + a_row) * AST + a_koff);
        uint32_t bBase = (uint32_t)__cvta_generic_to_shared(
            Bp + (wn * 32 + b_row) * AST + b_koff);

#pragma unroll
        for (int kk = 0; kk < 64; kk += 16) {
            uint32_t a[4][4];
#pragma unroll
            for (int mi = 0; mi < 4; mi++)
                ldsm4(a[mi][0], a[mi][1], a[mi][2], a[mi][3],
                      aBase + (uint32_t)((mi * 16 * AST + kk) * 2));
            uint32_t bf[8];
            ldsm4(bf[0], bf[1], bf[2], bf[3], bBase + (uint32_t)(kk * 2));
            ldsm4(bf[4], bf[5], bf[6], bf[7], bBase + (uint32_t)((16 * AST + kk) * 2));
#pragma unroll
            for (int mi = 0; mi < 4; mi++)
#pragma unroll
                for (int ni = 0; ni < 4; ni++)
                    mma_f16(c[mi][ni][0], c[mi][ni][1], c[mi][ni][2], c[mi][ni][3],
                            a[mi][0], a[mi][1], a[mi][2], a[mi][3],
                            bf[2 * ni], bf[2 * ni + 1]);
        }
        __syncthreads();
    }

    // direct global epilogue from c-frags
#pragma unroll
    for (int mi = 0; mi < 4; mi++) {
        int row0 = bm + wm * 64 + mi * 16 + quad;
#pragma unroll
        for (int ni = 0; ni < 4; ni++) {
            int col = bn + wn * 32 + ni * 8 + tig * 2;
            float2 bb = *(const float2*)&bias[col];
            float v00 = c[mi][ni][0] + bb.x, v01 = c[mi][ni][1] + bb.y;
            float v10 = c[mi][ni][2] + bb.x, v11 = c[mi][ni][3] + bb.y;
            if (RELU) {
                v00 = fmaxf(v00, 0.f); v01 = fmaxf(v01, 0.f);
                v10 = fmaxf(v10, 0.f); v11 = fmaxf(v11, 0.f);
            }
            if (HOUT) {
                __half* C = (__half*)Cv;
                *(__half2*)&C[(size_t)row0 * N + col]       = __floats2half2_rn(v00, v01);
                *(__half2*)&C[(size_t)(row0 + 8) * N + col] = __floats2half2_rn(v10, v11);
            } else {
                float* C = (float*)Cv;
                *(float2*)&C[(size_t)row0 * N + col]       = make_float2(v00, v01);
                *(float2*)&C[(size_t)(row0 + 8) * N + col] = make_float2(v10, v11);
            }
        }
    }
}

// ---------------- flash attention, fp16 mma ----------------
// grid (SEQP/128, NH), 256 threads / 8 warps; warp owns 16 query rows.
#define KST 72
#define VST 72
#define PST 72
#define KBUF (64 * KST)
#define VBUF (64 * VST)
#define ATTN_SMEM ((2 * KBUF + 2 * VBUF + 8 * 16 * PST) * 2)   // 55296 B

__global__ __launch_bounds__(256, 2)
void attn_kernel(const __half* __restrict__ qkv, __half* __restrict__ out)
{
    extern __shared__ __half sma[];
    __half* Ksm[2] = { sma, sma + KBUF };
    __half* Vsm[2] = { sma + 2 * KBUF, sma + 2 * KBUF + VBUF };
    __half* Pall   = sma + 2 * KBUF + 2 * VBUF;

    const int t    = threadIdx.x;
    const int lane = t & 31;
    const int w    = t >> 5;
    const int quad = lane >> 2;
    const int tig  = lane & 3;
    const int head = blockIdx.y;
    const int q0   = blockIdx.x * 128;
    const int coff = head * 64;

    __half* Pme = Pall + w * 16 * PST;

    // staging: K,V tiles 64 rows x 64 halves = 512 chunks of 16B each
    auto stage = [&](int k0, int buf) {
#pragma unroll
        for (int v = 0; v < 2; v++) {
            int linear = t + v * 256;
            int row = linear >> 3;
            int off = (linear & 7) * 8;
            __pipeline_memcpy_async(&Ksm[buf][row * KST + off],
                                    &qkv[(size_t)(k0 + row) * H3 + H + coff + off], 16);
            __pipeline_memcpy_async(&Vsm[buf][row * VST + off],
                                    &qkv[(size_t)(k0 + row) * H3 + 2 * H + coff + off], 16);
        }
        __pipeline_commit();
    };

    // ---- Q fragments (pre-scaled by 1/8): 4 k16 chunks ----
    uint32_t Qa[4][4];
    {
        const __half* qb = qkv + (size_t)(q0 + w * 16) * H3 + coff;
#pragma unroll
        for (int c = 0; c < 4; c++) {
#pragma unroll
            for (int e = 0; e < 4; e++) {
                int r   = quad + (e & 1) * 8;
                int col = c * 16 + (e >> 1) * 8 + tig * 2;
                float2 v = __half22float2(*(const __half2*)&qb[(size_t)r * H3 + col]);
                Qa[c][e] = pack_h2(v.x * 0.125f, v.y * 0.125f);
            }
        }
    }

    float o[8][4];
#pragma unroll
    for (int nb = 0; nb < 8; nb++)
#pragma unroll
        for (int e = 0; e < 4; e++) o[nb][e] = 0.f;
    float m0 = -1e30f, m1 = -1e30f, l0 = 0.f, l1 = 0.f;

    const int NITER = (SEQ + 63) / 64;   // 65

    stage(0, 0);
    for (int it = 0; it < NITER; it++) {
        const int k0 = it * 64;
        if (it + 1 < NITER) stage((it + 1) * 64, (it + 1) & 1);
        __pipeline_wait_prior((it + 1 < NITER) ? 1 : 0);
        __syncthreads();

        const __half* Kb = Ksm[it & 1];
        const __half* Vb = Vsm[it & 1];

        // ---- S = Q @ K^T ----
        float s[8][4];
#pragma unroll
        for (int jb = 0; jb < 8; jb++) {
            s[jb][0] = s[jb][1] = s[jb][2] = s[jb][3] = 0.f;
            const __half* kr = Kb + (8 * jb + quad) * KST + tig * 2;
#pragma unroll
            for (int c = 0; c < 4; c++) {
                uint32_t b0 = *(const uint32_t*)&kr[c * 16];
                uint32_t b1 = *(const uint32_t*)&kr[c * 16 + 8];
                mma_f16(s[jb][0], s[jb][1], s[jb][2], s[jb][3],
                        Qa[c][0], Qa[c][1], Qa[c][2], Qa[c][3], b0, b1);
            }
        }

        if (k0 + 64 > SEQ) {
#pragma unroll
            for (int jb = 0; jb < 8; jb++) {
                int col0 = k0 + jb * 8 + 2 * tig;
                if (col0 >= SEQ)     { s[jb][0] = -1e30f; s[jb][2] = -1e30f; }
                if (col0 + 1 >= SEQ) { s[jb][1] = -1e30f; s[jb][3] = -1e30f; }
            }
        }

        // ---- online softmax ----
        float mx0 = -1e30f, mx1 = -1e30f;
#pragma unroll
        for (int jb = 0; jb < 8; jb++) {
            mx0 = fmaxf(mx0, fmaxf(s[jb][0], s[jb][1]));
            mx1 = fmaxf(mx1, fmaxf(s[jb][2], s[jb][3]));
        }
        mx0 = fmaxf(mx0, __shfl_xor_sync(0xffffffffu, mx0, 1));
        mx0 = fmaxf(mx0, __shfl_xor_sync(0xffffffffu, mx0, 2));
        mx1 = fmaxf(mx1, __shfl_xor_sync(0xffffffffu, mx1, 1));
        mx1 = fmaxf(mx1, __shfl_xor_sync(0xffffffffu, mx1, 2));

        float mn0 = fmaxf(m0, mx0), mn1 = fmaxf(m1, mx1);
        float corr0 = __expf(m0 - mn0), corr1 = __expf(m1 - mn1);
        m0 = mn0; m1 = mn1;

        float sum0 = 0.f, sum1 = 0.f;
#pragma unroll
        for (int jb = 0; jb < 8; jb++) {
            float p0 = __expf(s[jb][0] - mn0);
            float p1 = __expf(s[jb][1] - mn0);
            float p2 = __expf(s[jb][2] - mn1);
            float p3 = __expf(s[jb][3] - mn1);
            sum0 += p0 + p1;
            sum1 += p2 + p3;
            *(__half2*)&Pme[quad * PST + jb * 8 + tig * 2]       = __floats2half2_rn(p0, p1);
            *(__half2*)&Pme[(quad + 8) * PST + jb * 8 + tig * 2] = __floats2half2_rn(p2, p3);
        }
        sum0 += __shfl_xor_sync(0xffffffffu, sum0, 1);
        sum0 += __shfl_xor_sync(0xffffffffu, sum0, 2);
        sum1 += __shfl_xor_sync(0xffffffffu, sum1, 1);
        sum1 += __shfl_xor_sync(0xffffffffu, sum1, 2);
        l0 = l0 * corr0 + sum0;
        l1 = l1 * corr1 + sum1;

#pragma unroll
        for (int nb = 0; nb < 8; nb++) {
            o[nb][0] *= corr0; o[nb][1] *= corr0;
            o[nb][2] *= corr1; o[nb][3] *= corr1;
        }

        __syncwarp();

        // ---- O += P @ V ----
#pragma unroll
        for (int kc = 0; kc < 4; kc++) {
            uint32_t p0 = *(const uint32_t*)&Pme[quad * PST + kc * 16 + tig * 2];
            uint32_t p1 = *(const uint32_t*)&Pme[(quad + 8) * PST + kc * 16 + tig * 2];
            uint32_t p2 = *(const uint32_t*)&Pme[quad * PST + kc * 16 + 8 + tig * 2];
            uint32_t p3 = *(const uint32_t*)&Pme[(quad + 8) * PST + kc * 16 + 8 + tig * 2];
            int kr0 = kc * 16 + tig * 2;
#pragma unroll
            for (int nb = 0; nb < 8; nb++) {
                int nn = nb * 8 + quad;
                __half2 h0 = __halves2half2(Vb[kr0 * VST + nn],       Vb[(kr0 + 1) * VST + nn]);
                __half2 h1 = __halves2half2(Vb[(kr0 + 8) * VST + nn], Vb[(kr0 + 9) * VST + nn]);
                mma_f16(o[nb][0], o[nb][1], o[nb][2], o[nb][3],
                        p0, p1, p2, p3, *(uint32_t*)&h0, *(uint32_t*)&h1);
            }
        }

        __syncthreads();
    }

    float inv0 = 1.0f / l0, inv1 = 1.0f / l1;
    __half* ob0 = out + (size_t)(q0 + w * 16 + quad) * H + coff;
    __half* ob1 = out + (size_t)(q0 + w * 16 + quad + 8) * H + coff;
#pragma unroll
    for (int nb = 0; nb < 8; nb++) {
        *(__half2*)&ob0[nb * 8 + 2 * tig] = __floats2half2_rn(o[nb][0] * inv0, o[nb][1] * inv0);
        *(__half2*)&ob1[nb * 8 + 2 * tig] = __floats2half2_rn(o[nb][2] * inv1, o[nb][3] * inv1);
    }
}

// ---------------- fused add + LayerNorm (writes x and fp16 xh) ----------------
__global__ __launch_bounds__(256)
void addln_kernel(const float* __restrict__ a, const float* __restrict__ b,
                  const float* __restrict__ w, const float* __restrict__ wb,
                  float* __restrict__ outx, __half* __restrict__ outxh)
{
    int s = blockIdx.x;
    int t = threadIdx.x;
    const float4 av = ((const float4*)(a + (size_t)s * H))[t];
    const float4 bv = ((const float4*)(b + (size_t)s * H))[t];
    float v[4] = {av.x + bv.x, av.y + bv.y, av.z + bv.z, av.w + bv.w};

    float s1 = v[0] + v[1] + v[2] + v[3];
    float s2 = v[0]*v[0] + v[1]*v[1] + v[2]*v[2] + v[3]*v[3];
#pragma unroll
    for (int off = 16; off > 0; off >>= 1) {
        s1 += __shfl_xor_sync(0xffffffffu, s1, off);
        s2 += __shfl_xor_sync(0xffffffffu, s2, off);
    }
    __shared__ float r1[8], r2[8];
    int wid = t >> 5, lane = t & 31;
    if (lane == 0) { r1[wid] = s1; r2[wid] = s2; }
    __syncthreads();
    if (t == 0) {
        float a0 = 0.f, b0 = 0.f;
#pragma unroll
        for (int i = 0; i < 8; i++) { a0 += r1[i]; b0 += r2[i]; }
        r1[0] = a0; r2[0] = b0;
    }
    __syncthreads();
    float mean = r1[0] * (1.0f / H);
    float var  = r2[0] * (1.0f / H) - mean * mean;
    float rstd = rsqrtf(var + 1e-5f);

    const float4 wv  = ((const float4*)w)[t];
    const float4 wbv = ((const float4*)wb)[t];
    float4 ov;
    ov.x = (v[0] - mean) * rstd * wv.x + wbv.x;
    ov.y = (v[1] - mean) * rstd * wv.y + wbv.y;
    ov.z = (v[2] - mean) * rstd * wv.z + wbv.z;
    ov.w = (v[3] - mean) * rstd * wv.w + wbv.w;
    ((float4*)(outx + (size_t)s * H))[t] = ov;

    __half2 h0 = __floats2half2_rn(ov.x, ov.y);
    __half2 h1 = __floats2half2_rn(ov.z, ov.w);
    ((__half2*)(outxh + (size_t)s * H))[2 * t]     = h0;
    ((__half2*)(outxh + (size_t)s * H))[2 * t + 1] = h1;
}

// ---------------- final projection ----------------
__global__ void final_kernel(const float* __restrict__ x, const float* __restrict__ Wout,
                             const float* __restrict__ bout, float* __restrict__ out)
{
    int o = threadIdx.x;
    if (o >= OUTD) return;
    const float* w = Wout + (size_t)o * H;
    float acc = bout[o];
#pragma unroll 8
    for (int d = 0; d < H; d++) acc = fmaf(x[d], w[d], acc);
    out[o] = acc;
}

// ---------------- launch ----------------
extern "C" void kernel_launch(void* const* d_in, const int* in_sizes, int n_in,
                              void* d_out, int out_size)
{
    (void)in_sizes; (void)n_in; (void)out_size;
    const float* q     = (const float*)d_in[0];
    const float* p     = (const float*)d_in[1];
    const float* qm    = (const float*)d_in[2];
    const float* pm    = (const float*)d_in[3];
    const float* z     = (const float*)d_in[4];
    const float* Wq    = (const float*)d_in[5];
    const float* bq    = (const float*)d_in[6];
    const float* Wp    = (const float*)d_in[7];
    const float* bp    = (const float*)d_in[8];
    const float* Wz    = (const float*)d_in[9];
    const float* bz    = (const float*)d_in[10];
    const float* pos   = (const float*)d_in[11];
    const float* noise = (const float*)d_in[12];
    const float* Wqkv  = (const float*)d_in[13];
    const float* bqkv  = (const float*)d_in[14];
    const float* Wo    = (const float*)d_in[15];
    const float* bo    = (const float*)d_in[16];
    const float* ln1w  = (const float*)d_in[17];
    const float* ln1b  = (const float*)d_in[18];
    const float* W1    = (const float*)d_in[19];
    const float* b1    = (const float*)d_in[20];
    const float* W2    = (const float*)d_in[21];
    const float* b2    = (const float*)d_in[22];
    const float* ln2w  = (const float*)d_in[23];
    const float* ln2b  = (const float*)d_in[24];
    const float* Wout  = (const float*)d_in[25];
    const float* bout  = (const float*)d_in[26];

    float *x, *tmp;
    __half *xh, *qkvb, *attnb, *ff, *wqkv_h, *wo_h, *w1_h, *w2_h;
    cudaGetSymbolAddress((void**)&x,      g_x);
    cudaGetSymbolAddress((void**)&xh,     g_xh);
    cudaGetSymbolAddress((void**)&qkvb,   g_qkv);
    cudaGetSymbolAddress((void**)&attnb,  g_attn);
    cudaGetSymbolAddress((void**)&tmp,    g_tmp);
    cudaGetSymbolAddress((void**)&ff,     g_ff);
    cudaGetSymbolAddress((void**)&wqkv_h, g_wqkv_h);
    cudaGetSymbolAddress((void**)&wo_h,   g_wo_h);
    cudaGetSymbolAddress((void**)&w1_h,   g_w1_h);
    cudaGetSymbolAddress((void**)&w2_h,   g_w2_h);

    cudaFuncSetAttribute((const void*)tgemm<false,true>,  cudaFuncAttributeMaxDynamicSharedMemorySize, GEMM_SMEM);
    cudaFuncSetAttribute((const void*)tgemm<false,false>, cudaFuncAttributeMaxDynamicSharedMemorySize, GEMM_SMEM);
    cudaFuncSetAttribute((const void*)tgemm<true,true>,   cudaFuncAttributeMaxDynamicSharedMemorySize, GEMM_SMEM);
    cudaFuncSetAttribute((const void*)attn_kernel,        cudaFuncAttributeMaxDynamicSharedMemorySize, ATTN_SMEM);

    // convert weights to fp16 (once per launch; deterministic)
    to_half_kernel<<<2048, 256>>>(Wqkv, wqkv_h, WQKV_N / 4);
    to_half_kernel<<<2048, 256>>>(Wo,   wo_h,   WO_N / 4);
    to_half_kernel<<<2048, 256>>>(W1,   w1_h,   W1_N / 4);
    to_half_kernel<<<2048, 256>>>(W2,   w2_h,   W2_N / 4);

    embed_kernel<<<SEQP, 256>>>(q, p, qm, pm, z, Wq, bq, Wp, bp, Wz, bz, pos, noise, x, xh);

    const int MB = SEQP / 128;   // 33
    for (int i = 0; i < LAYERS; i++) {
        tgemm<false,true><<<dim3(H3 / 128, MB), 256, GEMM_SMEM>>>(
            xh, wqkv_h + (size_t)i * H3 * H, bqkv + (size_t)i * H3, qkvb, SEQP, H3, H);
        attn_kernel<<<dim3(SEQP / 128, NH), 256, ATTN_SMEM>>>(qkvb, attnb);
        tgemm<false,false><<<dim3(H / 128, MB), 256, GEMM_SMEM>>>(
            attnb, wo_h + (size_t)i * H * H, bo + (size_t)i * H, tmp, SEQP, H, H);
        addln_kernel<<<SEQP, 256>>>(x, tmp, ln1w + (size_t)i * H, ln1b + (size_t)i * H, x, xh);
        tgemm<true,true><<<dim3(FFD / 128, MB), 256, GEMM_SMEM>>>(
            xh, w1_h + (size_t)i * FFD * H, b1 + (size_t)i * FFD, ff, SEQP, FFD, H);
        tgemm<false,false><<<dim3(H / 128, MB), 256, GEMM_SMEM>>>(
            ff, w2_h + (size_t)i * H * FFD, b2 + (size_t)i * H, tmp, SEQP, H, FFD);
        addln_kernel<<<SEQP, 256>>>(x, tmp, ln2w + (size_t)i * H, ln2b + (size_t)i * H, x, xh);
    }

    final_kernel<<<1, 128>>>(x, Wout, bout, (float*)d_out);
}

// round 7
// speedup vs baseline: 6.6549x; 1.1955x over previous
#include <cuda_runtime.h>
#include <cuda_pipeline.h>
#include <cuda_fp16.h>
#include <math.h>
#include <stdint.h>

#define SEQ  4097
#define SEQP 4224          // 33 * 128, padded
#define H    1024
#define NH   16
#define HD   64
#define H3   3072
#define FFD  4096
#define LAYERS 6
#define OUTD 128

#define WQKV_N (LAYERS * H3 * H)
#define WO_N   (LAYERS * H * H)
#define W1_N   (LAYERS * FFD * H)
#define W2_N   (LAYERS * H * FFD)

// ---------------- scratch (device globals; no allocations) ----------------
__device__ float  g_x[SEQP * H];
__device__ __half g_xh[SEQP * H];
__device__ __half g_qkv[SEQP * H3];
__device__ __half g_attn[SEQP * H];
__device__ float  g_tmp[SEQP * H];
__device__ __half g_ff[SEQP * FFD];
__device__ __half g_wqkv_h[WQKV_N];
__device__ __half g_wo_h[WO_N];
__device__ __half g_w1_h[W1_N];
__device__ __half g_w2_h[W2_N];

__device__ __forceinline__ void mma_f16(float& d0, float& d1, float& d2, float& d3,
                                        uint32_t a0, uint32_t a1, uint32_t a2, uint32_t a3,
                                        uint32_t b0, uint32_t b1)
{
    asm volatile("mma.sync.aligned.m16n8k16.row.col.f32.f16.f16.f32 "
                 "{%0,%1,%2,%3},{%4,%5,%6,%7},{%8,%9},{%0,%1,%2,%3};"
                 : "+f"(d0), "+f"(d1), "+f"(d2), "+f"(d3)
                 : "r"(a0), "r"(a1), "r"(a2), "r"(a3), "r"(b0), "r"(b1));
}

__device__ __forceinline__ void ldsm4(uint32_t& r0, uint32_t& r1, uint32_t& r2, uint32_t& r3,
                                      uint32_t addr)
{
    asm volatile("ldmatrix.sync.aligned.m8n8.x4.shared.b16 {%0,%1,%2,%3}, [%4];"
                 : "=r"(r0), "=r"(r1), "=r"(r2), "=r"(r3) : "r"(addr));
}

__device__ __forceinline__ void ldsm4t(uint32_t& r0, uint32_t& r1, uint32_t& r2, uint32_t& r3,
                                       uint32_t addr)
{
    asm volatile("ldmatrix.sync.aligned.m8n8.x4.trans.shared.b16 {%0,%1,%2,%3}, [%4];"
                 : "=r"(r0), "=r"(r1), "=r"(r2), "=r"(r3) : "r"(addr));
}

__device__ __forceinline__ uint32_t pack_h2(float a, float b) {
    __half2 h = __floats2half2_rn(a, b);
    return *(uint32_t*)&h;
}

// ---------------- fp16 conversion kernel (weights, once per launch) ----------------
__global__ void to_half_kernel(const float* __restrict__ in, __half* __restrict__ out, int n4)
{
    for (int i = blockIdx.x * blockDim.x + threadIdx.x; i < n4; i += gridDim.x * blockDim.x) {
        float4 v = ((const float4*)in)[i];
        ((__half2*)out)[2 * i]     = __floats2half2_rn(v.x, v.y);
        ((__half2*)out)[2 * i + 1] = __floats2half2_rn(v.z, v.w);
    }
}

// ---------------- embedding (writes x and fp16 xh) ----------------
__global__ void embed_kernel(
    const float* __restrict__ q, const float* __restrict__ p,
    const float* __restrict__ qm, const float* __restrict__ pm,
    const float* __restrict__ z,
    const float* __restrict__ Wq, const float* __restrict__ bq,
    const float* __restrict__ Wp, const float* __restrict__ bp,
    const float* __restrict__ Wz, const float* __restrict__ bz,
    const float* __restrict__ pos, const float* __restrict__ noise,
    float* __restrict__ x, __half* __restrict__ xh)
{
    int s = blockIdx.x;
    if (s >= SEQ) {
        for (int h = threadIdx.x; h < H; h += blockDim.x) {
            x[(size_t)s * H + h] = 0.0f;
            xh[(size_t)s * H + h] = __float2half(0.0f);
        }
        return;
    }
    __shared__ float vin[128];
    const float *W, *b, *src;
    int dim;
    float mask;
    if (s == 0)          { src = z;                   dim = 128; W = Wz; b = bz; mask = 1.0f; }
    else if (s <= 2048)  { src = q + (s - 1) * 64;    dim = 64;  W = Wq; b = bq; mask = qm[s - 1]; }
    else                 { src = p + (s - 2049) * 64; dim = 64;  W = Wp; b = bp; mask = pm[s - 2049]; }

    for (int i = threadIdx.x; i < dim; i += blockDim.x) vin[i] = src[i];
    __syncthreads();

    int idx = (int)(mask * 100.0f);
    const float* ne = noise + (size_t)idx * H;

    for (int h = threadIdx.x; h < H; h += blockDim.x) {
        const float* w = W + (size_t)h * dim;
        float acc = b[h];
#pragma unroll 8
        for (int d = 0; d < dim; d++) acc = fmaf(vin[d], w[d], acc);
        float v = acc + pos[(size_t)s * H + h] + ne[h];
        x[(size_t)s * H + h] = v;
        xh[(size_t)s * H + h] = __float2half_rn(v);
    }
}

// ---------------- fp16 GEMM: raw mma m16n8k16 + ldmatrix (unchanged R6) ----------------
#define AST 72
#define GTILE (128 * AST)
#define GEMM_SMEM (4 * GTILE * 2)

template <bool RELU, bool HOUT>
__global__ __launch_bounds__(256, 2)
void tgemm(const __half* __restrict__ A, const __half* __restrict__ W,
           const float* __restrict__ bias, void* __restrict__ Cv,
           int M, int N, int K)
{
    extern __shared__ __half smg[];
    __half* AsBuf[2] = { smg,         smg + 2 * GTILE };
    __half* BsBuf[2] = { smg + GTILE, smg + 3 * GTILE };

    const int t    = threadIdx.x;
    const int lane = t & 31;
    const int w    = t >> 5;
    const int bm = blockIdx.y * 128, bn = blockIdx.x * 128;
    const int wm = w >> 2, wn = w & 3;
    const int quad = lane >> 2, tig = lane & 3;

    const int a_row  = (lane & 7) + ((lane >> 3) & 1) * 8;
    const int a_koff = ((lane >> 4) & 1) * 8;
    const int b_row  = (lane & 7) + ((lane & 16) >> 1);
    const int b_koff = ((lane >> 3) & 1) * 8;

    const __half* Ab = A + (size_t)bm * K;
    const __half* Wb = W + (size_t)bn * K;

    float c[4][4][4];
#pragma unroll
    for (int mi = 0; mi < 4; mi++)
#pragma unroll
        for (int ni = 0; ni < 4; ni++)
#pragma unroll
            for (int e = 0; e < 4; e++) c[mi][ni][e] = 0.f;

    const int kt = K / 64;

    auto stage = [&](int buf, int k0) {
#pragma unroll
        for (int v = 0; v < 4; v++) {
            int linear = t + v * 256;
            int row = linear >> 3;
            int off = (linear & 7) * 8;
            __pipeline_memcpy_async(&AsBuf[buf][row * AST + off],
                                    Ab + (size_t)row * K + k0 + off, 16);
            __pipeline_memcpy_async(&BsBuf[buf][row * AST + off],
                                    Wb + (size_t)row * K + k0 + off, 16);
        }
        __pipeline_commit();
    };

    stage(0, 0);
    for (int it = 0; it < kt; it++) {
        if (it + 1 < kt) stage((it + 1) & 1, (it + 1) * 64);
        __pipeline_wait_prior((it + 1 < kt) ? 1 : 0);
        __syncthreads();

        const __half* Ap = AsBuf[it & 1];
        const __half* Bp = BsBuf[it & 1];
        uint32_t aBase = (uint32_t)__cvta_generic_to_shared(
            Ap + (wm * 64 + a_row) * AST + a_koff);
        uint32_t bBase = (uint32_t)__cvta_generic_to_shared(
            Bp + (wn * 32 + b_row) * AST + b_koff);

#pragma unroll
        for (int kk = 0; kk < 64; kk += 16) {
            uint32_t a[4][4];
#pragma unroll
            for (int mi = 0; mi < 4; mi++)
                ldsm4(a[mi][0], a[mi][1], a[mi][2], a[mi][3],
                      aBase + (uint32_t)((mi * 16 * AST + kk) * 2));
            uint32_t bf[8];
            ldsm4(bf[0], bf[1], bf[2], bf[3], bBase + (uint32_t)(kk * 2));
            ldsm4(bf[4], bf[5], bf[6], bf[7], bBase + (uint32_t)((16 * AST + kk) * 2));
#pragma unroll
            for (int mi = 0; mi < 4; mi++)
#pragma unroll
                for (int ni = 0; ni < 4; ni++)
                    mma_f16(c[mi][ni][0], c[mi][ni][1], c[mi][ni][2], c[mi][ni][3],
                            a[mi][0], a[mi][1], a[mi][2], a[mi][3],
                            bf[2 * ni], bf[2 * ni + 1]);
        }
        __syncthreads();
    }

#pragma unroll
    for (int mi = 0; mi < 4; mi++) {
        int row0 = bm + wm * 64 + mi * 16 + quad;
#pragma unroll
        for (int ni = 0; ni < 4; ni++) {
            int col = bn + wn * 32 + ni * 8 + tig * 2;
            float2 bb = *(const float2*)&bias[col];
            float v00 = c[mi][ni][0] + bb.x, v01 = c[mi][ni][1] + bb.y;
            float v10 = c[mi][ni][2] + bb.x, v11 = c[mi][ni][3] + bb.y;
            if (RELU) {
                v00 = fmaxf(v00, 0.f); v01 = fmaxf(v01, 0.f);
                v10 = fmaxf(v10, 0.f); v11 = fmaxf(v11, 0.f);
            }
            if (HOUT) {
                __half* C = (__half*)Cv;
                *(__half2*)&C[(size_t)row0 * N + col]       = __floats2half2_rn(v00, v01);
                *(__half2*)&C[(size_t)(row0 + 8) * N + col] = __floats2half2_rn(v10, v11);
            } else {
                float* C = (float*)Cv;
                *(float2*)&C[(size_t)row0 * N + col]       = make_float2(v00, v01);
                *(float2*)&C[(size_t)(row0 + 8) * N + col] = make_float2(v10, v11);
            }
        }
    }
}

// ---------------- flash attention, fp16 mma + full ldmatrix ----------------
#define KST 72
#define VST 72
#define PST 72
#define KBUF (64 * KST)
#define VBUF (64 * VST)
#define ATTN_SMEM ((2 * KBUF + 2 * VBUF + 8 * 16 * PST) * 2)

__global__ __launch_bounds__(256, 2)
void attn_kernel(const __half* __restrict__ qkv, __half* __restrict__ out)
{
    extern __shared__ __half sma[];
    __half* Ksm[2] = { sma, sma + KBUF };
    __half* Vsm[2] = { sma + 2 * KBUF, sma + 2 * KBUF + VBUF };
    __half* Pall   = sma + 2 * KBUF + 2 * VBUF;

    const int t    = threadIdx.x;
    const int lane = t & 31;
    const int w    = t >> 5;
    const int quad = lane >> 2;
    const int tig  = lane & 3;
    const int head = blockIdx.y;
    const int q0   = blockIdx.x * 128;
    const int coff = head * 64;

    __half* Pme = Pall + w * 16 * PST;

    // ldmatrix lane mappings
    const int b_row  = (lane & 7) + ((lane & 16) >> 1);      // K: B-style (non-trans)
    const int b_koff = ((lane >> 3) & 1) * 8;
    const int a_row  = (lane & 7) + ((lane >> 3) & 1) * 8;   // P: A-style (non-trans)
    const int a_koff = ((lane >> 4) & 1) * 8;
    const int v_row  = (lane & 7) + ((lane >> 3) & 1) * 8;   // V: trans (k-rows)
    const int v_coff = ((lane >> 4) & 1) * 8;                // n within 16

    auto stage = [&](int k0, int buf) {
#pragma unroll
        for (int v = 0; v < 2; v++) {
            int linear = t + v * 256;
            int row = linear >> 3;
            int off = (linear & 7) * 8;
            __pipeline_memcpy_async(&Ksm[buf][row * KST + off],
                                    &qkv[(size_t)(k0 + row) * H3 + H + coff + off], 16);
            __pipeline_memcpy_async(&Vsm[buf][row * VST + off],
                                    &qkv[(size_t)(k0 + row) * H3 + 2 * H + coff + off], 16);
        }
        __pipeline_commit();
    };

    // ---- Q fragments (pre-scaled by 1/8): 4 k16 chunks ----
    uint32_t Qa[4][4];
    {
        const __half* qb = qkv + (size_t)(q0 + w * 16) * H3 + coff;
#pragma unroll
        for (int c = 0; c < 4; c++) {
#pragma unroll
            for (int e = 0; e < 4; e++) {
                int r   = quad + (e & 1) * 8;
                int col = c * 16 + (e >> 1) * 8 + tig * 2;
                float2 v = __half22float2(*(const __half2*)&qb[(size_t)r * H3 + col]);
                Qa[c][e] = pack_h2(v.x * 0.125f, v.y * 0.125f);
            }
        }
    }

    float o[8][4];
#pragma unroll
    for (int nb = 0; nb < 8; nb++)
#pragma unroll
        for (int e = 0; e < 4; e++) o[nb][e] = 0.f;
    float m0 = -1e30f, m1 = -1e30f, l0 = 0.f, l1 = 0.f;

    const int NITER = (SEQ + 63) / 64;   // 65

    stage(0, 0);
    for (int it = 0; it < NITER; it++) {
        const int k0 = it * 64;
        if (it + 1 < NITER) stage((it + 1) * 64, (it + 1) & 1);
        __pipeline_wait_prior((it + 1 < NITER) ? 1 : 0);
        __syncthreads();

        const __half* Kb = Ksm[it & 1];
        const __half* Vb = Vsm[it & 1];

        uint32_t kBase = (uint32_t)__cvta_generic_to_shared(Kb + b_row * KST + b_koff);
        uint32_t vBase = (uint32_t)__cvta_generic_to_shared(Vb + v_row * VST + v_coff);
        uint32_t pBase = (uint32_t)__cvta_generic_to_shared(Pme + a_row * PST + a_koff);

        // ---- S = Q @ K^T  (K via ldmatrix, GEMM-B layout) ----
        float s[8][4];
#pragma unroll
        for (int nb = 0; nb < 8; nb++)
            s[nb][0] = s[nb][1] = s[nb][2] = s[nb][3] = 0.f;
#pragma unroll
        for (int jn = 0; jn < 4; jn++) {
#pragma unroll
            for (int c = 0; c < 4; c++) {
                uint32_t bf[4];
                ldsm4(bf[0], bf[1], bf[2], bf[3],
                      kBase + (uint32_t)((jn * 16 * KST + c * 16) * 2));
                mma_f16(s[2*jn][0], s[2*jn][1], s[2*jn][2], s[2*jn][3],
                        Qa[c][0], Qa[c][1], Qa[c][2], Qa[c][3], bf[0], bf[1]);
                mma_f16(s[2*jn+1][0], s[2*jn+1][1], s[2*jn+1][2], s[2*jn+1][3],
                        Qa[c][0], Qa[c][1], Qa[c][2], Qa[c][3], bf[2], bf[3]);
            }
        }

        if (k0 + 64 > SEQ) {
#pragma unroll
            for (int jb = 0; jb < 8; jb++) {
                int col0 = k0 + jb * 8 + 2 * tig;
                if (col0 >= SEQ)     { s[jb][0] = -1e30f; s[jb][2] = -1e30f; }
                if (col0 + 1 >= SEQ) { s[jb][1] = -1e30f; s[jb][3] = -1e30f; }
            }
        }

        // ---- online softmax ----
        float mx0 = -1e30f, mx1 = -1e30f;
#pragma unroll
        for (int jb = 0; jb < 8; jb++) {
            mx0 = fmaxf(mx0, fmaxf(s[jb][0], s[jb][1]));
            mx1 = fmaxf(mx1, fmaxf(s[jb][2], s[jb][3]));
        }
        mx0 = fmaxf(mx0, __shfl_xor_sync(0xffffffffu, mx0, 1));
        mx0 = fmaxf(mx0, __shfl_xor_sync(0xffffffffu, mx0, 2));
        mx1 = fmaxf(mx1, __shfl_xor_sync(0xffffffffu, mx1, 1));
        mx1 = fmaxf(mx1, __shfl_xor_sync(0xffffffffu, mx1, 2));

        float mn0 = fmaxf(m0, mx0), mn1 = fmaxf(m1, mx1);
        float corr0 = __expf(m0 - mn0), corr1 = __expf(m1 - mn1);
        m0 = mn0; m1 = mn1;

        float sum0 = 0.f, sum1 = 0.f;
#pragma unroll
        for (int jb = 0; jb < 8; jb++) {
            float p0 = __expf(s[jb][0] - mn0);
            float p1 = __expf(s[jb][1] - mn0);
            float p2 = __expf(s[jb][2] - mn1);
            float p3 = __expf(s[jb][3] - mn1);
            sum0 += p0 + p1;
            sum1 += p2 + p3;
            *(__half2*)&Pme[quad * PST + jb * 8 + tig * 2]       = __floats2half2_rn(p0, p1);
            *(__half2*)&Pme[(quad + 8) * PST + jb * 8 + tig * 2] = __floats2half2_rn(p2, p3);
        }
        sum0 += __shfl_xor_sync(0xffffffffu, sum0, 1);
        sum0 += __shfl_xor_sync(0xffffffffu, sum0, 2);
        sum1 += __shfl_xor_sync(0xffffffffu, sum1, 1);
        sum1 += __shfl_xor_sync(0xffffffffu, sum1, 2);
        l0 = l0 * corr0 + sum0;
        l1 = l1 * corr1 + sum1;

#pragma unroll
        for (int nb = 0; nb < 8; nb++) {
            o[nb][0] *= corr0; o[nb][1] *= corr0;
            o[nb][2] *= corr1; o[nb][3] *= corr1;
        }

        __syncwarp();   // P stores visible to this warp's ldmatrix

        // ---- O += P @ V  (P via ldmatrix-A, V via ldmatrix-trans) ----
#pragma unroll
        for (int kc = 0; kc < 4; kc++) {
            uint32_t pf[4];
            ldsm4(pf[0], pf[1], pf[2], pf[3], pBase + (uint32_t)(kc * 16 * 2));
#pragma unroll
            for (int jn = 0; jn < 4; jn++) {
                uint32_t bf[4];
                ldsm4t(bf[0], bf[1], bf[2], bf[3],
                       vBase + (uint32_t)((kc * 16 * VST + jn * 16) * 2));
                mma_f16(o[2*jn][0], o[2*jn][1], o[2*jn][2], o[2*jn][3],
                        pf[0], pf[1], pf[2], pf[3], bf[0], bf[1]);
                mma_f16(o[2*jn+1][0], o[2*jn+1][1], o[2*jn+1][2], o[2*jn+1][3],
                        pf[0], pf[1], pf[2], pf[3], bf[2], bf[3]);
            }
        }

        __syncthreads();
    }

    float inv0 = 1.0f / l0, inv1 = 1.0f / l1;
    __half* ob0 = out + (size_t)(q0 + w * 16 + quad) * H + coff;
    __half* ob1 = out + (size_t)(q0 + w * 16 + quad + 8) * H + coff;
#pragma unroll
    for (int nb = 0; nb < 8; nb++) {
        *(__half2*)&ob0[nb * 8 + 2 * tig] = __floats2half2_rn(o[nb][0] * inv0, o[nb][1] * inv0);
        *(__half2*)&ob1[nb * 8 + 2 * tig] = __floats2half2_rn(o[nb][2] * inv1, o[nb][3] * inv1);
    }
}

// ---------------- fused add + LayerNorm (writes x and fp16 xh) ----------------
__global__ __launch_bounds__(256)
void addln_kernel(const float* __restrict__ a, const float* __restrict__ b,
                  const float* __restrict__ w, const float* __restrict__ wb,
                  float* __restrict__ outx, __half* __restrict__ outxh)
{
    int s = blockIdx.x;
    int t = threadIdx.x;
    const float4 av = ((const float4*)(a + (size_t)s * H))[t];
    const float4 bv = ((const float4*)(b + (size_t)s * H))[t];
    float v[4] = {av.x + bv.x, av.y + bv.y, av.z + bv.z, av.w + bv.w};

    float s1 = v[0] + v[1] + v[2] + v[3];
    float s2 = v[0]*v[0] + v[1]*v[1] + v[2]*v[2] + v[3]*v[3];
#pragma unroll
    for (int off = 16; off > 0; off >>= 1) {
        s1 += __shfl_xor_sync(0xffffffffu, s1, off);
        s2 += __shfl_xor_sync(0xffffffffu, s2, off);
    }
    __shared__ float r1[8], r2[8];
    int wid = t >> 5, lane = t & 31;
    if (lane == 0) { r1[wid] = s1; r2[wid] = s2; }
    __syncthreads();
    if (t == 0) {
        float a0 = 0.f, b0 = 0.f;
#pragma unroll
        for (int i = 0; i < 8; i++) { a0 += r1[i]; b0 += r2[i]; }
        r1[0] = a0; r2[0] = b0;
    }
    __syncthreads();
    float mean = r1[0] * (1.0f / H);
    float var  = r2[0] * (1.0f / H) - mean * mean;
    float rstd = rsqrtf(var + 1e-5f);

    const float4 wv  = ((const float4*)w)[t];
    const float4 wbv = ((const float4*)wb)[t];
    float4 ov;
    ov.x = (v[0] - mean) * rstd * wv.x + wbv.x;
    ov.y = (v[1] - mean) * rstd * wv.y + wbv.y;
    ov.z = (v[2] - mean) * rstd * wv.z + wbv.z;
    ov.w = (v[3] - mean) * rstd * wv.w + wbv.w;
    ((float4*)(outx + (size_t)s * H))[t] = ov;

    ((__half2*)(outxh + (size_t)s * H))[2 * t]     = __floats2half2_rn(ov.x, ov.y);
    ((__half2*)(outxh + (size_t)s * H))[2 * t + 1] = __floats2half2_rn(ov.z, ov.w);
}

// ---------------- final projection ----------------
__global__ void final_kernel(const float* __restrict__ x, const float* __restrict__ Wout,
                             const float* __restrict__ bout, float* __restrict__ out)
{
    int o = threadIdx.x;
    if (o >= OUTD) return;
    const float* w = Wout + (size_t)o * H;
    float acc = bout[o];
#pragma unroll 8
    for (int d = 0; d < H; d++) acc = fmaf(x[d], w[d], acc);
    out[o] = acc;
}

// ---------------- launch ----------------
extern "C" void kernel_launch(void* const* d_in, const int* in_sizes, int n_in,
                              void* d_out, int out_size)
{
    (void)in_sizes; (void)n_in; (void)out_size;
    const float* q     = (const float*)d_in[0];
    const float* p     = (const float*)d_in[1];
    const float* qm    = (const float*)d_in[2];
    const float* pm    = (const float*)d_in[3];
    const float* z     = (const float*)d_in[4];
    const float* Wq    = (const float*)d_in[5];
    const float* bq    = (const float*)d_in[6];
    const float* Wp    = (const float*)d_in[7];
    const float* bp    = (const float*)d_in[8];
    const float* Wz    = (const float*)d_in[9];
    const float* bz    = (const float*)d_in[10];
    const float* pos   = (const float*)d_in[11];
    const float* noise = (const float*)d_in[12];
    const float* Wqkv  = (const float*)d_in[13];
    const float* bqkv  = (const float*)d_in[14];
    const float* Wo    = (const float*)d_in[15];
    const float* bo    = (const float*)d_in[16];
    const float* ln1w  = (const float*)d_in[17];
    const float* ln1b  = (const float*)d_in[18];
    const float* W1    = (const float*)d_in[19];
    const float* b1    = (const float*)d_in[20];
    const float* W2    = (const float*)d_in[21];
    const float* b2    = (const float*)d_in[22];
    const float* ln2w  = (const float*)d_in[23];
    const float* ln2b  = (const float*)d_in[24];
    const float* Wout  = (const float*)d_in[25];
    const float* bout  = (const float*)d_in[26];

    float *x, *tmp;
    __half *xh, *qkvb, *attnb, *ff, *wqkv_h, *wo_h, *w1_h, *w2_h;
    cudaGetSymbolAddress((void**)&x,      g_x);
    cudaGetSymbolAddress((void**)&xh,     g_xh);
    cudaGetSymbolAddress((void**)&qkvb,   g_qkv);
    cudaGetSymbolAddress((void**)&attnb,  g_attn);
    cudaGetSymbolAddress((void**)&tmp,    g_tmp);
    cudaGetSymbolAddress((void**)&ff,     g_ff);
    cudaGetSymbolAddress((void**)&wqkv_h, g_wqkv_h);
    cudaGetSymbolAddress((void**)&wo_h,   g_wo_h);
    cudaGetSymbolAddress((void**)&w1_h,   g_w1_h);
    cudaGetSymbolAddress((void**)&w2_h,   g_w2_h);

    cudaFuncSetAttribute((const void*)tgemm<false,true>,  cudaFuncAttributeMaxDynamicSharedMemorySize, GEMM_SMEM);
    cudaFuncSetAttribute((const void*)tgemm<false,false>, cudaFuncAttributeMaxDynamicSharedMemorySize, GEMM_SMEM);
    cudaFuncSetAttribute((const void*)tgemm<true,true>,   cudaFuncAttributeMaxDynamicSharedMemorySize, GEMM_SMEM);
    cudaFuncSetAttribute((const void*)attn_kernel,        cudaFuncAttributeMaxDynamicSharedMemorySize, ATTN_SMEM);

    to_half_kernel<<<2048, 256>>>(Wqkv, wqkv_h, WQKV_N / 4);
    to_half_kernel<<<2048, 256>>>(Wo,   wo_h,   WO_N / 4);
    to_half_kernel<<<2048, 256>>>(W1,   w1_h,   W1_N / 4);
    to_half_kernel<<<2048, 256>>>(W2,   w2_h,   W2_N / 4);

    embed_kernel<<<SEQP, 256>>>(q, p, qm, pm, z, Wq, bq, Wp, bp, Wz, bz, pos, noise, x, xh);

    const int MB = SEQP / 128;   // 33
    for (int i = 0; i < LAYERS; i++) {
        tgemm<false,true><<<dim3(H3 / 128, MB), 256, GEMM_SMEM>>>(
            xh, wqkv_h + (size_t)i * H3 * H, bqkv + (size_t)i * H3, qkvb, SEQP, H3, H);
        attn_kernel<<<dim3(SEQP / 128, NH), 256, ATTN_SMEM>>>(qkvb, attnb);
        tgemm<false,false><<<dim3(H / 128, MB), 256, GEMM_SMEM>>>(
            attnb, wo_h + (size_t)i * H * H, bo + (size_t)i * H, tmp, SEQP, H, H);
        addln_kernel<<<SEQP, 256>>>(x, tmp, ln1w + (size_t)i * H, ln1b + (size_t)i * H, x, xh);
        tgemm<true,true><<<dim3(FFD / 128, MB), 256, GEMM_SMEM>>>(
            xh, w1_h + (size_t)i * FFD * H, b1 + (size_t)i * FFD, ff, SEQP, FFD, H);
        tgemm<false,false><<<dim3(H / 128, MB), 256, GEMM_SMEM>>>(
            ff, w2_h + (size_t)i * H * FFD, b2 + (size_t)i * H, tmp, SEQP, H, FFD);
        addln_kernel<<<SEQP, 256>>>(x, tmp, ln2w + (size_t)i * H, ln2b + (size_t)i * H, x, xh);
    }

    final_kernel<<<1, 128>>>(x, Wout, bout, (float*)d_out);
}

// round 9
// speedup vs baseline: 6.7878x; 1.0200x over previous
#include <cuda_runtime.h>
#include <cuda_pipeline.h>
#include <cuda_fp16.h>
#include <math.h>
#include <stdint.h>

#define SEQ  4097
#define SEQP 4224          // 33 * 128, padded
#define H    1024
#define NH   16
#define HD   64
#define H3   3072
#define FFD  4096
#define LAYERS 6
#define OUTD 128

#define WQKV_N (LAYERS * H3 * H)
#define WO_N   (LAYERS * H * H)
#define W1_N   (LAYERS * FFD * H)
#define W2_N   (LAYERS * H * FFD)

// ---------------- scratch (device globals; no allocations) ----------------
__device__ float  g_x[SEQP * H];
__device__ __half g_xh[SEQP * H];
__device__ __half g_qkv[SEQP * H3];
__device__ __half g_attn[SEQP * H];
__device__ float  g_tmp[SEQP * H];
__device__ __half g_ff[SEQP * FFD];
__device__ __half g_wqkv_h[WQKV_N];
__device__ __half g_wo_h[WO_N];
__device__ __half g_w1_h[W1_N];
__device__ __half g_w2_h[W2_N];

__device__ __forceinline__ void mma_f16(float& d0, float& d1, float& d2, float& d3,
                                        uint32_t a0, uint32_t a1, uint32_t a2, uint32_t a3,
                                        uint32_t b0, uint32_t b1)
{
    asm volatile("mma.sync.aligned.m16n8k16.row.col.f32.f16.f16.f32 "
                 "{%0,%1,%2,%3},{%4,%5,%6,%7},{%8,%9},{%0,%1,%2,%3};"
                 : "+f"(d0), "+f"(d1), "+f"(d2), "+f"(d3)
                 : "r"(a0), "r"(a1), "r"(a2), "r"(a3), "r"(b0), "r"(b1));
}

__device__ __forceinline__ void ldsm4(uint32_t& r0, uint32_t& r1, uint32_t& r2, uint32_t& r3,
                                      uint32_t addr)
{
    asm volatile("ldmatrix.sync.aligned.m8n8.x4.shared.b16 {%0,%1,%2,%3}, [%4];"
                 : "=r"(r0), "=r"(r1), "=r"(r2), "=r"(r3) : "r"(addr));
}

__device__ __forceinline__ void ldsm4t(uint32_t& r0, uint32_t& r1, uint32_t& r2, uint32_t& r3,
                                       uint32_t addr)
{
    asm volatile("ldmatrix.sync.aligned.m8n8.x4.trans.shared.b16 {%0,%1,%2,%3}, [%4];"
                 : "=r"(r0), "=r"(r1), "=r"(r2), "=r"(r3) : "r"(addr));
}

__device__ __forceinline__ uint32_t pack_h2(float a, float b) {
    __half2 h = __floats2half2_rn(a, b);
    return *(uint32_t*)&h;
}

// ---------------- fp16 conversion: all four weight tensors, one launch ----------------
__global__ void to_half_all_kernel(const float* __restrict__ w0, __half* __restrict__ o0,
                                   const float* __restrict__ w1, __half* __restrict__ o1,
                                   const float* __restrict__ w2, __half* __restrict__ o2,
                                   const float* __restrict__ w3, __half* __restrict__ o3)
{
    const int n0 = WQKV_N / 4, n1 = WO_N / 4, n2 = W1_N / 4, n3 = W2_N / 4;
    const int total = n0 + n1 + n2 + n3;
    for (int i = blockIdx.x * blockDim.x + threadIdx.x; i < total; i += gridDim.x * blockDim.x) {
        const float* in; __half* out; int j = i;
        if (j < n0)                { in = w0; out = o0; }
        else if ((j -= n0) < n1)   { in = w1; out = o1; }
        else if ((j -= n1) < n2)   { in = w2; out = o2; }
        else { j -= n2;              in = w3; out = o3; }
        float4 v = ((const float4*)in)[j];
        ((__half2*)out)[2 * j]     = __floats2half2_rn(v.x, v.y);
        ((__half2*)out)[2 * j + 1] = __floats2half2_rn(v.z, v.w);
    }
}

// ---------------- embedding (writes x and fp16 xh) ----------------
__global__ void embed_kernel(
    const float* __restrict__ q, const float* __restrict__ p,
    const float* __restrict__ qm, const float* __restrict__ pm,
    const float* __restrict__ z,
    const float* __restrict__ Wq, const float* __restrict__ bq,
    const float* __restrict__ Wp, const float* __restrict__ bp,
    const float* __restrict__ Wz, const float* __restrict__ bz,
    const float* __restrict__ pos, const float* __restrict__ noise,
    float* __restrict__ x, __half* __restrict__ xh)
{
    int s = blockIdx.x;
    if (s >= SEQ) {
        for (int h = threadIdx.x; h < H; h += blockDim.x) {
            x[(size_t)s * H + h] = 0.0f;
            xh[(size_t)s * H + h] = __float2half(0.0f);
        }
        return;
    }
    __shared__ float vin[128];
    const float *W, *b, *src;
    int dim;
    float mask;
    if (s == 0)          { src = z;                   dim = 128; W = Wz; b = bz; mask = 1.0f; }
    else if (s <= 2048)  { src = q + (s - 1) * 64;    dim = 64;  W = Wq; b = bq; mask = qm[s - 1]; }
    else                 { src = p + (s - 2049) * 64; dim = 64;  W = Wp; b = bp; mask = pm[s - 2049]; }

    for (int i = threadIdx.x; i < dim; i += blockDim.x) vin[i] = src[i];
    __syncthreads();

    int idx = (int)(mask * 100.0f);
    const float* ne = noise + (size_t)idx * H;

    for (int h = threadIdx.x; h < H; h += blockDim.x) {
        const float* w = W + (size_t)h * dim;
        float acc = b[h];
#pragma unroll 8
        for (int d = 0; d < dim; d++) acc = fmaf(vin[d], w[d], acc);
        float v = acc + pos[(size_t)s * H + h] + ne[h];
        x[(size_t)s * H + h] = v;
        xh[(size_t)s * H + h] = __float2half_rn(v);
    }
}

// ---------------- fp16 GEMM: raw mma m16n8k16 + ldmatrix, 1 sync/iter ----------------
#define AST 72
#define GTILE (128 * AST)
#define GEMM_SMEM (4 * GTILE * 2)

template <bool RELU, bool HOUT>
__global__ __launch_bounds__(256, 2)
void tgemm(const __half* __restrict__ A, const __half* __restrict__ W,
           const float* __restrict__ bias, void* __restrict__ Cv,
           int M, int N, int K)
{
    extern __shared__ __half smg[];
    __half* AsBuf[2] = { smg,         smg + 2 * GTILE };
    __half* BsBuf[2] = { smg + GTILE, smg + 3 * GTILE };

    const int t    = threadIdx.x;
    const int lane = t & 31;
    const int w    = t >> 5;
    const int bm = blockIdx.y * 128, bn = blockIdx.x * 128;
    const int wm = w >> 2, wn = w & 3;
    const int quad = lane >> 2, tig = lane & 3;

    const int a_row  = (lane & 7) + ((lane >> 3) & 1) * 8;
    const int a_koff = ((lane >> 4) & 1) * 8;
    const int b_row  = (lane & 7) + ((lane & 16) >> 1);
    const int b_koff = ((lane >> 3) & 1) * 8;

    const __half* Ab = A + (size_t)bm * K;
    const __half* Wb = W + (size_t)bn * K;

    float c[4][4][4];
#pragma unroll
    for (int mi = 0; mi < 4; mi++)
#pragma unroll
        for (int ni = 0; ni < 4; ni++)
#pragma unroll
            for (int e = 0; e < 4; e++) c[mi][ni][e] = 0.f;

    const int kt = K / 64;

    auto stage = [&](int buf, int k0) {
#pragma unroll
        for (int v = 0; v < 4; v++) {
            int linear = t + v * 256;
            int row = linear >> 3;
            int off = (linear & 7) * 8;
            __pipeline_memcpy_async(&AsBuf[buf][row * AST + off],
                                    Ab + (size_t)row * K + k0 + off, 16);
            __pipeline_memcpy_async(&BsBuf[buf][row * AST + off],
                                    Wb + (size_t)row * K + k0 + off, 16);
        }
        __pipeline_commit();
    };

    stage(0, 0);
    for (int it = 0; it < kt; it++) {
        __pipeline_wait_prior(0);
        __syncthreads();
        // stage next tile AFTER the sync: its buffer's last readers (iter it-1)
        // are provably done; cp.async overlaps this tile's mma work.
        if (it + 1 < kt) stage((it + 1) & 1, (it + 1) * 64);

        const __half* Ap = AsBuf[it & 1];
        const __half* Bp = BsBuf[it & 1];
        uint32_t aBase = (uint32_t)__cvta_generic_to_shared(
            Ap + (wm * 64 + a_row) * AST + a_koff);
        uint32_t bBase = (uint32_t)__cvta_generic_to_shared(
            Bp + (wn * 32 + b_row) * AST + b_koff);

#pragma unroll
        for (int kk = 0; kk < 64; kk += 16) {
            uint32_t a[4][4];
#pragma unroll
            for (int mi = 0; mi < 4; mi++)
                ldsm4(a[mi][0], a[mi][1], a[mi][2], a[mi][3],
                      aBase + (uint32_t)((mi * 16 * AST + kk) * 2));
            uint32_t bf[8];
            ldsm4(bf[0], bf[1], bf[2], bf[3], bBase + (uint32_t)(kk * 2));
            ldsm4(bf[4], bf[5], bf[6], bf[7], bBase + (uint32_t)((16 * AST + kk) * 2));
#pragma unroll
            for (int mi = 0; mi < 4; mi++)
#pragma unroll
                for (int ni = 0; ni < 4; ni++)
                    mma_f16(c[mi][ni][0], c[mi][ni][1], c[mi][ni][2], c[mi][ni][3],
                            a[mi][0], a[mi][1], a[mi][2], a[mi][3],
                            bf[2 * ni], bf[2 * ni + 1]);
        }
    }

#pragma unroll
    for (int mi = 0; mi < 4; mi++) {
        int row0 = bm + wm * 64 + mi * 16 + quad;
#pragma unroll
        for (int ni = 0; ni < 4; ni++) {
            int col = bn + wn * 32 + ni * 8 + tig * 2;
            float2 bb = *(const float2*)&bias[col];
            float v00 = c[mi][ni][0] + bb.x, v01 = c[mi][ni][1] + bb.y;
            float v10 = c[mi][ni][2] + bb.x, v11 = c[mi][ni][3] + bb.y;
            if (RELU) {
                v00 = fmaxf(v00, 0.f); v01 = fmaxf(v01, 0.f);
                v10 = fmaxf(v10, 0.f); v11 = fmaxf(v11, 0.f);
            }
            if (HOUT) {
                __half* C = (__half*)Cv;
                *(__half2*)&C[(size_t)row0 * N + col]       = __floats2half2_rn(v00, v01);
                *(__half2*)&C[(size_t)(row0 + 8) * N + col] = __floats2half2_rn(v10, v11);
            } else {
                float* C = (float*)Cv;
                *(float2*)&C[(size_t)row0 * N + col]       = make_float2(v00, v01);
                *(float2*)&C[(size_t)(row0 + 8) * N + col] = make_float2(v10, v11);
            }
        }
    }
}

// ---------------- flash attention, fp16 mma + full ldmatrix, 1 sync/iter ----------------
#define KST 72
#define VST 72
#define PST 72
#define KBUF (64 * KST)
#define VBUF (64 * VST)
#define ATTN_SMEM ((2 * KBUF + 2 * VBUF + 8 * 16 * PST) * 2)

__global__ __launch_bounds__(256, 2)
void attn_kernel(const __half* __restrict__ qkv, __half* __restrict__ out)
{
    extern __shared__ __half sma[];
    __half* Ksm[2] = { sma, sma + KBUF };
    __half* Vsm[2] = { sma + 2 * KBUF, sma + 2 * KBUF + VBUF };
    __half* Pall   = sma + 2 * KBUF + 2 * VBUF;

    const int t    = threadIdx.x;
    const int lane = t & 31;
    const int w    = t >> 5;
    const int quad = lane >> 2;
    const int tig  = lane & 3;
    const int head = blockIdx.y;
    const int q0   = blockIdx.x * 128;
    const int coff = head * 64;

    __half* Pme = Pall + w * 16 * PST;

    const int b_row  = (lane & 7) + ((lane & 16) >> 1);
    const int b_koff = ((lane >> 3) & 1) * 8;
    const int a_row  = (lane & 7) + ((lane >> 3) & 1) * 8;
    const int a_koff = ((lane >> 4) & 1) * 8;
    const int v_row  = (lane & 7) + ((lane >> 3) & 1) * 8;
    const int v_coff = ((lane >> 4) & 1) * 8;

    auto stage = [&](int k0, int buf) {
#pragma unroll
        for (int v = 0; v < 2; v++) {
            int linear = t + v * 256;
            int row = linear >> 3;
            int off = (linear & 7) * 8;
            __pipeline_memcpy_async(&Ksm[buf][row * KST + off],
                                    &qkv[(size_t)(k0 + row) * H3 + H + coff + off], 16);
            __pipeline_memcpy_async(&Vsm[buf][row * VST + off],
                                    &qkv[(size_t)(k0 + row) * H3 + 2 * H + coff + off], 16);
        }
        __pipeline_commit();
    };

    uint32_t Qa[4][4];
    {
        const __half* qb = qkv + (size_t)(q0 + w * 16) * H3 + coff;
#pragma unroll
        for (int c = 0; c < 4; c++) {
#pragma unroll
            for (int e = 0; e < 4; e++) {
                int r   = quad + (e & 1) * 8;
                int col = c * 16 + (e >> 1) * 8 + tig * 2;
                float2 v = __half22float2(*(const __half2*)&qb[(size_t)r * H3 + col]);
                Qa[c][e] = pack_h2(v.x * 0.125f, v.y * 0.125f);
            }
        }
    }

    float o[8][4];
#pragma unroll
    for (int nb = 0; nb < 8; nb++)
#pragma unroll
        for (int e = 0; e < 4; e++) o[nb][e] = 0.f;
    float m0 = -1e30f, m1 = -1e30f, l0 = 0.f, l1 = 0.f;

    const int NITER = (SEQ + 63) / 64;   // 65

    stage(0, 0);
    for (int it = 0; it < NITER; it++) {
        const int k0 = it * 64;
        __pipeline_wait_prior(0);
        __syncthreads();
        // stage next AFTER sync: buffer (it+1)&1's last readers (iter it-1) done.
        if (it + 1 < NITER) stage((it + 1) * 64, (it + 1) & 1);

        const __half* Kb = Ksm[it & 1];
        const __half* Vb = Vsm[it & 1];

        uint32_t kBase = (uint32_t)__cvta_generic_to_shared(Kb + b_row * KST + b_koff);
        uint32_t vBase = (uint32_t)__cvta_generic_to_shared(Vb + v_row * VST + v_coff);
        uint32_t pBase = (uint32_t)__cvta_generic_to_shared(Pme + a_row * PST + a_koff);

        float s[8][4];
#pragma unroll
        for (int nb = 0; nb < 8; nb++)
            s[nb][0] = s[nb][1] = s[nb][2] = s[nb][3] = 0.f;
#pragma unroll
        for (int jn = 0; jn < 4; jn++) {
#pragma unroll
            for (int c = 0; c < 4; c++) {
                uint32_t bf[4];
                ldsm4(bf[0], bf[1], bf[2], bf[3],
                      kBase + (uint32_t)((jn * 16 * KST + c * 16) * 2));
                mma_f16(s[2*jn][0], s[2*jn][1], s[2*jn][2], s[2*jn][3],
                        Qa[c][0], Qa[c][1], Qa[c][2], Qa[c][3], bf[0], bf[1]);
                mma_f16(s[2*jn+1][0], s[2*jn+1][1], s[2*jn+1][2], s[2*jn+1][3],
                        Qa[c][0], Qa[c][1], Qa[c][2], Qa[c][3], bf[2], bf[3]);
            }
        }

        if (k0 + 64 > SEQ) {
#pragma unroll
            for (int jb = 0; jb < 8; jb++) {
                int col0 = k0 + jb * 8 + 2 * tig;
                if (col0 >= SEQ)     { s[jb][0] = -1e30f; s[jb][2] = -1e30f; }
                if (col0 + 1 >= SEQ) { s[jb][1] = -1e30f; s[jb][3] = -1e30f; }
            }
        }

        float mx0 = -1e30f, mx1 = -1e30f;
#pragma unroll
        for (int jb = 0; jb < 8; jb++) {
            mx0 = fmaxf(mx0, fmaxf(s[jb][0], s[jb][1]));
            mx1 = fmaxf(mx1, fmaxf(s[jb][2], s[jb][3]));
        }
        mx0 = fmaxf(mx0, __shfl_xor_sync(0xffffffffu, mx0, 1));
        mx0 = fmaxf(mx0, __shfl_xor_sync(0xffffffffu, mx0, 2));
        mx1 = fmaxf(mx1, __shfl_xor_sync(0xffffffffu, mx1, 1));
        mx1 = fmaxf(mx1, __shfl_xor_sync(0xffffffffu, mx1, 2));

        float mn0 = fmaxf(m0, mx0), mn1 = fmaxf(m1, mx1);
        float corr0 = __expf(m0 - mn0), corr1 = __expf(m1 - mn1);
        m0 = mn0; m1 = mn1;

        float sum0 = 0.f, sum1 = 0.f;
#pragma unroll
        for (int jb = 0; jb < 8; jb++) {
            float p0 = __expf(s[jb][0] - mn0);
            float p1 = __expf(s[jb][1] - mn0);
            float p2 = __expf(s[jb][2] - mn1);
            float p3 = __expf(s[jb][3] - mn1);
            sum0 += p0 + p1;
            sum1 += p2 + p3;
            *(__half2*)&Pme[quad * PST + jb * 8 + tig * 2]       = __floats2half2_rn(p0, p1);
            *(__half2*)&Pme[(quad + 8) * PST + jb * 8 + tig * 2] = __floats2half2_rn(p2, p3);
        }
        sum0 += __shfl_xor_sync(0xffffffffu, sum0, 1);
        sum0 += __shfl_xor_sync(0xffffffffu, sum0, 2);
        sum1 += __shfl_xor_sync(0xffffffffu, sum1, 1);
        sum1 += __shfl_xor_sync(0xffffffffu, sum1, 2);
        l0 = l0 * corr0 + sum0;
        l1 = l1 * corr1 + sum1;

#pragma unroll
        for (int nb = 0; nb < 8; nb++) {
            o[nb][0] *= corr0; o[nb][1] *= corr0;
            o[nb][2] *= corr1; o[nb][3] *= corr1;
        }

        __syncwarp();

#pragma unroll
        for (int kc = 0; kc < 4; kc++) {
            uint32_t pf[4];
            ldsm4(pf[0], pf[1], pf[2], pf[3], pBase + (uint32_t)(kc * 16 * 2));
#pragma unroll
            for (int jn = 0; jn < 4; jn++) {
                uint32_t bf[4];
                ldsm4t(bf[0], bf[1], bf[2], bf[3],
                       vBase + (uint32_t)((kc * 16 * VST + jn * 16) * 2));
                mma_f16(o[2*jn][0], o[2*jn][1], o[2*jn][2], o[2*jn][3],
                        pf[0], pf[1], pf[2], pf[3], bf[0], bf[1]);
                mma_f16(o[2*jn+1][0], o[2*jn+1][1], o[2*jn+1][2], o[2*jn+1][3],
                        pf[0], pf[1], pf[2], pf[3], bf[2], bf[3]);
            }
        }
    }

    float inv0 = 1.0f / l0, inv1 = 1.0f / l1;
    __half* ob0 = out + (size_t)(q0 + w * 16 + quad) * H + coff;
    __half* ob1 = out + (size_t)(q0 + w * 16 + quad + 8) * H + coff;
#pragma unroll
    for (int nb = 0; nb < 8; nb++) {
        *(__half2*)&ob0[nb * 8 + 2 * tig] = __floats2half2_rn(o[nb][0] * inv0, o[nb][1] * inv0);
        *(__half2*)&ob1[nb * 8 + 2 * tig] = __floats2half2_rn(o[nb][2] * inv1, o[nb][3] * inv1);
    }
}

// ---------------- fused add + LayerNorm (writes x and fp16 xh) ----------------
__global__ __launch_bounds__(256)
void addln_kernel(const float* __restrict__ a, const float* __restrict__ b,
                  const float* __restrict__ w, const float* __restrict__ wb,
                  float* __restrict__ outx, __half* __restrict__ outxh)
{
    int s = blockIdx.x;
    int t = threadIdx.x;
    const float4 av = ((const float4*)(a + (size_t)s * H))[t];
    const float4 bv = ((const float4*)(b + (size_t)s * H))[t];
    float v[4] = {av.x + bv.x, av.y + bv.y, av.z + bv.z, av.w + bv.w};

    float s1 = v[0] + v[1] + v[2] + v[3];
    float s2 = v[0]*v[0] + v[1]*v[1] + v[2]*v[2] + v[3]*v[3];
#pragma unroll
    for (int off = 16; off > 0; off >>= 1) {
        s1 += __shfl_xor_sync(0xffffffffu, s1, off);
        s2 += __shfl_xor_sync(0xffffffffu, s2, off);
    }
    __shared__ float r1[8], r2[8];
    int wid = t >> 5, lane = t & 31;
    if (lane == 0) { r1[wid] = s1; r2[wid] = s2; }
    __syncthreads();
    if (t == 0) {
        float a0 = 0.f, b0 = 0.f;
#pragma unroll
        for (int i = 0; i < 8; i++) { a0 += r1[i]; b0 += r2[i]; }
        r1[0] = a0; r2[0] = b0;
    }
    __syncthreads();
    float mean = r1[0] * (1.0f / H);
    float var  = r2[0] * (1.0f / H) - mean * mean;
    float rstd = rsqrtf(var + 1e-5f);

    const float4 wv  = ((const float4*)w)[t];
    const float4 wbv = ((const float4*)wb)[t];
    float4 ov;
    ov.x = (v[0] - mean) * rstd * wv.x + wbv.x;
    ov.y = (v[1] - mean) * rstd * wv.y + wbv.y;
    ov.z = (v[2] - mean) * rstd * wv.z + wbv.z;
    ov.w = (v[3] - mean) * rstd * wv.w + wbv.w;
    ((float4*)(outx + (size_t)s * H))[t] = ov;

    ((__half2*)(outxh + (size_t)s * H))[2 * t]     = __floats2half2_rn(ov.x, ov.y);
    ((__half2*)(outxh + (size_t)s * H))[2 * t + 1] = __floats2half2_rn(ov.z, ov.w);
}

// ---------------- final projection ----------------
__global__ void final_kernel(const float* __restrict__ x, const float* __restrict__ Wout,
                             const float* __restrict__ bout, float* __restrict__ out)
{
    int o = threadIdx.x;
    if (o >= OUTD) return;
    const float* w = Wout + (size_t)o * H;
    float acc = bout[o];
#pragma unroll 8
    for (int d = 0; d < H; d++) acc = fmaf(x[d], w[d], acc);
    out[o] = acc;
}

// ---------------- launch ----------------
extern "C" void kernel_launch(void* const* d_in, const int* in_sizes, int n_in,
                              void* d_out, int out_size)
{
    (void)in_sizes; (void)n_in; (void)out_size;
    const float* q     = (const float*)d_in[0];
    const float* p     = (const float*)d_in[1];
    const float* qm    = (const float*)d_in[2];
    const float* pm    = (const float*)d_in[3];
    const float* z     = (const float*)d_in[4];
    const float* Wq    = (const float*)d_in[5];
    const float* bq    = (const float*)d_in[6];
    const float* Wp    = (const float*)d_in[7];
    const float* bp    = (const float*)d_in[8];
    const float* Wz    = (const float*)d_in[9];
    const float* bz    = (const float*)d_in[10];
    const float* pos   = (const float*)d_in[11];
    const float* noise = (const float*)d_in[12];
    const float* Wqkv  = (const float*)d_in[13];
    const float* bqkv  = (const float*)d_in[14];
    const float* Wo    = (const float*)d_in[15];
    const float* bo    = (const float*)d_in[16];
    const float* ln1w  = (const float*)d_in[17];
    const float* ln1b  = (const float*)d_in[18];
    const float* W1    = (const float*)d_in[19];
    const float* b1    = (const float*)d_in[20];
    const float* W2    = (const float*)d_in[21];
    const float* b2    = (const float*)d_in[22];
    const float* ln2w  = (const float*)d_in[23];
    const float* ln2b  = (const float*)d_in[24];
    const float* Wout  = (const float*)d_in[25];
    const float* bout  = (const float*)d_in[26];

    float *x, *tmp;
    __half *xh, *qkvb, *attnb, *ff, *wqkv_h, *wo_h, *w1_h, *w2_h;
    cudaGetSymbolAddress((void**)&x,      g_x);
    cudaGetSymbolAddress((void**)&xh,     g_xh);
    cudaGetSymbolAddress((void**)&qkvb,   g_qkv);
    cudaGetSymbolAddress((void**)&attnb,  g_attn);
    cudaGetSymbolAddress((void**)&tmp,    g_tmp);
    cudaGetSymbolAddress((void**)&ff,     g_ff);
    cudaGetSymbolAddress((void**)&wqkv_h, g_wqkv_h);
    cudaGetSymbolAddress((void**)&wo_h,   g_wo_h);
    cudaGetSymbolAddress((void**)&w1_h,   g_w1_h);
    cudaGetSymbolAddress((void**)&w2_h,   g_w2_h);

    cudaFuncSetAttribute((const void*)tgemm<false,true>,  cudaFuncAttributeMaxDynamicSharedMemorySize, GEMM_SMEM);
    cudaFuncSetAttribute((const void*)tgemm<false,false>, cudaFuncAttributeMaxDynamicSharedMemorySize, GEMM_SMEM);
    cudaFuncSetAttribute((const void*)tgemm<true,true>,   cudaFuncAttributeMaxDynamicSharedMemorySize, GEMM_SMEM);
    cudaFuncSetAttribute((const void*)attn_kernel,        cudaFuncAttributeMaxDynamicSharedMemorySize, ATTN_SMEM);

    to_half_all_kernel<<<4096, 256>>>(Wqkv, wqkv_h, Wo, wo_h, W1, w1_h, W2, w2_h);

    embed_kernel<<<SEQP, 256>>>(q, p, qm, pm, z, Wq, bq, Wp, bp, Wz, bz, pos, noise, x, xh);

    const int MB = SEQP / 128;   // 33
    for (int i = 0; i < LAYERS; i++) {
        tgemm<false,true><<<dim3(H3 / 128, MB), 256, GEMM_SMEM>>>(
            xh, wqkv_h + (size_t)i * H3 * H, bqkv + (size_t)i * H3, qkvb, SEQP, H3, H);
        attn_kernel<<<dim3(SEQP / 128, NH), 256, ATTN_SMEM>>>(qkvb, attnb);
        tgemm<false,false><<<dim3(H / 128, MB), 256, GEMM_SMEM>>>(
            attnb, wo_h + (size_t)i * H * H, bo + (size_t)i * H, tmp, SEQP, H, H);
        addln_kernel<<<SEQP, 256>>>(x, tmp, ln1w + (size_t)i * H, ln1b + (size_t)i * H, x, xh);
        tgemm<true,true><<<dim3(FFD / 128, MB), 256, GEMM_SMEM>>>(
            xh, w1_h + (size_t)i * FFD * H, b1 + (size_t)i * FFD, ff, SEQP, FFD, H);
        tgemm<false,false><<<dim3(H / 128, MB), 256, GEMM_SMEM>>>(
            ff, w2_h + (size_t)i * H * FFD, b2 + (size_t)i * H, tmp, SEQP, H, FFD);
        addln_kernel<<<SEQP, 256>>>(x, tmp, ln2w + (size_t)i * H, ln2b + (size_t)i * H, x, xh);
    }

    final_kernel<<<1, 128>>>(x, Wout, bout, (float*)d_out);
}

// round 10
// speedup vs baseline: 7.0130x; 1.0332x over previous
#include <cuda_runtime.h>
#include <cuda_pipeline.h>
#include <cuda_fp16.h>
#include <math.h>
#include <stdint.h>

#define SEQ  4097
#define SEQP 4224          // 33 * 128, padded
#define H    1024
#define NH   16
#define HD   64
#define H3   3072
#define FFD  4096
#define LAYERS 6
#define OUTD 128

#define WQKV_N (LAYERS * H3 * H)
#define WO_N   (LAYERS * H * H)
#define W1_N   (LAYERS * FFD * H)
#define W2_N   (LAYERS * H * FFD)

// ---------------- scratch (device globals; no allocations) ----------------
__device__ float  g_x[SEQP * H];
__device__ __half g_xh[SEQP * H];
__device__ __half g_qkv[SEQP * H3];
__device__ __half g_attn[SEQP * H];
__device__ float  g_tmp[SEQP * H];
__device__ __half g_ff[SEQP * FFD];
__device__ __half g_wqkv_h[WQKV_N];
__device__ __half g_wo_h[WO_N];
__device__ __half g_w1_h[W1_N];
__device__ __half g_w2_h[W2_N];

__device__ __forceinline__ void mma_f16(float& d0, float& d1, float& d2, float& d3,
                                        uint32_t a0, uint32_t a1, uint32_t a2, uint32_t a3,
                                        uint32_t b0, uint32_t b1)
{
    asm volatile("mma.sync.aligned.m16n8k16.row.col.f32.f16.f16.f32 "
                 "{%0,%1,%2,%3},{%4,%5,%6,%7},{%8,%9},{%0,%1,%2,%3};"
                 : "+f"(d0), "+f"(d1), "+f"(d2), "+f"(d3)
                 : "r"(a0), "r"(a1), "r"(a2), "r"(a3), "r"(b0), "r"(b1));
}

__device__ __forceinline__ void ldsm4(uint32_t& r0, uint32_t& r1, uint32_t& r2, uint32_t& r3,
                                      uint32_t addr)
{
    asm volatile("ldmatrix.sync.aligned.m8n8.x4.shared.b16 {%0,%1,%2,%3}, [%4];"
                 : "=r"(r0), "=r"(r1), "=r"(r2), "=r"(r3) : "r"(addr));
}

__device__ __forceinline__ void ldsm4t(uint32_t& r0, uint32_t& r1, uint32_t& r2, uint32_t& r3,
                                       uint32_t addr)
{
    asm volatile("ldmatrix.sync.aligned.m8n8.x4.trans.shared.b16 {%0,%1,%2,%3}, [%4];"
                 : "=r"(r0), "=r"(r1), "=r"(r2), "=r"(r3) : "r"(addr));
}

__device__ __forceinline__ uint32_t pack_h2(float a, float b) {
    __half2 h = __floats2half2_rn(a, b);
    return *(uint32_t*)&h;
}

// ---------------- fp16 conversion: all four weight tensors, one launch ----------------
__global__ void to_half_all_kernel(const float* __restrict__ w0, __half* __restrict__ o0,
                                   const float* __restrict__ w1, __half* __restrict__ o1,
                                   const float* __restrict__ w2, __half* __restrict__ o2,
                                   const float* __restrict__ w3, __half* __restrict__ o3)
{
    const int n0 = WQKV_N / 4, n1 = WO_N / 4, n2 = W1_N / 4, n3 = W2_N / 4;
    const int total = n0 + n1 + n2 + n3;
    for (int i = blockIdx.x * blockDim.x + threadIdx.x; i < total; i += gridDim.x * blockDim.x) {
        const float* in; __half* out; int j = i;
        if (j < n0)                { in = w0; out = o0; }
        else if ((j -= n0) < n1)   { in = w1; out = o1; }
        else if ((j -= n1) < n2)   { in = w2; out = o2; }
        else { j -= n2;              in = w3; out = o3; }
        float4 v = ((const float4*)in)[j];
        ((__half2*)out)[2 * j]     = __floats2half2_rn(v.x, v.y);
        ((__half2*)out)[2 * j + 1] = __floats2half2_rn(v.z, v.w);
    }
}

// ---------------- embedding (writes x and fp16 xh) ----------------
__global__ void embed_kernel(
    const float* __restrict__ q, const float* __restrict__ p,
    const float* __restrict__ qm, const float* __restrict__ pm,
    const float* __restrict__ z,
    const float* __restrict__ Wq, const float* __restrict__ bq,
    const float* __restrict__ Wp, const float* __restrict__ bp,
    const float* __restrict__ Wz, const float* __restrict__ bz,
    const float* __restrict__ pos, const float* __restrict__ noise,
    float* __restrict__ x, __half* __restrict__ xh)
{
    int s = blockIdx.x;
    if (s >= SEQ) {
        for (int h = threadIdx.x; h < H; h += blockDim.x) {
            x[(size_t)s * H + h] = 0.0f;
            xh[(size_t)s * H + h] = __float2half(0.0f);
        }
        return;
    }
    __shared__ float vin[128];
    const float *W, *b, *src;
    int dim;
    float mask;
    if (s == 0)          { src = z;                   dim = 128; W = Wz; b = bz; mask = 1.0f; }
    else if (s <= 2048)  { src = q + (s - 1) * 64;    dim = 64;  W = Wq; b = bq; mask = qm[s - 1]; }
    else                 { src = p + (s - 2049) * 64; dim = 64;  W = Wp; b = bp; mask = pm[s - 2049]; }

    for (int i = threadIdx.x; i < dim; i += blockDim.x) vin[i] = src[i];
    __syncthreads();

    int idx = (int)(mask * 100.0f);
    const float* ne = noise + (size_t)idx * H;

    for (int h = threadIdx.x; h < H; h += blockDim.x) {
        const float* w = W + (size_t)h * dim;
        float acc = b[h];
#pragma unroll 8
        for (int d = 0; d < dim; d++) acc = fmaf(vin[d], w[d], acc);
        float v = acc + pos[(size_t)s * H + h] + ne[h];
        x[(size_t)s * H + h] = v;
        xh[(size_t)s * H + h] = __float2half_rn(v);
    }
}

// ---------------- fp16 GEMM: raw mma m16n8k16 + ldmatrix, 1 sync/iter ----------------
#define AST 72
#define GTILE (128 * AST)
#define GEMM_SMEM (4 * GTILE * 2)

template <bool RELU, bool HOUT>
__global__ __launch_bounds__(256, 2)
void tgemm(const __half* __restrict__ A, const __half* __restrict__ W,
           const float* __restrict__ bias, void* __restrict__ Cv,
           int M, int N, int K)
{
    extern __shared__ __half smg[];
    __half* AsBuf[2] = { smg,         smg + 2 * GTILE };
    __half* BsBuf[2] = { smg + GTILE, smg + 3 * GTILE };

    const int t    = threadIdx.x;
    const int lane = t & 31;
    const int w    = t >> 5;
    const int bm = blockIdx.y * 128, bn = blockIdx.x * 128;
    const int wm = w >> 2, wn = w & 3;
    const int quad = lane >> 2, tig = lane & 3;

    const int a_row  = (lane & 7) + ((lane >> 3) & 1) * 8;
    const int a_koff = ((lane >> 4) & 1) * 8;
    const int b_row  = (lane & 7) + ((lane & 16) >> 1);
    const int b_koff = ((lane >> 3) & 1) * 8;

    const __half* Ab = A + (size_t)bm * K;
    const __half* Wb = W + (size_t)bn * K;

    float c[4][4][4];
#pragma unroll
    for (int mi = 0; mi < 4; mi++)
#pragma unroll
        for (int ni = 0; ni < 4; ni++)
#pragma unroll
            for (int e = 0; e < 4; e++) c[mi][ni][e] = 0.f;

    const int kt = K / 64;

    auto stage = [&](int buf, int k0) {
#pragma unroll
        for (int v = 0; v < 4; v++) {
            int linear = t + v * 256;
            int row = linear >> 3;
            int off = (linear & 7) * 8;
            __pipeline_memcpy_async(&AsBuf[buf][row * AST + off],
                                    Ab + (size_t)row * K + k0 + off, 16);
            __pipeline_memcpy_async(&BsBuf[buf][row * AST + off],
                                    Wb + (size_t)row * K + k0 + off, 16);
        }
        __pipeline_commit();
    };

    stage(0, 0);
    for (int it = 0; it < kt; it++) {
        __pipeline_wait_prior(0);
        __syncthreads();
        if (it + 1 < kt) stage((it + 1) & 1, (it + 1) * 64);

        const __half* Ap = AsBuf[it & 1];
        const __half* Bp = BsBuf[it & 1];
        uint32_t aBase = (uint32_t)__cvta_generic_to_shared(
            Ap + (wm * 64 + a_row) * AST + a_koff);
        uint32_t bBase = (uint32_t)__cvta_generic_to_shared(
            Bp + (wn * 32 + b_row) * AST + b_koff);

#pragma unroll
        for (int kk = 0; kk < 64; kk += 16) {
            uint32_t a[4][4];
#pragma unroll
            for (int mi = 0; mi < 4; mi++)
                ldsm4(a[mi][0], a[mi][1], a[mi][2], a[mi][3],
                      aBase + (uint32_t)((mi * 16 * AST + kk) * 2));
            uint32_t bf[8];
            ldsm4(bf[0], bf[1], bf[2], bf[3], bBase + (uint32_t)(kk * 2));
            ldsm4(bf[4], bf[5], bf[6], bf[7], bBase + (uint32_t)((16 * AST + kk) * 2));
#pragma unroll
            for (int mi = 0; mi < 4; mi++)
#pragma unroll
                for (int ni = 0; ni < 4; ni++)
                    mma_f16(c[mi][ni][0], c[mi][ni][1], c[mi][ni][2], c[mi][ni][3],
                            a[mi][0], a[mi][1], a[mi][2], a[mi][3],
                            bf[2 * ni], bf[2 * ni + 1]);
        }
    }

#pragma unroll
    for (int mi = 0; mi < 4; mi++) {
        int row0 = bm + wm * 64 + mi * 16 + quad;
#pragma unroll
        for (int ni = 0; ni < 4; ni++) {
            int col = bn + wn * 32 + ni * 8 + tig * 2;
            float2 bb = *(const float2*)&bias[col];
            float v00 = c[mi][ni][0] + bb.x, v01 = c[mi][ni][1] + bb.y;
            float v10 = c[mi][ni][2] + bb.x, v11 = c[mi][ni][3] + bb.y;
            if (RELU) {
                v00 = fmaxf(v00, 0.f); v01 = fmaxf(v01, 0.f);
                v10 = fmaxf(v10, 0.f); v11 = fmaxf(v11, 0.f);
            }
            if (HOUT) {
                __half* C = (__half*)Cv;
                *(__half2*)&C[(size_t)row0 * N + col]       = __floats2half2_rn(v00, v01);
                *(__half2*)&C[(size_t)(row0 + 8) * N + col] = __floats2half2_rn(v10, v11);
            } else {
                float* C = (float*)Cv;
                *(float2*)&C[(size_t)row0 * N + col]       = make_float2(v00, v01);
                *(float2*)&C[(size_t)(row0 + 8) * N + col] = make_float2(v10, v11);
            }
        }
    }
}

// ---------------- flash attention: fp16 mma, P kept in registers (FA2 reuse) ----------------
#define KST 72
#define VST 72
#define KBUF (64 * KST)
#define VBUF (64 * VST)
#define ATTN_SMEM ((2 * KBUF + 2 * VBUF) * 2)   // 36864 B

__global__ __launch_bounds__(256, 2)
void attn_kernel(const __half* __restrict__ qkv, __half* __restrict__ out)
{
    extern __shared__ __half sma[];
    __half* Ksm[2] = { sma, sma + KBUF };
    __half* Vsm[2] = { sma + 2 * KBUF, sma + 2 * KBUF + VBUF };

    const int t    = threadIdx.x;
    const int lane = t & 31;
    const int w    = t >> 5;
    const int quad = lane >> 2;
    const int tig  = lane & 3;
    const int head = blockIdx.y;
    const int q0   = blockIdx.x * 128;
    const int coff = head * 64;

    const int b_row  = (lane & 7) + ((lane & 16) >> 1);
    const int b_koff = ((lane >> 3) & 1) * 8;
    const int v_row  = (lane & 7) + ((lane >> 3) & 1) * 8;
    const int v_coff = ((lane >> 4) & 1) * 8;

    auto stage = [&](int k0, int buf) {
#pragma unroll
        for (int v = 0; v < 2; v++) {
            int linear = t + v * 256;
            int row = linear >> 3;
            int off = (linear & 7) * 8;
            __pipeline_memcpy_async(&Ksm[buf][row * KST + off],
                                    &qkv[(size_t)(k0 + row) * H3 + H + coff + off], 16);
            __pipeline_memcpy_async(&Vsm[buf][row * VST + off],
                                    &qkv[(size_t)(k0 + row) * H3 + 2 * H + coff + off], 16);
        }
        __pipeline_commit();
    };

    uint32_t Qa[4][4];
    {
        const __half* qb = qkv + (size_t)(q0 + w * 16) * H3 + coff;
#pragma unroll
        for (int c = 0; c < 4; c++) {
#pragma unroll
            for (int e = 0; e < 4; e++) {
                int r   = quad + (e & 1) * 8;
                int col = c * 16 + (e >> 1) * 8 + tig * 2;
                float2 v = __half22float2(*(const __half2*)&qb[(size_t)r * H3 + col]);
                Qa[c][e] = pack_h2(v.x * 0.125f, v.y * 0.125f);
            }
        }
    }

    float o[8][4];
#pragma unroll
    for (int nb = 0; nb < 8; nb++)
#pragma unroll
        for (int e = 0; e < 4; e++) o[nb][e] = 0.f;
    float m0 = -1e30f, m1 = -1e30f, l0 = 0.f, l1 = 0.f;

    const int NITER = (SEQ + 63) / 64;   // 65

    stage(0, 0);
    for (int it = 0; it < NITER; it++) {
        const int k0 = it * 64;
        __pipeline_wait_prior(0);
        __syncthreads();
        if (it + 1 < NITER) stage((it + 1) * 64, (it + 1) & 1);

        const __half* Kb = Ksm[it & 1];
        const __half* Vb = Vsm[it & 1];

        uint32_t kBase = (uint32_t)__cvta_generic_to_shared(Kb + b_row * KST + b_koff);
        uint32_t vBase = (uint32_t)__cvta_generic_to_shared(Vb + v_row * VST + v_coff);

        // ---- S = Q @ K^T ----
        float s[8][4];
#pragma unroll
        for (int nb = 0; nb < 8; nb++)
            s[nb][0] = s[nb][1] = s[nb][2] = s[nb][3] = 0.f;
#pragma unroll
        for (int jn = 0; jn < 4; jn++) {
#pragma unroll
            for (int c = 0; c < 4; c++) {
                uint32_t bf[4];
                ldsm4(bf[0], bf[1], bf[2], bf[3],
                      kBase + (uint32_t)((jn * 16 * KST + c * 16) * 2));
                mma_f16(s[2*jn][0], s[2*jn][1], s[2*jn][2], s[2*jn][3],
                        Qa[c][0], Qa[c][1], Qa[c][2], Qa[c][3], bf[0], bf[1]);
                mma_f16(s[2*jn+1][0], s[2*jn+1][1], s[2*jn+1][2], s[2*jn+1][3],
                        Qa[c][0], Qa[c][1], Qa[c][2], Qa[c][3], bf[2], bf[3]);
            }
        }

        if (k0 + 64 > SEQ) {
#pragma unroll
            for (int jb = 0; jb < 8; jb++) {
                int col0 = k0 + jb * 8 + 2 * tig;
                if (col0 >= SEQ)     { s[jb][0] = -1e30f; s[jb][2] = -1e30f; }
                if (col0 + 1 >= SEQ) { s[jb][1] = -1e30f; s[jb][3] = -1e30f; }
            }
        }

        // ---- online softmax (P stays in registers) ----
        float mx0 = -1e30f, mx1 = -1e30f;
#pragma unroll
        for (int jb = 0; jb < 8; jb++) {
            mx0 = fmaxf(mx0, fmaxf(s[jb][0], s[jb][1]));
            mx1 = fmaxf(mx1, fmaxf(s[jb][2], s[jb][3]));
        }
        mx0 = fmaxf(mx0, __shfl_xor_sync(0xffffffffu, mx0, 1));
        mx0 = fmaxf(mx0, __shfl_xor_sync(0xffffffffu, mx0, 2));
        mx1 = fmaxf(mx1, __shfl_xor_sync(0xffffffffu, mx1, 1));
        mx1 = fmaxf(mx1, __shfl_xor_sync(0xffffffffu, mx1, 2));

        float mn0 = fmaxf(m0, mx0), mn1 = fmaxf(m1, mx1);
        float corr0 = __expf(m0 - mn0), corr1 = __expf(m1 - mn1);
        m0 = mn0; m1 = mn1;

        float sum0 = 0.f, sum1 = 0.f;
#pragma unroll
        for (int jb = 0; jb < 8; jb++) {
            float p0 = __expf(s[jb][0] - mn0);
            float p1 = __expf(s[jb][1] - mn0);
            float p2 = __expf(s[jb][2] - mn1);
            float p3 = __expf(s[jb][3] - mn1);
            sum0 += p0 + p1;
            sum1 += p2 + p3;
            s[jb][0] = p0; s[jb][1] = p1; s[jb][2] = p2; s[jb][3] = p3;
        }
        sum0 += __shfl_xor_sync(0xffffffffu, sum0, 1);
        sum0 += __shfl_xor_sync(0xffffffffu, sum0, 2);
        sum1 += __shfl_xor_sync(0xffffffffu, sum1, 1);
        sum1 += __shfl_xor_sync(0xffffffffu, sum1, 2);
        l0 = l0 * corr0 + sum0;
        l1 = l1 * corr1 + sum1;

#pragma unroll
        for (int nb = 0; nb < 8; nb++) {
            o[nb][0] *= corr0; o[nb][1] *= corr0;
            o[nb][2] *= corr1; o[nb][3] *= corr1;
        }

        // ---- O += P @ V  (P fragments packed directly from S accumulators;
        //      D-layout of m16n8k16 == A-layout: a0=(q,2t..+1) a1=(q+8) a2=(q,+8) a3=(q+8,+8)) ----
#pragma unroll
        for (int kc = 0; kc < 4; kc++) {
            uint32_t pf0 = pack_h2(s[2*kc][0],   s[2*kc][1]);
            uint32_t pf1 = pack_h2(s[2*kc][2],   s[2*kc][3]);
            uint32_t pf2 = pack_h2(s[2*kc+1][0], s[2*kc+1][1]);
            uint32_t pf3 = pack_h2(s[2*kc+1][2], s[2*kc+1][3]);
#pragma unroll
            for (int jn = 0; jn < 4; jn++) {
                uint32_t bf[4];
                ldsm4t(bf[0], bf[1], bf[2], bf[3],
                       vBase + (uint32_t)((kc * 16 * VST + jn * 16) * 2));
                mma_f16(o[2*jn][0], o[2*jn][1], o[2*jn][2], o[2*jn][3],
                        pf0, pf1, pf2, pf3, bf[0], bf[1]);
                mma_f16(o[2*jn+1][0], o[2*jn+1][1], o[2*jn+1][2], o[2*jn+1][3],
                        pf0, pf1, pf2, pf3, bf[2], bf[3]);
            }
        }
    }

    float inv0 = 1.0f / l0, inv1 = 1.0f / l1;
    __half* ob0 = out + (size_t)(q0 + w * 16 + quad) * H + coff;
    __half* ob1 = out + (size_t)(q0 + w * 16 + quad + 8) * H + coff;
#pragma unroll
    for (int nb = 0; nb < 8; nb++) {
        *(__half2*)&ob0[nb * 8 + 2 * tig] = __floats2half2_rn(o[nb][0] * inv0, o[nb][1] * inv0);
        *(__half2*)&ob1[nb * 8 + 2 * tig] = __floats2half2_rn(o[nb][2] * inv1, o[nb][3] * inv1);
    }
}

// ---------------- fused add + LayerNorm (writes x and fp16 xh) ----------------
__global__ __launch_bounds__(256)
void addln_kernel(const float* __restrict__ a, const float* __restrict__ b,
                  const float* __restrict__ w, const float* __restrict__ wb,
                  float* __restrict__ outx, __half* __restrict__ outxh)
{
    int s = blockIdx.x;
    int t = threadIdx.x;
    const float4 av = ((const float4*)(a + (size_t)s * H))[t];
    const float4 bv = ((const float4*)(b + (size_t)s * H))[t];
    float v[4] = {av.x + bv.x, av.y + bv.y, av.z + bv.z, av.w + bv.w};

    float s1 = v[0] + v[1] + v[2] + v[3];
    float s2 = v[0]*v[0] + v[1]*v[1] + v[2]*v[2] + v[3]*v[3];
#pragma unroll
    for (int off = 16; off > 0; off >>= 1) {
        s1 += __shfl_xor_sync(0xffffffffu, s1, off);
        s2 += __shfl_xor_sync(0xffffffffu, s2, off);
    }
    __shared__ float r1[8], r2[8];
    int wid = t >> 5, lane = t & 31;
    if (lane == 0) { r1[wid] = s1; r2[wid] = s2; }
    __syncthreads();
    if (t == 0) {
        float a0 = 0.f, b0 = 0.f;
#pragma unroll
        for (int i = 0; i < 8; i++) { a0 += r1[i]; b0 += r2[i]; }
        r1[0] = a0; r2[0] = b0;
    }
    __syncthreads();
    float mean = r1[0] * (1.0f / H);
    float var  = r2[0] * (1.0f / H) - mean * mean;
    float rstd = rsqrtf(var + 1e-5f);

    const float4 wv  = ((const float4*)w)[t];
    const float4 wbv = ((const float4*)wb)[t];
    float4 ov;
    ov.x = (v[0] - mean) * rstd * wv.x + wbv.x;
    ov.y = (v[1] - mean) * rstd * wv.y + wbv.y;
    ov.z = (v[2] - mean) * rstd * wv.z + wbv.z;
    ov.w = (v[3] - mean) * rstd * wv.w + wbv.w;
    ((float4*)(outx + (size_t)s * H))[t] = ov;

    ((__half2*)(outxh + (size_t)s * H))[2 * t]     = __floats2half2_rn(ov.x, ov.y);
    ((__half2*)(outxh + (size_t)s * H))[2 * t + 1] = __floats2half2_rn(ov.z, ov.w);
}

// ---------------- final projection ----------------
__global__ void final_kernel(const float* __restrict__ x, const float* __restrict__ Wout,
                             const float* __restrict__ bout, float* __restrict__ out)
{
    int o = threadIdx.x;
    if (o >= OUTD) return;
    const float* w = Wout + (size_t)o * H;
    float acc = bout[o];
#pragma unroll 8
    for (int d = 0; d < H; d++) acc = fmaf(x[d], w[d], acc);
    out[o] = acc;
}

// ---------------- launch ----------------
extern "C" void kernel_launch(void* const* d_in, const int* in_sizes, int n_in,
                              void* d_out, int out_size)
{
    (void)in_sizes; (void)n_in; (void)out_size;
    const float* q     = (const float*)d_in[0];
    const float* p     = (const float*)d_in[1];
    const float* qm    = (const float*)d_in[2];
    const float* pm    = (const float*)d_in[3];
    const float* z     = (const float*)d_in[4];
    const float* Wq    = (const float*)d_in[5];
    const float* bq    = (const float*)d_in[6];
    const float* Wp    = (const float*)d_in[7];
    const float* bp    = (const float*)d_in[8];
    const float* Wz    = (const float*)d_in[9];
    const float* bz    = (const float*)d_in[10];
    const float* pos   = (const float*)d_in[11];
    const float* noise = (const float*)d_in[12];
    const float* Wqkv  = (const float*)d_in[13];
    const float* bqkv  = (const float*)d_in[14];
    const float* Wo    = (const float*)d_in[15];
    const float* bo    = (const float*)d_in[16];
    const float* ln1w  = (const float*)d_in[17];
    const float* ln1b  = (const float*)d_in[18];
    const float* W1    = (const float*)d_in[19];
    const float* b1    = (const float*)d_in[20];
    const float* W2    = (const float*)d_in[21];
    const float* b2    = (const float*)d_in[22];
    const float* ln2w  = (const float*)d_in[23];
    const float* ln2b  = (const float*)d_in[24];
    const float* Wout  = (const float*)d_in[25];
    const float* bout  = (const float*)d_in[26];

    float *x, *tmp;
    __half *xh, *qkvb, *attnb, *ff, *wqkv_h, *wo_h, *w1_h, *w2_h;
    cudaGetSymbolAddress((void**)&x,      g_x);
    cudaGetSymbolAddress((void**)&xh,     g_xh);
    cudaGetSymbolAddress((void**)&qkvb,   g_qkv);
    cudaGetSymbolAddress((void**)&attnb,  g_attn);
    cudaGetSymbolAddress((void**)&tmp,    g_tmp);
    cudaGetSymbolAddress((void**)&ff,     g_ff);
    cudaGetSymbolAddress((void**)&wqkv_h, g_wqkv_h);
    cudaGetSymbolAddress((void**)&wo_h,   g_wo_h);
    cudaGetSymbolAddress((void**)&w1_h,   g_w1_h);
    cudaGetSymbolAddress((void**)&w2_h,   g_w2_h);

    cudaFuncSetAttribute((const void*)tgemm<false,true>,  cudaFuncAttributeMaxDynamicSharedMemorySize, GEMM_SMEM);
    cudaFuncSetAttribute((const void*)tgemm<false,false>, cudaFuncAttributeMaxDynamicSharedMemorySize, GEMM_SMEM);
    cudaFuncSetAttribute((const void*)tgemm<true,true>,   cudaFuncAttributeMaxDynamicSharedMemorySize, GEMM_SMEM);
    cudaFuncSetAttribute((const void*)attn_kernel,        cudaFuncAttributeMaxDynamicSharedMemorySize, ATTN_SMEM);

    to_half_all_kernel<<<4096, 256>>>(Wqkv, wqkv_h, Wo, wo_h, W1, w1_h, W2, w2_h);

    embed_kernel<<<SEQP, 256>>>(q, p, qm, pm, z, Wq, bq, Wp, bp, Wz, bz, pos, noise, x, xh);

    const int MB = SEQP / 128;   // 33
    for (int i = 0; i < LAYERS; i++) {
        tgemm<false,true><<<dim3(H3 / 128, MB), 256, GEMM_SMEM>>>(
            xh, wqkv_h + (size_t)i * H3 * H, bqkv + (size_t)i * H3, qkvb, SEQP, H3, H);
        attn_kernel<<<dim3(SEQP / 128, NH), 256, ATTN_SMEM>>>(qkvb, attnb);
        tgemm<false,false><<<dim3(H / 128, MB), 256, GEMM_SMEM>>>(
            attnb, wo_h + (size_t)i * H * H, bo + (size_t)i * H, tmp, SEQP, H, H);
        addln_kernel<<<SEQP, 256>>>(x, tmp, ln1w + (size_t)i * H, ln1b + (size_t)i * H, x, xh);
        tgemm<true,true><<<dim3(FFD / 128, MB), 256, GEMM_SMEM>>>(
            xh, w1_h + (size_t)i * FFD * H, b1 + (size_t)i * FFD, ff, SEQP, FFD, H);
        tgemm<false,false><<<dim3(H / 128, MB), 256, GEMM_SMEM>>>(
            ff, w2_h + (size_t)i * H * FFD, b2 + (size_t)i * H, tmp, SEQP, H, FFD);
        addln_kernel<<<SEQP, 256>>>(x, tmp, ln2w + (size_t)i * H, ln2b + (size_t)i * H, x, xh);
    }

    final_kernel<<<1, 128>>>(x, Wout, bout, (float*)d_out);
}